// round 3
// baseline (speedup 1.0000x reference)
#include <cuda_runtime.h>

// Fused transformer block: B=262144, T=8, C=32, heads=4, head=8, FF=128, fp32.
// One warp per batch item. Weights repacked in shared; fma.rn.f32x2 packed
// over the reduction dimension; attention scratch padded to stride 36 to
// kill quarter-warp bank conflicts.

#define WARPS_PER_BLOCK 8
#define THREADS_PER_BLOCK 256
#define GRID_BLOCKS 2048

// weights: sWkq 2048 | sWv 1024 | sWp 1024 | sW1 4096 | sW2 4096 = 12288 floats
// per-warp scratch: sX 256 | sX1 256 | sK/sQ/sV/sA 4*288 (sH 1024 overlays) = 1664
#define SCRATCH_FLOATS 1664
#define SMEM_FLOATS (12288 + WARPS_PER_BLOCK * SCRATCH_FLOATS)
#define SMEM_BYTES  (SMEM_FLOATS * 4)

typedef unsigned long long ull;

__device__ __forceinline__ ull pk(float lo, float hi) {
    ull r; asm("mov.b64 %0,{%1,%2};" : "=l"(r) : "f"(lo), "f"(hi)); return r;
}
__device__ __forceinline__ void fma2(ull& d, ull a, ull b) {
    asm("fma.rn.f32x2 %0,%1,%2,%3;" : "=l"(d) : "l"(a), "l"(b), "l"(d));
}
__device__ __forceinline__ float psum(ull v) {
    float lo, hi; asm("mov.b64 {%0,%1},%2;" : "=f"(lo), "=f"(hi) : "l"(v));
    return lo + hi;
}

__global__ __launch_bounds__(THREADS_PER_BLOCK, 2)
void tblock_kernel(const float* __restrict__ X,
                   const float* __restrict__ Wa,
                   const float* __restrict__ Wp,
                   const float* __restrict__ W1,
                   const float* __restrict__ W2,
                   float* __restrict__ Out,
                   int NB)
{
    extern __shared__ float sm[];
    float* const sWkq = sm;            // 2048: [cpair][lane][4] = (k0,k1,q0*s,q1*s)
    float* const sWv  = sm + 2048;     // 1024: [cpair][lane][2] = (v0,v1)
    float* const sWp  = sm + 3072;     // 1024: [ci4][lane][4]   = Wp[4a+i][lane]
    float* const sW1  = sm + 4096;     // 4096: [cpair][lane][8] = pairs per k
    float* const sW2  = sm + 8192;     // 4096: [f4][lane][4]    = W2[4a+i][lane]
    float* const scr  = sm + 12288;

    const int tid  = threadIdx.x;
    const int warp = tid >> 5;
    const int lane = tid & 31;

    const float scale = 0.17677669529663687f;   // 32^{-1/2}

    // ---------------- pack weights ----------------
    for (int idx = tid; idx < 512; idx += THREADS_PER_BLOCK) {
        int p = idx >> 5, l = idx & 31;
        int h = l >> 3, d = l & 7;
        const float* base = Wa + h * 768 + d;        // [h][c][24]: K=+0, Q=+8, V=+16
        int c0 = 2 * p, c1 = 2 * p + 1;
        sWkq[p * 128 + l * 4 + 0] = base[c0 * 24];
        sWkq[p * 128 + l * 4 + 1] = base[c1 * 24];
        sWkq[p * 128 + l * 4 + 2] = base[c0 * 24 + 8] * scale;
        sWkq[p * 128 + l * 4 + 3] = base[c1 * 24 + 8] * scale;
        sWv[p * 64 + l * 2 + 0]   = base[c0 * 24 + 16];
        sWv[p * 64 + l * 2 + 1]   = base[c1 * 24 + 16];
        // sW1: pairs over c for each of 4 output groups k
        for (int k = 0; k < 4; k++) {
            sW1[p * 256 + l * 8 + k * 2 + 0] = W1[c0 * 128 + k * 32 + l];
            sW1[p * 256 + l * 8 + k * 2 + 1] = W1[c1 * 128 + k * 32 + l];
        }
    }
    for (int idx = tid; idx < 256; idx += THREADS_PER_BLOCK) {
        int a = idx >> 5, l = idx & 31;
        *(float4*)&sWp[(a << 7) + (l << 2)] =
            make_float4(Wp[(a * 4 + 0) * 32 + l], Wp[(a * 4 + 1) * 32 + l],
                        Wp[(a * 4 + 2) * 32 + l], Wp[(a * 4 + 3) * 32 + l]);
    }
    for (int idx = tid; idx < 1024; idx += THREADS_PER_BLOCK) {
        int a = idx >> 5, l = idx & 31;
        *(float4*)&sW2[(a << 7) + (l << 2)] =
            make_float4(W2[(a * 4 + 0) * 32 + l], W2[(a * 4 + 1) * 32 + l],
                        W2[(a * 4 + 2) * 32 + l], W2[(a * 4 + 3) * 32 + l]);
    }
    __syncthreads();

    float* const buf = scr + warp * SCRATCH_FLOATS;
    float* const sX  = buf;            // 256 [t*32+c]
    float* const sX1 = buf + 256;      // 256
    float* const sK  = buf + 512;      // 288, stride 36
    float* const sQ  = buf + 800;      // 288
    float* const sV  = buf + 1088;     // 288
    float* const sA  = buf + 1376;     // 288, stride 36
    float* const sH  = buf + 512;      // 1024 [t*128+f], overlays K/Q/V/A

    const int h3 = lane >> 3;
    const int qt = lane & 7;
    const int ho = h3 * 8;

    for (int b = blockIdx.x * WARPS_PER_BLOCK + warp; b < NB;
         b += GRID_BLOCKS * WARPS_PER_BLOCK) {
        const float* xg = X + (long long)b * 256;

        *(float4*)&sX[lane * 8]     = *(const float4*)(xg + lane * 8);
        *(float4*)&sX[lane * 8 + 4] = *(const float4*)(xg + lane * 8 + 4);
        __syncwarp();

        // ---- QKV, packed over c-pairs. lane = (h,d) ----
        {
            ull k2[8], q2[8], v2[8];
            #pragma unroll
            for (int t = 0; t < 8; t++) { k2[t] = 0; q2[t] = 0; v2[t] = 0; }
            #pragma unroll 1
            for (int g = 0; g < 8; g++) {            // c-quad = 2 c-pairs
                const ulonglong2 wkq0 = *(const ulonglong2*)&sWkq[(2 * g) * 128 + lane * 4];
                const ull        wv0  = *(const ull*)&sWv[(2 * g) * 64 + lane * 2];
                const ulonglong2 wkq1 = *(const ulonglong2*)&sWkq[(2 * g + 1) * 128 + lane * 4];
                const ull        wv1  = *(const ull*)&sWv[(2 * g + 1) * 64 + lane * 2];
                #pragma unroll
                for (int t = 0; t < 8; t++) {
                    const ulonglong2 x2 = *(const ulonglong2*)&sX[t * 32 + g * 4];
                    fma2(k2[t], x2.x, wkq0.x);
                    fma2(q2[t], x2.x, wkq0.y);
                    fma2(v2[t], x2.x, wv0);
                    fma2(k2[t], x2.y, wkq1.x);
                    fma2(q2[t], x2.y, wkq1.y);
                    fma2(v2[t], x2.y, wv1);
                }
            }
            #pragma unroll
            for (int t = 0; t < 8; t++) {
                sK[t * 36 + lane] = psum(k2[t]);
                sQ[t * 36 + lane] = psum(q2[t]);
                sV[t * 36 + lane] = psum(v2[t]);
            }
        }
        __syncwarp();

        // ---- attention. lane = (h3, qt); scale folded into Q ----
        {
            const ulonglong2 qA = *(const ulonglong2*)&sQ[qt * 36 + ho];
            const ulonglong2 qB = *(const ulonglong2*)&sQ[qt * 36 + ho + 4];
            float e[8];
            float mx = -1e30f;
            #pragma unroll
            for (int kt = 0; kt < 8; kt++) {
                const ulonglong2 kA = *(const ulonglong2*)&sK[kt * 36 + ho];
                const ulonglong2 kB = *(const ulonglong2*)&sK[kt * 36 + ho + 4];
                ull a2 = 0;
                fma2(a2, qA.x, kA.x);
                fma2(a2, qA.y, kA.y);
                fma2(a2, qB.x, kB.x);
                fma2(a2, qB.y, kB.y);
                float acc = psum(a2);
                e[kt] = (kt <= qt) ? acc : -1e30f;
                mx = fmaxf(mx, e[kt]);
            }
            float sum = 0.f;
            #pragma unroll
            for (int kt = 0; kt < 8; kt++) { e[kt] = __expf(e[kt] - mx); sum += e[kt]; }
            const float inv = __fdividef(1.0f, sum);
            float4 oa = make_float4(0.f, 0.f, 0.f, 0.f);
            float4 ob = make_float4(0.f, 0.f, 0.f, 0.f);
            #pragma unroll
            for (int kt = 0; kt < 8; kt++) {
                const float wgt = e[kt] * inv;
                const float4 va = *(const float4*)&sV[kt * 36 + ho];
                const float4 vb = *(const float4*)&sV[kt * 36 + ho + 4];
                oa.x = fmaf(wgt, va.x, oa.x);
                oa.y = fmaf(wgt, va.y, oa.y);
                oa.z = fmaf(wgt, va.z, oa.z);
                oa.w = fmaf(wgt, va.w, oa.w);
                ob.x = fmaf(wgt, vb.x, ob.x);
                ob.y = fmaf(wgt, vb.y, ob.y);
                ob.z = fmaf(wgt, vb.z, ob.z);
                ob.w = fmaf(wgt, vb.w, ob.w);
            }
            *(float4*)&sA[qt * 36 + ho]     = oa;
            *(float4*)&sA[qt * 36 + ho + 4] = ob;
        }
        __syncwarp();

        // ---- proj + residual, packed over ci-pairs. lane = out channel ----
        float x1[8];
        {
            ull x1p[8];
            #pragma unroll
            for (int t = 0; t < 8; t++) x1p[t] = pk(sX[t * 32 + lane], 0.f);
            #pragma unroll 1
            for (int a = 0; a < 8; a++) {
                const ulonglong2 w = *(const ulonglong2*)&sWp[a * 128 + lane * 4];
                #pragma unroll
                for (int t = 0; t < 8; t++) {
                    const ulonglong2 a2 = *(const ulonglong2*)&sA[t * 36 + a * 4];
                    fma2(x1p[t], a2.x, w.x);
                    fma2(x1p[t], a2.y, w.y);
                }
            }
            #pragma unroll
            for (int t = 0; t < 8; t++) {
                x1[t] = psum(x1p[t]);
                sX1[t * 32 + lane] = x1[t];
            }
        }
        __syncwarp();

        // ---- FF1 + relu, packed over c-pairs, split by k-halves ----
        #pragma unroll 1
        for (int hv = 0; hv < 2; hv++) {
            ull h2a[8], h2b[8];
            #pragma unroll
            for (int t = 0; t < 8; t++) { h2a[t] = 0; h2b[t] = 0; }
            #pragma unroll 1
            for (int g = 0; g < 8; g++) {
                const ulonglong2 w0 = *(const ulonglong2*)&sW1[(2 * g) * 256 + lane * 8 + hv * 4];
                const ulonglong2 w1 = *(const ulonglong2*)&sW1[(2 * g + 1) * 256 + lane * 8 + hv * 4];
                #pragma unroll
                for (int t = 0; t < 8; t++) {
                    const ulonglong2 x2 = *(const ulonglong2*)&sX1[t * 32 + g * 4];
                    fma2(h2a[t], x2.x, w0.x);
                    fma2(h2b[t], x2.x, w0.y);
                    fma2(h2a[t], x2.y, w1.x);
                    fma2(h2b[t], x2.y, w1.y);
                }
            }
            #pragma unroll
            for (int t = 0; t < 8; t++) {
                sH[t * 128 + (2 * hv + 0) * 32 + lane] = fmaxf(psum(h2a[t]), 0.f);
                sH[t * 128 + (2 * hv + 1) * 32 + lane] = fmaxf(psum(h2b[t]), 0.f);
            }
        }
        __syncwarp();

        // ---- FF2 + residual, packed over f-pairs ----
        {
            ull x1p[8];
            #pragma unroll
            for (int t = 0; t < 8; t++) x1p[t] = pk(x1[t], 0.f);
            #pragma unroll 1
            for (int a = 0; a < 32; a++) {
                const ulonglong2 w = *(const ulonglong2*)&sW2[a * 128 + lane * 4];
                #pragma unroll
                for (int t = 0; t < 8; t++) {
                    const ulonglong2 h2 = *(const ulonglong2*)&sH[t * 128 + a * 4];
                    fma2(x1p[t], h2.x, w.x);
                    fma2(x1p[t], h2.y, w.y);
                }
            }
            #pragma unroll
            for (int t = 0; t < 8; t++) sX[t * 32 + lane] = psum(x1p[t]);
        }
        __syncwarp();

        float* og = Out + (long long)b * 256;
        *(float4*)(og + lane * 8)     = *(float4*)&sX[lane * 8];
        *(float4*)(og + lane * 8 + 4) = *(float4*)&sX[lane * 8 + 4];
        __syncwarp();
    }
}

extern "C" void kernel_launch(void* const* d_in, const int* in_sizes, int n_in,
                              void* d_out, int out_size) {
    const float* X  = (const float*)d_in[0];
    const float* Wa = (const float*)d_in[1];
    const float* Wp = (const float*)d_in[2];
    const float* W1 = (const float*)d_in[3];
    const float* W2 = (const float*)d_in[4];
    float* Out = (float*)d_out;
    const int NB = in_sizes[0] / 256;

    cudaFuncSetAttribute(tblock_kernel,
                         cudaFuncAttributeMaxDynamicSharedMemorySize, SMEM_BYTES);
    tblock_kernel<<<GRID_BLOCKS, THREADS_PER_BLOCK, SMEM_BYTES>>>(
        X, Wa, Wp, W1, W2, Out, NB);
}

// round 5
// speedup vs baseline: 2.3614x; 2.3614x over previous
#include <cuda_runtime.h>
#include <cstdint>

// Fused transformer block via mma.sync tf32 (m16n8k8), sm_103 base target.
// 2M rows x 32, tiles of 128 rows/CTA, 256 threads, persistent grid 148.

#define THREADS 256
#define NUM_CTAS 148
#define NUM_TILES 16384

// float offsets in dynamic smem
#define OFF_WQKV 0          // 32 x 104  (K=32, N=96 cols permuted [K|Q|V])
#define OFF_WP   3328       // 32 x 40
#define OFF_W1   4608       // 32 x 136
#define OFF_W2   8960       // 128 x 40
#define OFF_X    14080      // 128 x 36
#define OFF_K    18688      // 128 x 36
#define OFF_Q    23296      // 128 x 36
#define OFF_V    27904      // 128 x 36
#define OFF_H    18688      // 128 x 132 (overlays K/Q/V after proj)
#define SMEM_FLOATS 35584
#define SMEM_BYTES  (SMEM_FLOATS * 4)

#define PW_QKV 104
#define PW_P   40
#define PW_1   136
#define PW_2   40
#define PA     36
#define PH     132

__device__ __forceinline__ uint32_t tf32u(float x) {
    uint32_t r; asm("cvt.rna.tf32.f32 %0,%1;" : "=r"(r) : "f"(x)); return r;
}
__device__ __forceinline__ float tf32f(float x) {
    float r; asm("cvt.rna.tf32.f32 %0,%1;" : "=f"(r) : "f"(x)); return r;
}
__device__ __forceinline__ void mma8(float c[4], const uint32_t a[4], const uint32_t b[2]) {
    asm volatile(
        "mma.sync.aligned.m16n8k8.row.col.f32.tf32.tf32.f32 "
        "{%0,%1,%2,%3},{%4,%5,%6,%7},{%8,%9},{%0,%1,%2,%3};"
        : "+f"(c[0]), "+f"(c[1]), "+f"(c[2]), "+f"(c[3])
        : "r"(a[0]), "r"(a[1]), "r"(a[2]), "r"(a[3]), "r"(b[0]), "r"(b[1]));
}

// A fragment (16x8) at (row0, k0) from row-major act buffer, converting to tf32.
#define LOAD_A(A, act, pitch, row0, k0) do {                                   \
    (A)[0] = tf32u((act)[((row0) + r) * (pitch) + (k0) + c]);                  \
    (A)[1] = tf32u((act)[((row0) + r + 8) * (pitch) + (k0) + c]);              \
    (A)[2] = tf32u((act)[((row0) + r) * (pitch) + (k0) + c + 4]);              \
    (A)[3] = tf32u((act)[((row0) + r + 8) * (pitch) + (k0) + c + 4]);          \
} while (0)

// B fragment (8x8) at (k0, n0) from row-major K x N weight buffer (pre-tf32).
#define LOAD_B(B, w, pitch, k0, n0) do {                                       \
    (B)[0] = __float_as_uint((w)[((k0) + c) * (pitch) + (n0) + r]);            \
    (B)[1] = __float_as_uint((w)[((k0) + c + 4) * (pitch) + (n0) + r]);        \
} while (0)

__global__ void __launch_bounds__(THREADS, 1)
tblock_mma(const float* __restrict__ X, const float* __restrict__ Wa,
           const float* __restrict__ Wp, const float* __restrict__ W1,
           const float* __restrict__ W2, float* __restrict__ Out)
{
    extern __shared__ float sm[];
    float* const sWqkv = sm + OFF_WQKV;
    float* const sWp   = sm + OFF_WP;
    float* const sW1   = sm + OFF_W1;
    float* const sW2   = sm + OFF_W2;
    float* const sX    = sm + OFF_X;
    float* const sK    = sm + OFF_K;
    float* const sQ    = sm + OFF_Q;
    float* const sV    = sm + OFF_V;
    float* const sH    = sm + OFF_H;

    const int tid  = threadIdx.x;
    const int warp = tid >> 5;
    const int lane = tid & 31;
    const int r = lane >> 2;      // mma fragment row-in-group
    const int c = lane & 3;       // mma fragment col-in-group
    const float scale = 0.17677669529663687f;   // 32^{-1/2}, folded into Wq

    // ---------------- pack weights (tf32-rounded) ----------------
    // sWqkv cols permuted: n' in [0,32)=K (h*8+d), [32,64)=Q*scale, [64,96)=V
    for (int idx = tid; idx < 3072; idx += THREADS) {
        int k = idx / 96, n = idx % 96;
        int g = n >> 5, hh = (n & 31) >> 3, d = n & 7;
        float v = Wa[hh * 768 + k * 24 + g * 8 + d];
        if (g == 1) v *= scale;
        sWqkv[k * PW_QKV + n] = tf32f(v);
    }
    for (int idx = tid; idx < 1024; idx += THREADS)
        sWp[(idx >> 5) * PW_P + (idx & 31)] = tf32f(Wp[idx]);
    for (int idx = tid; idx < 4096; idx += THREADS)
        sW1[(idx >> 7) * PW_1 + (idx & 127)] = tf32f(W1[idx]);
    for (int idx = tid; idx < 4096; idx += THREADS)
        sW2[(idx >> 5) * PW_2 + (idx & 31)] = tf32f(W2[idx]);
    __syncthreads();

    const int m  = warp & 3;
    const int nh = warp >> 2;
    const int row0a = m * 32;
    const int row0b = m * 32 + 16;
    const int srow = tid >> 1;          // X load/store staging
    const int shalf = (tid & 1) * 16;

    for (int tile = blockIdx.x; tile < NUM_TILES; tile += NUM_CTAS) {
        const float* xg = X + (long long)tile * 4096;
        float* og = Out + (long long)tile * 4096;

        // ---- stage 0: load X tile -> sX ----
        #pragma unroll
        for (int i = 0; i < 4; i++)
            *(float4*)&sX[srow * PA + shalf + i * 4] =
                *(const float4*)(xg + srow * 32 + shalf + i * 4);
        __syncthreads();

        // ---- stage 1: QKV = X @ Wqkv -> sK/sQ/sV ----
        {
            uint32_t A0[4][4], A1[4][4];
            #pragma unroll
            for (int ks = 0; ks < 4; ks++) {
                LOAD_A(A0[ks], sX, PA, row0a, ks * 8);
                LOAD_A(A1[ks], sX, PA, row0b, ks * 8);
            }
            #pragma unroll
            for (int j = 0; j < 6; j++) {
                const int n0 = nh * 48 + j * 8;
                uint32_t B[4][2];
                #pragma unroll
                for (int ks = 0; ks < 4; ks++) LOAD_B(B[ks], sWqkv, PW_QKV, ks * 8, n0);
                float C0[4] = {0.f,0.f,0.f,0.f}, C1[4] = {0.f,0.f,0.f,0.f};
                #pragma unroll
                for (int ks = 0; ks < 4; ks++) { mma8(C0, A0[ks], B[ks]); mma8(C1, A1[ks], B[ks]); }
                float* cb = (n0 < 32) ? (sK + n0) : (n0 < 64 ? (sQ + n0 - 32) : (sV + n0 - 64));
                *(float2*)&cb[(row0a + r) * PA + 2 * c]     = make_float2(C0[0], C0[1]);
                *(float2*)&cb[(row0a + r + 8) * PA + 2 * c] = make_float2(C0[2], C0[3]);
                *(float2*)&cb[(row0b + r) * PA + 2 * c]     = make_float2(C1[0], C1[1]);
                *(float2*)&cb[(row0b + r + 8) * PA + 2 * c] = make_float2(C1[2], C1[3]);
            }
        }
        __syncthreads();

        // ---- stage 2: attention (CUDA cores), 2 batch items/warp ----
        {
            const int h = lane >> 3, qt = lane & 7, ho = h * 8;
            #pragma unroll 1
            for (int p = 0; p < 2; p++) {
                const int rb = m * 32 + (nh * 2 + p) * 8;
                const float4 qa = *(float4*)&sQ[(rb + qt) * PA + ho];
                const float4 qb = *(float4*)&sQ[(rb + qt) * PA + ho + 4];
                float e[8], mx = -1e30f;
                #pragma unroll
                for (int kt = 0; kt < 8; kt++) {
                    const float4 ka = *(const float4*)&sK[(rb + kt) * PA + ho];
                    const float4 kb = *(const float4*)&sK[(rb + kt) * PA + ho + 4];
                    float acc = qa.x * ka.x;
                    acc = fmaf(qa.y, ka.y, acc); acc = fmaf(qa.z, ka.z, acc);
                    acc = fmaf(qa.w, ka.w, acc); acc = fmaf(qb.x, kb.x, acc);
                    acc = fmaf(qb.y, kb.y, acc); acc = fmaf(qb.z, kb.z, acc);
                    acc = fmaf(qb.w, kb.w, acc);
                    e[kt] = (kt <= qt) ? acc : -1e30f;
                    mx = fmaxf(mx, e[kt]);
                }
                float sum = 0.f;
                #pragma unroll
                for (int kt = 0; kt < 8; kt++) { e[kt] = __expf(e[kt] - mx); sum += e[kt]; }
                const float inv = __fdividef(1.0f, sum);
                float4 oa = make_float4(0.f,0.f,0.f,0.f), ob = make_float4(0.f,0.f,0.f,0.f);
                #pragma unroll
                for (int kt = 0; kt < 8; kt++) {
                    const float w = e[kt] * inv;
                    const float4 va = *(const float4*)&sV[(rb + kt) * PA + ho];
                    const float4 vb = *(const float4*)&sV[(rb + kt) * PA + ho + 4];
                    oa.x = fmaf(w, va.x, oa.x); oa.y = fmaf(w, va.y, oa.y);
                    oa.z = fmaf(w, va.z, oa.z); oa.w = fmaf(w, va.w, oa.w);
                    ob.x = fmaf(w, vb.x, ob.x); ob.y = fmaf(w, vb.y, ob.y);
                    ob.z = fmaf(w, vb.z, ob.z); ob.w = fmaf(w, vb.w, ob.w);
                }
                __syncwarp();
                *(float4*)&sQ[(rb + qt) * PA + ho]     = oa;   // overlay q-slot
                *(float4*)&sQ[(rb + qt) * PA + ho + 4] = ob;
                __syncwarp();
            }
        }
        __syncthreads();

        // ---- stage 3: X1 = attn @ Wp + X -> sX ----
        {
            uint32_t A0[4][4], A1[4][4];
            #pragma unroll
            for (int ks = 0; ks < 4; ks++) {
                LOAD_A(A0[ks], sQ, PA, row0a, ks * 8);
                LOAD_A(A1[ks], sQ, PA, row0b, ks * 8);
            }
            #pragma unroll
            for (int j = 0; j < 2; j++) {
                const int n0 = nh * 16 + j * 8;
                uint32_t B[4][2];
                #pragma unroll
                for (int ks = 0; ks < 4; ks++) LOAD_B(B[ks], sWp, PW_P, ks * 8, n0);
                float C0[4] = {0.f,0.f,0.f,0.f}, C1[4] = {0.f,0.f,0.f,0.f};
                #pragma unroll
                for (int ks = 0; ks < 4; ks++) { mma8(C0, A0[ks], B[ks]); mma8(C1, A1[ks], B[ks]); }
                float2* p00 = (float2*)&sX[(row0a + r) * PA + n0 + 2 * c];
                float2* p01 = (float2*)&sX[(row0a + r + 8) * PA + n0 + 2 * c];
                float2* p10 = (float2*)&sX[(row0b + r) * PA + n0 + 2 * c];
                float2* p11 = (float2*)&sX[(row0b + r + 8) * PA + n0 + 2 * c];
                float2 v;
                v = *p00; *p00 = make_float2(C0[0] + v.x, C0[1] + v.y);
                v = *p01; *p01 = make_float2(C0[2] + v.x, C0[3] + v.y);
                v = *p10; *p10 = make_float2(C1[0] + v.x, C1[1] + v.y);
                v = *p11; *p11 = make_float2(C1[2] + v.x, C1[3] + v.y);
            }
        }
        __syncthreads();

        // ---- stage 4: H = relu(X1 @ W1) -> sH (overlays K/Q/V) ----
        {
            uint32_t A0[4][4], A1[4][4];
            #pragma unroll
            for (int ks = 0; ks < 4; ks++) {
                LOAD_A(A0[ks], sX, PA, row0a, ks * 8);
                LOAD_A(A1[ks], sX, PA, row0b, ks * 8);
            }
            #pragma unroll
            for (int j = 0; j < 8; j++) {
                const int n0 = nh * 64 + j * 8;
                uint32_t B[4][2];
                #pragma unroll
                for (int ks = 0; ks < 4; ks++) LOAD_B(B[ks], sW1, PW_1, ks * 8, n0);
                float C0[4] = {0.f,0.f,0.f,0.f}, C1[4] = {0.f,0.f,0.f,0.f};
                #pragma unroll
                for (int ks = 0; ks < 4; ks++) { mma8(C0, A0[ks], B[ks]); mma8(C1, A1[ks], B[ks]); }
                *(float2*)&sH[(row0a + r) * PH + n0 + 2 * c] =
                    make_float2(fmaxf(C0[0], 0.f), fmaxf(C0[1], 0.f));
                *(float2*)&sH[(row0a + r + 8) * PH + n0 + 2 * c] =
                    make_float2(fmaxf(C0[2], 0.f), fmaxf(C0[3], 0.f));
                *(float2*)&sH[(row0b + r) * PH + n0 + 2 * c] =
                    make_float2(fmaxf(C1[0], 0.f), fmaxf(C1[1], 0.f));
                *(float2*)&sH[(row0b + r + 8) * PH + n0 + 2 * c] =
                    make_float2(fmaxf(C1[2], 0.f), fmaxf(C1[3], 0.f));
            }
        }
        __syncthreads();

        // ---- stage 5: X2 = H @ W2 + X1 -> sX ----
        {
            const int n0 = nh * 16, n1 = nh * 16 + 8;
            float C00[4] = {0.f,0.f,0.f,0.f}, C01[4] = {0.f,0.f,0.f,0.f};
            float C10[4] = {0.f,0.f,0.f,0.f}, C11[4] = {0.f,0.f,0.f,0.f};
            #pragma unroll
            for (int ks = 0; ks < 16; ks++) {
                uint32_t A0[4], A1[4], B0[2], B1[2];
                LOAD_A(A0, sH, PH, row0a, ks * 8);
                LOAD_A(A1, sH, PH, row0b, ks * 8);
                LOAD_B(B0, sW2, PW_2, ks * 8, n0);
                LOAD_B(B1, sW2, PW_2, ks * 8, n1);
                mma8(C00, A0, B0); mma8(C01, A0, B1);
                mma8(C10, A1, B0); mma8(C11, A1, B1);
            }
            float2* p; float2 v;
            p = (float2*)&sX[(row0a + r) * PA + n0 + 2*c];     v = *p; *p = make_float2(C00[0]+v.x, C00[1]+v.y);
            p = (float2*)&sX[(row0a + r + 8) * PA + n0 + 2*c]; v = *p; *p = make_float2(C00[2]+v.x, C00[3]+v.y);
            p = (float2*)&sX[(row0a + r) * PA + n1 + 2*c];     v = *p; *p = make_float2(C01[0]+v.x, C01[1]+v.y);
            p = (float2*)&sX[(row0a + r + 8) * PA + n1 + 2*c]; v = *p; *p = make_float2(C01[2]+v.x, C01[3]+v.y);
            p = (float2*)&sX[(row0b + r) * PA + n0 + 2*c];     v = *p; *p = make_float2(C10[0]+v.x, C10[1]+v.y);
            p = (float2*)&sX[(row0b + r + 8) * PA + n0 + 2*c]; v = *p; *p = make_float2(C10[2]+v.x, C10[3]+v.y);
            p = (float2*)&sX[(row0b + r) * PA + n1 + 2*c];     v = *p; *p = make_float2(C11[0]+v.x, C11[1]+v.y);
            p = (float2*)&sX[(row0b + r + 8) * PA + n1 + 2*c]; v = *p; *p = make_float2(C11[2]+v.x, C11[3]+v.y);
        }
        __syncthreads();

        // ---- stage 6: store output ----
        #pragma unroll
        for (int i = 0; i < 4; i++)
            *(float4*)(og + srow * 32 + shalf + i * 4) =
                *(float4*)&sX[srow * PA + shalf + i * 4];
        __syncthreads();
    }
}

extern "C" void kernel_launch(void* const* d_in, const int* in_sizes, int n_in,
                              void* d_out, int out_size) {
    const float* X  = (const float*)d_in[0];
    const float* Wa = (const float*)d_in[1];
    const float* Wp = (const float*)d_in[2];
    const float* W1 = (const float*)d_in[3];
    const float* W2 = (const float*)d_in[4];
    float* Out = (float*)d_out;

    cudaFuncSetAttribute(tblock_mma,
                         cudaFuncAttributeMaxDynamicSharedMemorySize, SMEM_BYTES);
    tblock_mma<<<NUM_CTAS, THREADS, SMEM_BYTES>>>(X, Wa, Wp, W1, W2, Out);
}

// round 6
// speedup vs baseline: 2.5024x; 1.0597x over previous
#include <cuda_runtime.h>
#include <cstdint>

// Fused transformer block via mma.sync tf32 (m16n8k8), sm_103 base target.
// 2M rows x 32, 128-row tiles, 256 threads, persistent grid 148.
// QKV/proj B-fragments hoisted to registers; FF hidden kept in registers
// (FF1 C-frags feed FF2 A-slots via W2 row permutation {2c,2c+1}).

#define THREADS 256
#define NUM_CTAS 148
#define NUM_TILES 16384

// float offsets in dynamic smem
#define OFF_WQKV 0          // 32 x 104 (dead after hoist; sX overlays)
#define OFF_WP   3328       // 32 x 40  (dead after hoist)
#define OFF_X    0          // 128 x 36 overlays WQKV+WP (3328+1280 = 4608)
#define OFF_W1   4608       // 32 x 136
#define OFF_W2   8960       // 128 x 36
#define OFF_K    13568      // 128 x 36 (reused as FF2 partial buffer)
#define OFF_Q    18176      // 128 x 36
#define OFF_V    22784      // 128 x 36
#define SMEM_FLOATS 27392
#define SMEM_BYTES  (SMEM_FLOATS * 4)

#define PW_QKV 104
#define PW_P   40
#define PW_1   136
#define PW_2   36
#define PA     36

__device__ __forceinline__ uint32_t tf32u(float x) {
    uint32_t r; asm("cvt.rna.tf32.f32 %0,%1;" : "=r"(r) : "f"(x)); return r;
}
__device__ __forceinline__ float tf32f(float x) {
    float r; asm("cvt.rna.tf32.f32 %0,%1;" : "=f"(r) : "f"(x)); return r;
}
__device__ __forceinline__ void mma8(float c[4], const uint32_t a[4], const uint32_t b[2]) {
    asm volatile(
        "mma.sync.aligned.m16n8k8.row.col.f32.tf32.tf32.f32 "
        "{%0,%1,%2,%3},{%4,%5,%6,%7},{%8,%9},{%0,%1,%2,%3};"
        : "+f"(c[0]), "+f"(c[1]), "+f"(c[2]), "+f"(c[3])
        : "r"(a[0]), "r"(a[1]), "r"(a[2]), "r"(a[3]), "r"(b[0]), "r"(b[1]));
}

// A fragment (16x8) at (row0, k0) from row-major act buffer, converting to tf32.
#define LOAD_A(A, act, pitch, row0, k0) do {                                   \
    (A)[0] = tf32u((act)[((row0) + r) * (pitch) + (k0) + c]);                  \
    (A)[1] = tf32u((act)[((row0) + r + 8) * (pitch) + (k0) + c]);              \
    (A)[2] = tf32u((act)[((row0) + r) * (pitch) + (k0) + c + 4]);              \
    (A)[3] = tf32u((act)[((row0) + r + 8) * (pitch) + (k0) + c + 4]);          \
} while (0)

// B fragment (8x8) at (k0, n0), standard rows {c, c+4}.
#define LOAD_B(B, w, pitch, k0, n0) do {                                       \
    (B)[0] = __float_as_uint((w)[((k0) + c) * (pitch) + (n0) + r]);            \
    (B)[1] = __float_as_uint((w)[((k0) + c + 4) * (pitch) + (n0) + r]);        \
} while (0)

// B fragment with permuted rows {2c, 2c+1}: pairs k-slots with FF1 C-frag layout.
#define LOAD_B2(B, w, pitch, k0, n0) do {                                      \
    (B)[0] = __float_as_uint((w)[((k0) + 2 * c) * (pitch) + (n0) + r]);        \
    (B)[1] = __float_as_uint((w)[((k0) + 2 * c + 1) * (pitch) + (n0) + r]);    \
} while (0)

__global__ void __launch_bounds__(THREADS, 1)
tblock_mma(const float* __restrict__ X, const float* __restrict__ Wa,
           const float* __restrict__ Wp, const float* __restrict__ W1,
           const float* __restrict__ W2, float* __restrict__ Out)
{
    extern __shared__ float sm[];
    float* const sWqkv = sm + OFF_WQKV;
    float* const sWp   = sm + OFF_WP;
    float* const sW1   = sm + OFF_W1;
    float* const sW2   = sm + OFF_W2;
    float* const sX    = sm + OFF_X;
    float* const sK    = sm + OFF_K;
    float* const sQ    = sm + OFF_Q;
    float* const sV    = sm + OFF_V;
    float* const sP    = sm + OFF_K;    // FF2 partial exchange (K is dead by then)

    const int tid  = threadIdx.x;
    const int warp = tid >> 5;
    const int lane = tid & 31;
    const int r = lane >> 2;
    const int c = lane & 3;
    const float scale = 0.17677669529663687f;   // 32^{-1/2}, folded into Wq

    // ---------------- pack weights (tf32-rounded) ----------------
    // sWqkv cols permuted: n' in [0,32)=K (h*8+d), [32,64)=Q*scale, [64,96)=V
    for (int idx = tid; idx < 3072; idx += THREADS) {
        int k = idx / 96, n = idx % 96;
        int g = n >> 5, hh = (n & 31) >> 3, d = n & 7;
        float v = Wa[hh * 768 + k * 24 + g * 8 + d];
        if (g == 1) v *= scale;
        sWqkv[k * PW_QKV + n] = tf32f(v);
    }
    for (int idx = tid; idx < 1024; idx += THREADS)
        sWp[(idx >> 5) * PW_P + (idx & 31)] = tf32f(Wp[idx]);
    for (int idx = tid; idx < 4096; idx += THREADS)
        sW1[(idx >> 7) * PW_1 + (idx & 127)] = tf32f(W1[idx]);
    for (int idx = tid; idx < 4096; idx += THREADS)
        sW2[(idx >> 5) * PW_2 + (idx & 31)] = tf32f(W2[idx]);
    __syncthreads();

    const int m  = warp & 3;
    const int nh = warp >> 2;
    const int row0a = m * 32;
    const int row0b = m * 32 + 16;
    const int srow = tid >> 1;
    const int shalf = (tid & 1) * 16;

    // ---------------- hoist QKV + proj B fragments into registers ----------------
    uint32_t BQ[6][4][2], BP[2][4][2];
    #pragma unroll
    for (int j = 0; j < 6; j++)
        #pragma unroll
        for (int ks = 0; ks < 4; ks++)
            LOAD_B(BQ[j][ks], sWqkv, PW_QKV, ks * 8, nh * 48 + j * 8);
    #pragma unroll
    for (int j = 0; j < 2; j++)
        #pragma unroll
        for (int ks = 0; ks < 4; ks++)
            LOAD_B(BP[j][ks], sWp, PW_P, ks * 8, nh * 16 + j * 8);
    __syncthreads();   // all warps done reading sWqkv/sWp before sX overlays them

    for (int tile = blockIdx.x; tile < NUM_TILES; tile += NUM_CTAS) {
        const float* xg = X + (long long)tile * 4096;
        float* og = Out + (long long)tile * 4096;

        // ---- stage 0: load X tile -> sX ----
        #pragma unroll
        for (int i = 0; i < 4; i++)
            *(float4*)&sX[srow * PA + shalf + i * 4] =
                *(const float4*)(xg + srow * 32 + shalf + i * 4);
        __syncthreads();

        // ---- stage 1: QKV = X @ Wqkv -> sK/sQ/sV (B hoisted) ----
        {
            uint32_t A0[4][4], A1[4][4];
            #pragma unroll
            for (int ks = 0; ks < 4; ks++) {
                LOAD_A(A0[ks], sX, PA, row0a, ks * 8);
                LOAD_A(A1[ks], sX, PA, row0b, ks * 8);
            }
            #pragma unroll
            for (int j = 0; j < 6; j++) {
                const int n0 = nh * 48 + j * 8;
                float C0[4] = {0.f,0.f,0.f,0.f}, C1[4] = {0.f,0.f,0.f,0.f};
                #pragma unroll
                for (int ks = 0; ks < 4; ks++) { mma8(C0, A0[ks], BQ[j][ks]); mma8(C1, A1[ks], BQ[j][ks]); }
                float* cb = (n0 < 32) ? (sK + n0) : (n0 < 64 ? (sQ + n0 - 32) : (sV + n0 - 64));
                *(float2*)&cb[(row0a + r) * PA + 2 * c]     = make_float2(C0[0], C0[1]);
                *(float2*)&cb[(row0a + r + 8) * PA + 2 * c] = make_float2(C0[2], C0[3]);
                *(float2*)&cb[(row0b + r) * PA + 2 * c]     = make_float2(C1[0], C1[1]);
                *(float2*)&cb[(row0b + r + 8) * PA + 2 * c] = make_float2(C1[2], C1[3]);
            }
        }
        __syncthreads();

        // ---- stage 2: attention (CUDA cores), 2 batch items/warp ----
        {
            const int h = lane >> 3, qt = lane & 7, ho = h * 8;
            #pragma unroll 1
            for (int p = 0; p < 2; p++) {
                const int rb = m * 32 + (nh * 2 + p) * 8;
                const float4 qa = *(float4*)&sQ[(rb + qt) * PA + ho];
                const float4 qb = *(float4*)&sQ[(rb + qt) * PA + ho + 4];
                float e[8], mx = -1e30f;
                #pragma unroll
                for (int kt = 0; kt < 8; kt++) {
                    const float4 ka = *(const float4*)&sK[(rb + kt) * PA + ho];
                    const float4 kb = *(const float4*)&sK[(rb + kt) * PA + ho + 4];
                    float acc = qa.x * ka.x;
                    acc = fmaf(qa.y, ka.y, acc); acc = fmaf(qa.z, ka.z, acc);
                    acc = fmaf(qa.w, ka.w, acc); acc = fmaf(qb.x, kb.x, acc);
                    acc = fmaf(qb.y, kb.y, acc); acc = fmaf(qb.z, kb.z, acc);
                    acc = fmaf(qb.w, kb.w, acc);
                    e[kt] = (kt <= qt) ? acc : -1e30f;
                    mx = fmaxf(mx, e[kt]);
                }
                float sum = 0.f;
                #pragma unroll
                for (int kt = 0; kt < 8; kt++) { e[kt] = __expf(e[kt] - mx); sum += e[kt]; }
                const float inv = __fdividef(1.0f, sum);
                float4 oa = make_float4(0.f,0.f,0.f,0.f), ob = make_float4(0.f,0.f,0.f,0.f);
                #pragma unroll
                for (int kt = 0; kt < 8; kt++) {
                    const float w = e[kt] * inv;
                    const float4 va = *(const float4*)&sV[(rb + kt) * PA + ho];
                    const float4 vb = *(const float4*)&sV[(rb + kt) * PA + ho + 4];
                    oa.x = fmaf(w, va.x, oa.x); oa.y = fmaf(w, va.y, oa.y);
                    oa.z = fmaf(w, va.z, oa.z); oa.w = fmaf(w, va.w, oa.w);
                    ob.x = fmaf(w, vb.x, ob.x); ob.y = fmaf(w, vb.y, ob.y);
                    ob.z = fmaf(w, vb.z, ob.z); ob.w = fmaf(w, vb.w, ob.w);
                }
                __syncwarp();
                *(float4*)&sQ[(rb + qt) * PA + ho]     = oa;   // overlay q-slot
                *(float4*)&sQ[(rb + qt) * PA + ho + 4] = ob;
                __syncwarp();
            }
        }
        __syncthreads();

        // ---- stage 3: X1 = attn @ Wp + X -> sX (B hoisted) ----
        {
            uint32_t A0[4][4], A1[4][4];
            #pragma unroll
            for (int ks = 0; ks < 4; ks++) {
                LOAD_A(A0[ks], sQ, PA, row0a, ks * 8);
                LOAD_A(A1[ks], sQ, PA, row0b, ks * 8);
            }
            #pragma unroll
            for (int j = 0; j < 2; j++) {
                const int n0 = nh * 16 + j * 8;
                float C0[4] = {0.f,0.f,0.f,0.f}, C1[4] = {0.f,0.f,0.f,0.f};
                #pragma unroll
                for (int ks = 0; ks < 4; ks++) { mma8(C0, A0[ks], BP[j][ks]); mma8(C1, A1[ks], BP[j][ks]); }
                float2* p00 = (float2*)&sX[(row0a + r) * PA + n0 + 2 * c];
                float2* p01 = (float2*)&sX[(row0a + r + 8) * PA + n0 + 2 * c];
                float2* p10 = (float2*)&sX[(row0b + r) * PA + n0 + 2 * c];
                float2* p11 = (float2*)&sX[(row0b + r + 8) * PA + n0 + 2 * c];
                float2 v;
                v = *p00; *p00 = make_float2(C0[0] + v.x, C0[1] + v.y);
                v = *p01; *p01 = make_float2(C0[2] + v.x, C0[3] + v.y);
                v = *p10; *p10 = make_float2(C1[0] + v.x, C1[1] + v.y);
                v = *p11; *p11 = make_float2(C1[2] + v.x, C1[3] + v.y);
            }
        }
        __syncthreads();

        // ---- stage 4: H = relu(X1 @ W1), kept in registers (f-half per nh) ----
        uint32_t H0[8][4], H1[8][4];
        {
            uint32_t A0[4][4], A1[4][4];
            #pragma unroll
            for (int ks = 0; ks < 4; ks++) {
                LOAD_A(A0[ks], sX, PA, row0a, ks * 8);
                LOAD_A(A1[ks], sX, PA, row0b, ks * 8);
            }
            #pragma unroll
            for (int j = 0; j < 8; j++) {
                const int n0 = nh * 64 + j * 8;
                uint32_t B[4][2];
                #pragma unroll
                for (int ks = 0; ks < 4; ks++) LOAD_B(B[ks], sW1, PW_1, ks * 8, n0);
                float C0[4] = {0.f,0.f,0.f,0.f}, C1[4] = {0.f,0.f,0.f,0.f};
                #pragma unroll
                for (int ks = 0; ks < 4; ks++) { mma8(C0, A0[ks], B[ks]); mma8(C1, A1[ks], B[ks]); }
                #pragma unroll
                for (int i = 0; i < 4; i++) {
                    H0[j][i] = tf32u(fmaxf(C0[i], 0.f));
                    H1[j][i] = tf32u(fmaxf(C1[i], 0.f));
                }
            }
        }

        // ---- stage 5: FF2 partial over this nh's f-half; H C-frags are A ----
        float C5a[4][4], C5b[4][4];
        #pragma unroll
        for (int nf = 0; nf < 4; nf++)
            #pragma unroll
            for (int i = 0; i < 4; i++) { C5a[nf][i] = 0.f; C5b[nf][i] = 0.f; }
        #pragma unroll
        for (int j = 0; j < 8; j++) {
            const int k0 = nh * 64 + j * 8;
            const uint32_t A0[4] = {H0[j][0], H0[j][2], H0[j][1], H0[j][3]};
            const uint32_t A1[4] = {H1[j][0], H1[j][2], H1[j][1], H1[j][3]};
            #pragma unroll
            for (int nf = 0; nf < 4; nf++) {
                uint32_t B[2];
                LOAD_B2(B, sW2, PW_2, k0, nf * 8);
                mma8(C5a[nf], A0, B);
                mma8(C5b[nf], A1, B);
            }
        }
        // exchange: nh=1 posts partials; nh=0 combines with residual into sX
        if (nh == 1) {
            #pragma unroll
            for (int nf = 0; nf < 4; nf++) {
                *(float2*)&sP[(row0a + r) * PA + nf * 8 + 2 * c]     = make_float2(C5a[nf][0], C5a[nf][1]);
                *(float2*)&sP[(row0a + r + 8) * PA + nf * 8 + 2 * c] = make_float2(C5a[nf][2], C5a[nf][3]);
                *(float2*)&sP[(row0b + r) * PA + nf * 8 + 2 * c]     = make_float2(C5b[nf][0], C5b[nf][1]);
                *(float2*)&sP[(row0b + r + 8) * PA + nf * 8 + 2 * c] = make_float2(C5b[nf][2], C5b[nf][3]);
            }
        }
        __syncthreads();
        if (nh == 0) {
            #pragma unroll
            for (int nf = 0; nf < 4; nf++) {
                float2 q, v2; float2* p;
                p = (float2*)&sX[(row0a + r) * PA + nf * 8 + 2 * c];
                q = *(float2*)&sP[(row0a + r) * PA + nf * 8 + 2 * c];
                v2 = *p; *p = make_float2(C5a[nf][0] + q.x + v2.x, C5a[nf][1] + q.y + v2.y);
                p = (float2*)&sX[(row0a + r + 8) * PA + nf * 8 + 2 * c];
                q = *(float2*)&sP[(row0a + r + 8) * PA + nf * 8 + 2 * c];
                v2 = *p; *p = make_float2(C5a[nf][2] + q.x + v2.x, C5a[nf][3] + q.y + v2.y);
                p = (float2*)&sX[(row0b + r) * PA + nf * 8 + 2 * c];
                q = *(float2*)&sP[(row0b + r) * PA + nf * 8 + 2 * c];
                v2 = *p; *p = make_float2(C5b[nf][0] + q.x + v2.x, C5b[nf][1] + q.y + v2.y);
                p = (float2*)&sX[(row0b + r + 8) * PA + nf * 8 + 2 * c];
                q = *(float2*)&sP[(row0b + r + 8) * PA + nf * 8 + 2 * c];
                v2 = *p; *p = make_float2(C5b[nf][2] + q.x + v2.x, C5b[nf][3] + q.y + v2.y);
            }
        }
        __syncthreads();

        // ---- stage 6: store output ----
        #pragma unroll
        for (int i = 0; i < 4; i++)
            *(float4*)(og + srow * 32 + shalf + i * 4) =
                *(float4*)&sX[srow * PA + shalf + i * 4];
        __syncthreads();
    }
}

extern "C" void kernel_launch(void* const* d_in, const int* in_sizes, int n_in,
                              void* d_out, int out_size) {
    const float* X  = (const float*)d_in[0];
    const float* Wa = (const float*)d_in[1];
    const float* Wp = (const float*)d_in[2];
    const float* W1 = (const float*)d_in[3];
    const float* W2 = (const float*)d_in[4];
    float* Out = (float*)d_out;

    cudaFuncSetAttribute(tblock_mma,
                         cudaFuncAttributeMaxDynamicSharedMemorySize, SMEM_BYTES);
    tblock_mma<<<NUM_CTAS, THREADS, SMEM_BYTES>>>(X, Wa, Wp, W1, W2, Out);
}

// round 7
// speedup vs baseline: 2.7580x; 1.1021x over previous
#include <cuda_runtime.h>
#include <cstdint>

// Fused transformer block via mma.sync tf32 (m16n8k8), sm_103 base target.
// 2M rows x 32, 256-row tiles, 512 threads (16 warps), persistent grid 148.
// FF hidden kept in registers (FF1 C-frags feed FF2 A-slots via W2 row
// permutation {2c,2c+1}); FF2 nf-outer with dual partial buffers.

#define THREADS 512
#define NUM_CTAS 148
#define NUM_TILES 8192

// float offsets in dynamic smem
#define OFF_WQKV 0          // 32 x 104 (N=96 cols permuted [K|Q|V])
#define OFF_WP   3328       // 32 x 40
#define OFF_W1   4608       // 32 x 136
#define OFF_W2   8960       // 128 x 36
#define OFF_X    13568      // 256 x 36
#define OFF_K    22784      // 256 x 36 (reused as FF2 partial buffer 0)
#define OFF_Q    32000      // 256 x 36 (reused as FF2 partial buffer 1)
#define OFF_V    41216      // 256 x 36
#define SMEM_FLOATS 50432
#define SMEM_BYTES  (SMEM_FLOATS * 4)

#define PW_QKV 104
#define PW_P   40
#define PW_1   136
#define PW_2   36
#define PA     36

__device__ __forceinline__ uint32_t tf32u(float x) {
    uint32_t r; asm("cvt.rna.tf32.f32 %0,%1;" : "=r"(r) : "f"(x)); return r;
}
__device__ __forceinline__ float tf32f(float x) {
    float r; asm("cvt.rna.tf32.f32 %0,%1;" : "=f"(r) : "f"(x)); return r;
}
__device__ __forceinline__ void mma8(float c[4], const uint32_t a[4], const uint32_t b[2]) {
    asm volatile(
        "mma.sync.aligned.m16n8k8.row.col.f32.tf32.tf32.f32 "
        "{%0,%1,%2,%3},{%4,%5,%6,%7},{%8,%9},{%0,%1,%2,%3};"
        : "+f"(c[0]), "+f"(c[1]), "+f"(c[2]), "+f"(c[3])
        : "r"(a[0]), "r"(a[1]), "r"(a[2]), "r"(a[3]), "r"(b[0]), "r"(b[1]));
}

// A fragment (16x8) at (row0, k0) from row-major act buffer, converting to tf32.
#define LOAD_A(A, act, pitch, row0, k0) do {                                   \
    (A)[0] = tf32u((act)[((row0) + r) * (pitch) + (k0) + c]);                  \
    (A)[1] = tf32u((act)[((row0) + r + 8) * (pitch) + (k0) + c]);              \
    (A)[2] = tf32u((act)[((row0) + r) * (pitch) + (k0) + c + 4]);              \
    (A)[3] = tf32u((act)[((row0) + r + 8) * (pitch) + (k0) + c + 4]);          \
} while (0)

// B fragment (8x8) at (k0, n0), standard rows {c, c+4}.
#define LOAD_B(B, w, pitch, k0, n0) do {                                       \
    (B)[0] = __float_as_uint((w)[((k0) + c) * (pitch) + (n0) + r]);            \
    (B)[1] = __float_as_uint((w)[((k0) + c + 4) * (pitch) + (n0) + r]);        \
} while (0)

// B fragment with permuted rows {2c, 2c+1}: pairs k-slots with FF1 C-frag layout.
#define LOAD_B2(B, w, pitch, k0, n0) do {                                      \
    (B)[0] = __float_as_uint((w)[((k0) + 2 * c) * (pitch) + (n0) + r]);        \
    (B)[1] = __float_as_uint((w)[((k0) + 2 * c + 1) * (pitch) + (n0) + r]);    \
} while (0)

__global__ void __launch_bounds__(THREADS, 1)
tblock_mma(const float* __restrict__ X, const float* __restrict__ Wa,
           const float* __restrict__ Wp, const float* __restrict__ W1,
           const float* __restrict__ W2, float* __restrict__ Out)
{
    extern __shared__ float sm[];
    float* const sWqkv = sm + OFF_WQKV;
    float* const sWp   = sm + OFF_WP;
    float* const sW1   = sm + OFF_W1;
    float* const sW2   = sm + OFF_W2;
    float* const sX    = sm + OFF_X;
    float* const sK    = sm + OFF_K;
    float* const sQ    = sm + OFF_Q;
    float* const sV    = sm + OFF_V;
    float* const sP0   = sm + OFF_K;    // FF2 partials (K/Q dead by stage 5)
    float* const sP1   = sm + OFF_Q;

    const int tid  = threadIdx.x;
    const int warp = tid >> 5;
    const int lane = tid & 31;
    const int r = lane >> 2;
    const int c = lane & 3;
    const float scale = 0.17677669529663687f;   // 32^{-1/2}, folded into Wq

    // ---------------- pack weights (tf32-rounded) ----------------
    // sWqkv cols permuted: n' in [0,32)=K (h*8+d), [32,64)=Q*scale, [64,96)=V
    for (int idx = tid; idx < 3072; idx += THREADS) {
        int k = idx / 96, n = idx % 96;
        int g = n >> 5, hh = (n & 31) >> 3, d = n & 7;
        float v = Wa[hh * 768 + k * 24 + g * 8 + d];
        if (g == 1) v *= scale;
        sWqkv[k * PW_QKV + n] = tf32f(v);
    }
    for (int idx = tid; idx < 1024; idx += THREADS)
        sWp[(idx >> 5) * PW_P + (idx & 31)] = tf32f(Wp[idx]);
    for (int idx = tid; idx < 4096; idx += THREADS)
        sW1[(idx >> 7) * PW_1 + (idx & 127)] = tf32f(W1[idx]);
    for (int idx = tid; idx < 4096; idx += THREADS)
        sW2[(idx >> 5) * PW_2 + (idx & 31)] = tf32f(W2[idx]);
    __syncthreads();

    const int m  = warp & 7;            // 8 M-blocks of 32 rows
    const int nh = warp >> 3;           // 2 N-halves
    const int row0a = m * 32;
    const int row0b = m * 32 + 16;
    const int srow = tid >> 1;          // 0..255
    const int shalf = (tid & 1) * 16;

    for (int tile = blockIdx.x; tile < NUM_TILES; tile += NUM_CTAS) {
        const float* xg = X + (long long)tile * 8192;
        float* og = Out + (long long)tile * 8192;

        // ---- stage 0: load X tile (256 x 32) -> sX ----
        #pragma unroll
        for (int i = 0; i < 4; i++)
            *(float4*)&sX[srow * PA + shalf + i * 4] =
                *(const float4*)(xg + srow * 32 + shalf + i * 4);
        __syncthreads();

        // ---- stage 1: QKV = X @ Wqkv -> sK/sQ/sV ----
        {
            uint32_t A0[4][4], A1[4][4];
            #pragma unroll
            for (int ks = 0; ks < 4; ks++) {
                LOAD_A(A0[ks], sX, PA, row0a, ks * 8);
                LOAD_A(A1[ks], sX, PA, row0b, ks * 8);
            }
            #pragma unroll
            for (int j = 0; j < 6; j++) {
                const int n0 = nh * 48 + j * 8;
                uint32_t B[4][2];
                #pragma unroll
                for (int ks = 0; ks < 4; ks++) LOAD_B(B[ks], sWqkv, PW_QKV, ks * 8, n0);
                float C0[4] = {0.f,0.f,0.f,0.f}, C1[4] = {0.f,0.f,0.f,0.f};
                #pragma unroll
                for (int ks = 0; ks < 4; ks++) { mma8(C0, A0[ks], B[ks]); mma8(C1, A1[ks], B[ks]); }
                float* cb = (n0 < 32) ? (sK + n0) : (n0 < 64 ? (sQ + n0 - 32) : (sV + n0 - 64));
                *(float2*)&cb[(row0a + r) * PA + 2 * c]     = make_float2(C0[0], C0[1]);
                *(float2*)&cb[(row0a + r + 8) * PA + 2 * c] = make_float2(C0[2], C0[3]);
                *(float2*)&cb[(row0b + r) * PA + 2 * c]     = make_float2(C1[0], C1[1]);
                *(float2*)&cb[(row0b + r + 8) * PA + 2 * c] = make_float2(C1[2], C1[3]);
            }
        }
        __syncthreads();

        // ---- stage 2: attention (CUDA cores), 2 batch items/warp ----
        {
            const int h = lane >> 3, qt = lane & 7, ho = h * 8;
            #pragma unroll 1
            for (int p = 0; p < 2; p++) {
                const int rb = m * 32 + (nh * 2 + p) * 8;
                const float4 qa = *(float4*)&sQ[(rb + qt) * PA + ho];
                const float4 qb = *(float4*)&sQ[(rb + qt) * PA + ho + 4];
                float e[8], mx = -1e30f;
                #pragma unroll
                for (int kt = 0; kt < 8; kt++) {
                    const float4 ka = *(const float4*)&sK[(rb + kt) * PA + ho];
                    const float4 kb = *(const float4*)&sK[(rb + kt) * PA + ho + 4];
                    float acc = qa.x * ka.x;
                    acc = fmaf(qa.y, ka.y, acc); acc = fmaf(qa.z, ka.z, acc);
                    acc = fmaf(qa.w, ka.w, acc); acc = fmaf(qb.x, kb.x, acc);
                    acc = fmaf(qb.y, kb.y, acc); acc = fmaf(qb.z, kb.z, acc);
                    acc = fmaf(qb.w, kb.w, acc);
                    e[kt] = (kt <= qt) ? acc : -1e30f;
                    mx = fmaxf(mx, e[kt]);
                }
                float sum = 0.f;
                #pragma unroll
                for (int kt = 0; kt < 8; kt++) { e[kt] = __expf(e[kt] - mx); sum += e[kt]; }
                const float inv = __fdividef(1.0f, sum);
                float4 oa = make_float4(0.f,0.f,0.f,0.f), ob = make_float4(0.f,0.f,0.f,0.f);
                #pragma unroll
                for (int kt = 0; kt < 8; kt++) {
                    const float w = e[kt] * inv;
                    const float4 va = *(const float4*)&sV[(rb + kt) * PA + ho];
                    const float4 vb = *(const float4*)&sV[(rb + kt) * PA + ho + 4];
                    oa.x = fmaf(w, va.x, oa.x); oa.y = fmaf(w, va.y, oa.y);
                    oa.z = fmaf(w, va.z, oa.z); oa.w = fmaf(w, va.w, oa.w);
                    ob.x = fmaf(w, vb.x, ob.x); ob.y = fmaf(w, vb.y, ob.y);
                    ob.z = fmaf(w, vb.z, ob.z); ob.w = fmaf(w, vb.w, ob.w);
                }
                __syncwarp();
                *(float4*)&sQ[(rb + qt) * PA + ho]     = oa;   // overlay q-slot
                *(float4*)&sQ[(rb + qt) * PA + ho + 4] = ob;
                __syncwarp();
            }
        }
        __syncthreads();

        // ---- stage 3: X1 = attn @ Wp + X -> sX ----
        {
            uint32_t A0[4][4], A1[4][4];
            #pragma unroll
            for (int ks = 0; ks < 4; ks++) {
                LOAD_A(A0[ks], sQ, PA, row0a, ks * 8);
                LOAD_A(A1[ks], sQ, PA, row0b, ks * 8);
            }
            #pragma unroll
            for (int j = 0; j < 2; j++) {
                const int n0 = nh * 16 + j * 8;
                uint32_t B[4][2];
                #pragma unroll
                for (int ks = 0; ks < 4; ks++) LOAD_B(B[ks], sWp, PW_P, ks * 8, n0);
                float C0[4] = {0.f,0.f,0.f,0.f}, C1[4] = {0.f,0.f,0.f,0.f};
                #pragma unroll
                for (int ks = 0; ks < 4; ks++) { mma8(C0, A0[ks], B[ks]); mma8(C1, A1[ks], B[ks]); }
                float2* p00 = (float2*)&sX[(row0a + r) * PA + n0 + 2 * c];
                float2* p01 = (float2*)&sX[(row0a + r + 8) * PA + n0 + 2 * c];
                float2* p10 = (float2*)&sX[(row0b + r) * PA + n0 + 2 * c];
                float2* p11 = (float2*)&sX[(row0b + r + 8) * PA + n0 + 2 * c];
                float2 v;
                v = *p00; *p00 = make_float2(C0[0] + v.x, C0[1] + v.y);
                v = *p01; *p01 = make_float2(C0[2] + v.x, C0[3] + v.y);
                v = *p10; *p10 = make_float2(C1[0] + v.x, C1[1] + v.y);
                v = *p11; *p11 = make_float2(C1[2] + v.x, C1[3] + v.y);
            }
        }
        __syncthreads();

        // ---- stage 4: H = relu(X1 @ W1), kept in registers (f-half per nh) ----
        uint32_t H0[8][4], H1[8][4];
        {
            uint32_t A0[4][4], A1[4][4];
            #pragma unroll
            for (int ks = 0; ks < 4; ks++) {
                LOAD_A(A0[ks], sX, PA, row0a, ks * 8);
                LOAD_A(A1[ks], sX, PA, row0b, ks * 8);
            }
            #pragma unroll
            for (int j = 0; j < 8; j++) {
                const int n0 = nh * 64 + j * 8;
                uint32_t B[4][2];
                #pragma unroll
                for (int ks = 0; ks < 4; ks++) LOAD_B(B[ks], sW1, PW_1, ks * 8, n0);
                float C0[4] = {0.f,0.f,0.f,0.f}, C1[4] = {0.f,0.f,0.f,0.f};
                #pragma unroll
                for (int ks = 0; ks < 4; ks++) { mma8(C0, A0[ks], B[ks]); mma8(C1, A1[ks], B[ks]); }
                #pragma unroll
                for (int i = 0; i < 4; i++) {
                    H0[j][i] = tf32u(fmaxf(C0[i], 0.f));
                    H1[j][i] = tf32u(fmaxf(C1[i], 0.f));
                }
            }
        }

        // ---- stage 5: FF2 partials, nf-outer (8 live accumulators) ----
        {
            float* const sPo = (nh == 0) ? sP0 : sP1;
            #pragma unroll
            for (int nf = 0; nf < 4; nf++) {
                float Ca[4] = {0.f,0.f,0.f,0.f}, Cb[4] = {0.f,0.f,0.f,0.f};
                #pragma unroll
                for (int j = 0; j < 8; j++) {
                    const int k0 = nh * 64 + j * 8;
                    const uint32_t A0[4] = {H0[j][0], H0[j][2], H0[j][1], H0[j][3]};
                    const uint32_t A1[4] = {H1[j][0], H1[j][2], H1[j][1], H1[j][3]};
                    uint32_t B[2];
                    LOAD_B2(B, sW2, PW_2, k0, nf * 8);
                    mma8(Ca, A0, B);
                    mma8(Cb, A1, B);
                }
                *(float2*)&sPo[(row0a + r) * PA + nf * 8 + 2 * c]     = make_float2(Ca[0], Ca[1]);
                *(float2*)&sPo[(row0a + r + 8) * PA + nf * 8 + 2 * c] = make_float2(Ca[2], Ca[3]);
                *(float2*)&sPo[(row0b + r) * PA + nf * 8 + 2 * c]     = make_float2(Cb[0], Cb[1]);
                *(float2*)&sPo[(row0b + r + 8) * PA + nf * 8 + 2 * c] = make_float2(Cb[2], Cb[3]);
            }
        }
        __syncthreads();

        // ---- stage 6: out = X1 + P0 + P1 -> global ----
        #pragma unroll
        for (int i = 0; i < 4; i++) {
            const float4 a = *(float4*)&sX[srow * PA + shalf + i * 4];
            const float4 b = *(float4*)&sP0[srow * PA + shalf + i * 4];
            const float4 d = *(float4*)&sP1[srow * PA + shalf + i * 4];
            *(float4*)(og + srow * 32 + shalf + i * 4) =
                make_float4(a.x + b.x + d.x, a.y + b.y + d.y,
                            a.z + b.z + d.z, a.w + b.w + d.w);
        }
        __syncthreads();
    }
}

extern "C" void kernel_launch(void* const* d_in, const int* in_sizes, int n_in,
                              void* d_out, int out_size) {
    const float* X  = (const float*)d_in[0];
    const float* Wa = (const float*)d_in[1];
    const float* Wp = (const float*)d_in[2];
    const float* W1 = (const float*)d_in[3];
    const float* W2 = (const float*)d_in[4];
    float* Out = (float*)d_out;

    cudaFuncSetAttribute(tblock_mma,
                         cudaFuncAttributeMaxDynamicSharedMemorySize, SMEM_BYTES);
    tblock_mma<<<NUM_CTAS, THREADS, SMEM_BYTES>>>(X, Wa, Wp, W1, W2, Out);
}

// round 8
// speedup vs baseline: 3.1499x; 1.1421x over previous
#include <cuda_runtime.h>
#include <cstdint>

// Fused transformer block via mma.sync tf32 (m16n8k8), sm_103 base target.
// 2M rows x 32, 256-row tiles, 512 threads (16 warps), persistent grid 148.
// Tile loop uses per-pair named barriers (warps {m, m+8}, bar.sync m+1, 64):
// 8 independent 2-warp pipelines per CTA instead of one lock-step chain.

#define THREADS 512
#define NUM_CTAS 148
#define NUM_TILES 8192

// float offsets in dynamic smem
#define OFF_WQKV 0          // 32 x 104 (N=96 cols permuted [K|Q|V])
#define OFF_WP   3328       // 32 x 40
#define OFF_W1   4608       // 32 x 136
#define OFF_W2   8960       // 128 x 36
#define OFF_X    13568      // 256 x 36
#define OFF_K    22784      // 256 x 36 (reused as FF2 partial buffer 0)
#define OFF_Q    32000      // 256 x 36 (reused as FF2 partial buffer 1)
#define OFF_V    41216      // 256 x 36
#define SMEM_FLOATS 50432
#define SMEM_BYTES  (SMEM_FLOATS * 4)

#define PW_QKV 104
#define PW_P   40
#define PW_1   136
#define PW_2   36
#define PA     36

__device__ __forceinline__ uint32_t tf32u(float x) {
    uint32_t r; asm("cvt.rna.tf32.f32 %0,%1;" : "=r"(r) : "f"(x)); return r;
}
__device__ __forceinline__ float tf32f(float x) {
    float r; asm("cvt.rna.tf32.f32 %0,%1;" : "=f"(r) : "f"(x)); return r;
}
__device__ __forceinline__ void mma8(float c[4], const uint32_t a[4], const uint32_t b[2]) {
    asm volatile(
        "mma.sync.aligned.m16n8k8.row.col.f32.tf32.tf32.f32 "
        "{%0,%1,%2,%3},{%4,%5,%6,%7},{%8,%9},{%0,%1,%2,%3};"
        : "+f"(c[0]), "+f"(c[1]), "+f"(c[2]), "+f"(c[3])
        : "r"(a[0]), "r"(a[1]), "r"(a[2]), "r"(a[3]), "r"(b[0]), "r"(b[1]));
}

// pair barrier: warps {m, m+8} (64 threads), named barrier id m+1
#define PBAR() asm volatile("bar.sync %0, 64;" :: "r"(m + 1) : "memory")

// A fragment (16x8) at (row0, k0) from row-major act buffer, converting to tf32.
#define LOAD_A(A, act, pitch, row0, k0) do {                                   \
    (A)[0] = tf32u((act)[((row0) + r) * (pitch) + (k0) + c]);                  \
    (A)[1] = tf32u((act)[((row0) + r + 8) * (pitch) + (k0) + c]);              \
    (A)[2] = tf32u((act)[((row0) + r) * (pitch) + (k0) + c + 4]);              \
    (A)[3] = tf32u((act)[((row0) + r + 8) * (pitch) + (k0) + c + 4]);          \
} while (0)

// B fragment (8x8) at (k0, n0), standard rows {c, c+4}.
#define LOAD_B(B, w, pitch, k0, n0) do {                                       \
    (B)[0] = __float_as_uint((w)[((k0) + c) * (pitch) + (n0) + r]);            \
    (B)[1] = __float_as_uint((w)[((k0) + c + 4) * (pitch) + (n0) + r]);        \
} while (0)

// B fragment with permuted rows {2c, 2c+1}: pairs k-slots with FF1 C-frag layout.
#define LOAD_B2(B, w, pitch, k0, n0) do {                                      \
    (B)[0] = __float_as_uint((w)[((k0) + 2 * c) * (pitch) + (n0) + r]);        \
    (B)[1] = __float_as_uint((w)[((k0) + 2 * c + 1) * (pitch) + (n0) + r]);    \
} while (0)

__global__ void __launch_bounds__(THREADS, 1)
tblock_mma(const float* __restrict__ X, const float* __restrict__ Wa,
           const float* __restrict__ Wp, const float* __restrict__ W1,
           const float* __restrict__ W2, float* __restrict__ Out)
{
    extern __shared__ float sm[];
    float* const sWqkv = sm + OFF_WQKV;
    float* const sWp   = sm + OFF_WP;
    float* const sW1   = sm + OFF_W1;
    float* const sW2   = sm + OFF_W2;
    float* const sX    = sm + OFF_X;
    float* const sK    = sm + OFF_K;
    float* const sQ    = sm + OFF_Q;
    float* const sV    = sm + OFF_V;
    float* const sP0   = sm + OFF_K;    // FF2 partials (K/Q dead by stage 5)
    float* const sP1   = sm + OFF_Q;

    const int tid  = threadIdx.x;
    const int warp = tid >> 5;
    const int lane = tid & 31;
    const int r = lane >> 2;
    const int c = lane & 3;
    const float scale = 0.17677669529663687f;   // 32^{-1/2}, folded into Wq

    // ---------------- pack weights (tf32-rounded) ----------------
    // sWqkv cols permuted: n' in [0,32)=K (h*8+d), [32,64)=Q*scale, [64,96)=V
    for (int idx = tid; idx < 3072; idx += THREADS) {
        int k = idx / 96, n = idx % 96;
        int g = n >> 5, hh = (n & 31) >> 3, d = n & 7;
        float v = Wa[hh * 768 + k * 24 + g * 8 + d];
        if (g == 1) v *= scale;
        sWqkv[k * PW_QKV + n] = tf32f(v);
    }
    for (int idx = tid; idx < 1024; idx += THREADS)
        sWp[(idx >> 5) * PW_P + (idx & 31)] = tf32f(Wp[idx]);
    for (int idx = tid; idx < 4096; idx += THREADS)
        sW1[(idx >> 7) * PW_1 + (idx & 127)] = tf32f(W1[idx]);
    for (int idx = tid; idx < 4096; idx += THREADS)
        sW2[(idx >> 5) * PW_2 + (idx & 31)] = tf32f(W2[idx]);
    __syncthreads();

    const int m  = warp & 7;            // 8 M-blocks of 32 rows (pair index)
    const int nh = warp >> 3;           // 2 N-halves within the pair
    const int row0a = m * 32;
    const int row0b = m * 32 + 16;
    // per-pair staging: this warp loads/stores rows [m*32+nh*16, +16)
    const int prow = m * 32 + nh * 16 + (lane >> 1);
    const int psh  = (lane & 1) * 16;

    for (int tile = blockIdx.x; tile < NUM_TILES; tile += NUM_CTAS) {
        const float* xg = X + (long long)tile * 8192;
        float* og = Out + (long long)tile * 8192;

        // ---- stage 0: load pair's 32 rows of X -> sX ----
        #pragma unroll
        for (int i = 0; i < 4; i++)
            *(float4*)&sX[prow * PA + psh + i * 4] =
                *(const float4*)(xg + prow * 32 + psh + i * 4);
        PBAR();

        // ---- stage 1: QKV = X @ Wqkv -> sK/sQ/sV ----
        {
            uint32_t A0[4][4], A1[4][4];
            #pragma unroll
            for (int ks = 0; ks < 4; ks++) {
                LOAD_A(A0[ks], sX, PA, row0a, ks * 8);
                LOAD_A(A1[ks], sX, PA, row0b, ks * 8);
            }
            #pragma unroll
            for (int j = 0; j < 6; j++) {
                const int n0 = nh * 48 + j * 8;
                uint32_t B[4][2];
                #pragma unroll
                for (int ks = 0; ks < 4; ks++) LOAD_B(B[ks], sWqkv, PW_QKV, ks * 8, n0);
                float C0[4] = {0.f,0.f,0.f,0.f}, C1[4] = {0.f,0.f,0.f,0.f};
                #pragma unroll
                for (int ks = 0; ks < 4; ks++) { mma8(C0, A0[ks], B[ks]); mma8(C1, A1[ks], B[ks]); }
                float* cb = (n0 < 32) ? (sK + n0) : (n0 < 64 ? (sQ + n0 - 32) : (sV + n0 - 64));
                *(float2*)&cb[(row0a + r) * PA + 2 * c]     = make_float2(C0[0], C0[1]);
                *(float2*)&cb[(row0a + r + 8) * PA + 2 * c] = make_float2(C0[2], C0[3]);
                *(float2*)&cb[(row0b + r) * PA + 2 * c]     = make_float2(C1[0], C1[1]);
                *(float2*)&cb[(row0b + r + 8) * PA + 2 * c] = make_float2(C1[2], C1[3]);
            }
        }
        PBAR();

        // ---- stage 2: attention (CUDA cores), 2 batch items/warp ----
        {
            const int h = lane >> 3, qt = lane & 7, ho = h * 8;
            #pragma unroll 1
            for (int p = 0; p < 2; p++) {
                const int rb = m * 32 + (nh * 2 + p) * 8;
                const float4 qa = *(float4*)&sQ[(rb + qt) * PA + ho];
                const float4 qb = *(float4*)&sQ[(rb + qt) * PA + ho + 4];
                float e[8], mx = -1e30f;
                #pragma unroll
                for (int kt = 0; kt < 8; kt++) {
                    const float4 ka = *(const float4*)&sK[(rb + kt) * PA + ho];
                    const float4 kb = *(const float4*)&sK[(rb + kt) * PA + ho + 4];
                    float acc = qa.x * ka.x;
                    acc = fmaf(qa.y, ka.y, acc); acc = fmaf(qa.z, ka.z, acc);
                    acc = fmaf(qa.w, ka.w, acc); acc = fmaf(qb.x, kb.x, acc);
                    acc = fmaf(qb.y, kb.y, acc); acc = fmaf(qb.z, kb.z, acc);
                    acc = fmaf(qb.w, kb.w, acc);
                    e[kt] = (kt <= qt) ? acc : -1e30f;
                    mx = fmaxf(mx, e[kt]);
                }
                float sum = 0.f;
                #pragma unroll
                for (int kt = 0; kt < 8; kt++) { e[kt] = __expf(e[kt] - mx); sum += e[kt]; }
                const float inv = __fdividef(1.0f, sum);
                float4 oa = make_float4(0.f,0.f,0.f,0.f), ob = make_float4(0.f,0.f,0.f,0.f);
                #pragma unroll
                for (int kt = 0; kt < 8; kt++) {
                    const float w = e[kt] * inv;
                    const float4 va = *(const float4*)&sV[(rb + kt) * PA + ho];
                    const float4 vb = *(const float4*)&sV[(rb + kt) * PA + ho + 4];
                    oa.x = fmaf(w, va.x, oa.x); oa.y = fmaf(w, va.y, oa.y);
                    oa.z = fmaf(w, va.z, oa.z); oa.w = fmaf(w, va.w, oa.w);
                    ob.x = fmaf(w, vb.x, ob.x); ob.y = fmaf(w, vb.y, ob.y);
                    ob.z = fmaf(w, vb.z, ob.z); ob.w = fmaf(w, vb.w, ob.w);
                }
                __syncwarp();
                *(float4*)&sQ[(rb + qt) * PA + ho]     = oa;   // overlay q-slot
                *(float4*)&sQ[(rb + qt) * PA + ho + 4] = ob;
                __syncwarp();
            }
        }
        PBAR();

        // ---- stage 3: X1 = attn @ Wp + X -> sX ----
        {
            uint32_t A0[4][4], A1[4][4];
            #pragma unroll
            for (int ks = 0; ks < 4; ks++) {
                LOAD_A(A0[ks], sQ, PA, row0a, ks * 8);
                LOAD_A(A1[ks], sQ, PA, row0b, ks * 8);
            }
            #pragma unroll
            for (int j = 0; j < 2; j++) {
                const int n0 = nh * 16 + j * 8;
                uint32_t B[4][2];
                #pragma unroll
                for (int ks = 0; ks < 4; ks++) LOAD_B(B[ks], sWp, PW_P, ks * 8, n0);
                float C0[4] = {0.f,0.f,0.f,0.f}, C1[4] = {0.f,0.f,0.f,0.f};
                #pragma unroll
                for (int ks = 0; ks < 4; ks++) { mma8(C0, A0[ks], B[ks]); mma8(C1, A1[ks], B[ks]); }
                float2* p00 = (float2*)&sX[(row0a + r) * PA + n0 + 2 * c];
                float2* p01 = (float2*)&sX[(row0a + r + 8) * PA + n0 + 2 * c];
                float2* p10 = (float2*)&sX[(row0b + r) * PA + n0 + 2 * c];
                float2* p11 = (float2*)&sX[(row0b + r + 8) * PA + n0 + 2 * c];
                float2 v;
                v = *p00; *p00 = make_float2(C0[0] + v.x, C0[1] + v.y);
                v = *p01; *p01 = make_float2(C0[2] + v.x, C0[3] + v.y);
                v = *p10; *p10 = make_float2(C1[0] + v.x, C1[1] + v.y);
                v = *p11; *p11 = make_float2(C1[2] + v.x, C1[3] + v.y);
            }
        }
        PBAR();

        // ---- stage 4: H = relu(X1 @ W1), kept in registers (f-half per nh) ----
        uint32_t H0[8][4], H1[8][4];
        {
            uint32_t A0[4][4], A1[4][4];
            #pragma unroll
            for (int ks = 0; ks < 4; ks++) {
                LOAD_A(A0[ks], sX, PA, row0a, ks * 8);
                LOAD_A(A1[ks], sX, PA, row0b, ks * 8);
            }
            #pragma unroll
            for (int j = 0; j < 8; j++) {
                const int n0 = nh * 64 + j * 8;
                uint32_t B[4][2];
                #pragma unroll
                for (int ks = 0; ks < 4; ks++) LOAD_B(B[ks], sW1, PW_1, ks * 8, n0);
                float C0[4] = {0.f,0.f,0.f,0.f}, C1[4] = {0.f,0.f,0.f,0.f};
                #pragma unroll
                for (int ks = 0; ks < 4; ks++) { mma8(C0, A0[ks], B[ks]); mma8(C1, A1[ks], B[ks]); }
                #pragma unroll
                for (int i = 0; i < 4; i++) {
                    H0[j][i] = tf32u(fmaxf(C0[i], 0.f));
                    H1[j][i] = tf32u(fmaxf(C1[i], 0.f));
                }
            }
        }

        // ---- stage 5: FF2 partials, nf-outer (8 live accumulators) ----
        {
            float* const sPo = (nh == 0) ? sP0 : sP1;
            #pragma unroll
            for (int nf = 0; nf < 4; nf++) {
                float Ca[4] = {0.f,0.f,0.f,0.f}, Cb[4] = {0.f,0.f,0.f,0.f};
                #pragma unroll
                for (int j = 0; j < 8; j++) {
                    const int k0 = nh * 64 + j * 8;
                    const uint32_t A0[4] = {H0[j][0], H0[j][2], H0[j][1], H0[j][3]};
                    const uint32_t A1[4] = {H1[j][0], H1[j][2], H1[j][1], H1[j][3]};
                    uint32_t B[2];
                    LOAD_B2(B, sW2, PW_2, k0, nf * 8);
                    mma8(Ca, A0, B);
                    mma8(Cb, A1, B);
                }
                *(float2*)&sPo[(row0a + r) * PA + nf * 8 + 2 * c]     = make_float2(Ca[0], Ca[1]);
                *(float2*)&sPo[(row0a + r + 8) * PA + nf * 8 + 2 * c] = make_float2(Ca[2], Ca[3]);
                *(float2*)&sPo[(row0b + r) * PA + nf * 8 + 2 * c]     = make_float2(Cb[0], Cb[1]);
                *(float2*)&sPo[(row0b + r + 8) * PA + nf * 8 + 2 * c] = make_float2(Cb[2], Cb[3]);
            }
        }
        PBAR();

        // ---- stage 6: out = X1 + P0 + P1 -> global (pair's 32 rows) ----
        #pragma unroll
        for (int i = 0; i < 4; i++) {
            const float4 a = *(float4*)&sX[prow * PA + psh + i * 4];
            const float4 b = *(float4*)&sP0[prow * PA + psh + i * 4];
            const float4 d = *(float4*)&sP1[prow * PA + psh + i * 4];
            *(float4*)(og + prow * 32 + psh + i * 4) =
                make_float4(a.x + b.x + d.x, a.y + b.y + d.y,
                            a.z + b.z + d.z, a.w + b.w + d.w);
        }
        PBAR();   // pair done reading sX/sP before next tile's stage 0 write
    }
}

extern "C" void kernel_launch(void* const* d_in, const int* in_sizes, int n_in,
                              void* d_out, int out_size) {
    const float* X  = (const float*)d_in[0];
    const float* Wa = (const float*)d_in[1];
    const float* Wp = (const float*)d_in[2];
    const float* W1 = (const float*)d_in[3];
    const float* W2 = (const float*)d_in[4];
    float* Out = (float*)d_out;

    cudaFuncSetAttribute(tblock_mma,
                         cudaFuncAttributeMaxDynamicSharedMemorySize, SMEM_BYTES);
    tblock_mma<<<NUM_CTAS, THREADS, SMEM_BYTES>>>(X, Wa, Wp, W1, W2, Out);
}

// round 9
// speedup vs baseline: 3.3413x; 1.0608x over previous
#include <cuda_runtime.h>
#include <cstdint>

// Fused transformer block via mma.sync tf32 (m16n8k8), sm_103 base target.
// 2M rows x 32, 256-row tiles, 512 threads (16 warps), persistent grid 148.
// Per-pair named barriers (warps {m, m+8}); weights packed fragment-major
// (one LDS.64 per B fragment); L2-prefetch of next tile's X.

#define THREADS 512
#define NUM_CTAS 148
#define NUM_TILES 8192

// float offsets in dynamic smem (fragment-major weights)
#define OFF_WQKV 0          // 12 nb x 4 kb x 32 lanes x 2 = 3072
#define OFF_WP   3072       // 4 x 4 x 64 = 1024
#define OFF_W1   4096       // 16 x 4 x 64 = 4096
#define OFF_W2   8192       // 4 x 16 x 64 = 4096 (rows {2c,2c+1} baked in)
#define OFF_X    12288      // 256 x 36
#define OFF_K    21504      // 256 x 36 (reused as FF2 partial buffer 0)
#define OFF_Q    30720      // 256 x 36 (reused as FF2 partial buffer 1)
#define OFF_V    39936      // 256 x 36
#define SMEM_FLOATS 49152
#define SMEM_BYTES  (SMEM_FLOATS * 4)

#define PA 36

__device__ __forceinline__ uint32_t tf32u(float x) {
    uint32_t r; asm("cvt.rna.tf32.f32 %0,%1;" : "=r"(r) : "f"(x)); return r;
}
__device__ __forceinline__ float tf32f(float x) {
    float r; asm("cvt.rna.tf32.f32 %0,%1;" : "=f"(r) : "f"(x)); return r;
}
__device__ __forceinline__ void mma8(float c[4], const uint32_t a[4], const uint32_t b[2]) {
    asm volatile(
        "mma.sync.aligned.m16n8k8.row.col.f32.tf32.tf32.f32 "
        "{%0,%1,%2,%3},{%4,%5,%6,%7},{%8,%9},{%0,%1,%2,%3};"
        : "+f"(c[0]), "+f"(c[1]), "+f"(c[2]), "+f"(c[3])
        : "r"(a[0]), "r"(a[1]), "r"(a[2]), "r"(a[3]), "r"(b[0]), "r"(b[1]));
}

// pair barrier: warps {m, m+8} (64 threads), named barrier id m+1
#define PBAR() asm volatile("bar.sync %0, 64;" :: "r"(m + 1) : "memory")

// A fragment (16x8) at (row0, k0) from row-major act buffer, converting to tf32.
#define LOAD_A(A, act, pitch, row0, k0) do {                                   \
    (A)[0] = tf32u((act)[((row0) + r) * (pitch) + (k0) + c]);                  \
    (A)[1] = tf32u((act)[((row0) + r + 8) * (pitch) + (k0) + c]);              \
    (A)[2] = tf32u((act)[((row0) + r) * (pitch) + (k0) + c + 4]);              \
    (A)[3] = tf32u((act)[((row0) + r + 8) * (pitch) + (k0) + c + 4]);          \
} while (0)

// B fragment from fragment-major buffer: one LDS.64, conflict-free.
#define LOAD_BF(B, buf, fi) do {                                               \
    const float2 v2_ = *(const float2*)&(buf)[(((fi) << 5) + lane) << 1];      \
    (B)[0] = __float_as_uint(v2_.x);                                           \
    (B)[1] = __float_as_uint(v2_.y);                                           \
} while (0)

__device__ __forceinline__ float wa_val(const float* __restrict__ Wa,
                                        int k, int n, float scale) {
    int g = n >> 5, hh = (n & 31) >> 3, d = n & 7;
    float v = Wa[hh * 768 + k * 24 + g * 8 + d];
    return (g == 1) ? v * scale : v;
}

__global__ void __launch_bounds__(THREADS, 1)
tblock_mma(const float* __restrict__ X, const float* __restrict__ Wa,
           const float* __restrict__ Wp, const float* __restrict__ W1,
           const float* __restrict__ W2, float* __restrict__ Out)
{
    extern __shared__ float sm[];
    float* const sWqkv = sm + OFF_WQKV;
    float* const sWp   = sm + OFF_WP;
    float* const sW1   = sm + OFF_W1;
    float* const sW2   = sm + OFF_W2;
    float* const sX    = sm + OFF_X;
    float* const sK    = sm + OFF_K;
    float* const sQ    = sm + OFF_Q;
    float* const sV    = sm + OFF_V;
    float* const sP0   = sm + OFF_K;    // FF2 partials (K/Q dead by stage 5)
    float* const sP1   = sm + OFF_Q;

    const int tid  = threadIdx.x;
    const int warp = tid >> 5;
    const int lane = tid & 31;
    const int r = lane >> 2;
    const int c = lane & 3;
    const float scale = 0.17677669529663687f;   // 32^{-1/2}, folded into Wq

    // -------- pack weights fragment-major (tf32-rounded) --------
    // frag (nb, kb): lane l=(rr,cl) holds (W[kb*8+cl][nb*8+rr], W[kb*8+cl+4][nb*8+rr])
    for (int idx = tid; idx < 1536; idx += THREADS) {      // Wqkv: 12 nb x 4 kb
        int nb = idx >> 7, kb = (idx >> 5) & 3, l = idx & 31;
        int rr = l >> 2, cl = l & 3;
        int n = nb * 8 + rr, k0 = kb * 8;
        sWqkv[((nb * 4 + kb) * 32 + l) * 2 + 0] = tf32f(wa_val(Wa, k0 + cl, n, scale));
        sWqkv[((nb * 4 + kb) * 32 + l) * 2 + 1] = tf32f(wa_val(Wa, k0 + cl + 4, n, scale));
    }
    for (int idx = tid; idx < 512; idx += THREADS) {       // Wp: 4 nb x 4 kb
        int nb = idx >> 7, kb = (idx >> 5) & 3, l = idx & 31;
        int rr = l >> 2, cl = l & 3;
        int n = nb * 8 + rr, k0 = kb * 8;
        sWp[((nb * 4 + kb) * 32 + l) * 2 + 0] = tf32f(Wp[(k0 + cl) * 32 + n]);
        sWp[((nb * 4 + kb) * 32 + l) * 2 + 1] = tf32f(Wp[(k0 + cl + 4) * 32 + n]);
    }
    for (int idx = tid; idx < 2048; idx += THREADS) {      // W1: 16 nb x 4 kb
        int nb = idx >> 7, kb = (idx >> 5) & 3, l = idx & 31;
        int rr = l >> 2, cl = l & 3;
        int n = nb * 8 + rr, k0 = kb * 8;
        sW1[((nb * 4 + kb) * 32 + l) * 2 + 0] = tf32f(W1[(k0 + cl) * 128 + n]);
        sW1[((nb * 4 + kb) * 32 + l) * 2 + 1] = tf32f(W1[(k0 + cl + 4) * 128 + n]);
    }
    for (int idx = tid; idx < 2048; idx += THREADS) {      // W2: 4 nb x 16 kb, rows {2c,2c+1}
        int nb = idx >> 9, kb = (idx >> 5) & 15, l = idx & 31;
        int rr = l >> 2, cl = l & 3;
        int n = nb * 8 + rr, k0 = kb * 8;
        sW2[((nb * 16 + kb) * 32 + l) * 2 + 0] = tf32f(W2[(k0 + 2 * cl) * 32 + n]);
        sW2[((nb * 16 + kb) * 32 + l) * 2 + 1] = tf32f(W2[(k0 + 2 * cl + 1) * 32 + n]);
    }
    __syncthreads();

    const int m  = warp & 7;            // 8 M-blocks of 32 rows (pair index)
    const int nh = warp >> 3;           // 2 N-halves within the pair
    const int row0a = m * 32;
    const int row0b = m * 32 + 16;
    // per-pair staging: this warp loads/stores rows [m*32+nh*16, +16)
    const int prow = m * 32 + nh * 16 + (lane >> 1);
    const int psh  = (lane & 1) * 16;

    for (int tile = blockIdx.x; tile < NUM_TILES; tile += NUM_CTAS) {
        const float* xg = X + (long long)tile * 8192;
        float* og = Out + (long long)tile * 8192;

        // ---- stage 0: load pair's 32 rows of X -> sX; prefetch next tile ----
        #pragma unroll
        for (int i = 0; i < 4; i++)
            *(float4*)&sX[prow * PA + psh + i * 4] =
                *(const float4*)(xg + prow * 32 + psh + i * 4);
        {
            const long long ntile = (long long)tile + NUM_CTAS;
            if (ntile < NUM_TILES && (lane & 1) == 0) {
                const float* np = X + ntile * 8192 + prow * 32;
                asm volatile("prefetch.global.L2 [%0];" :: "l"(np));
            }
        }
        PBAR();

        // ---- stage 1: QKV = X @ Wqkv -> sK/sQ/sV ----
        {
            uint32_t A0[4][4], A1[4][4];
            #pragma unroll
            for (int ks = 0; ks < 4; ks++) {
                LOAD_A(A0[ks], sX, PA, row0a, ks * 8);
                LOAD_A(A1[ks], sX, PA, row0b, ks * 8);
            }
            #pragma unroll
            for (int j = 0; j < 6; j++) {
                const int n0 = nh * 48 + j * 8;
                uint32_t B[4][2];
                #pragma unroll
                for (int ks = 0; ks < 4; ks++) LOAD_BF(B[ks], sWqkv, (nh * 6 + j) * 4 + ks);
                float C0[4] = {0.f,0.f,0.f,0.f}, C1[4] = {0.f,0.f,0.f,0.f};
                #pragma unroll
                for (int ks = 0; ks < 4; ks++) { mma8(C0, A0[ks], B[ks]); mma8(C1, A1[ks], B[ks]); }
                float* cb = (n0 < 32) ? (sK + n0) : (n0 < 64 ? (sQ + n0 - 32) : (sV + n0 - 64));
                *(float2*)&cb[(row0a + r) * PA + 2 * c]     = make_float2(C0[0], C0[1]);
                *(float2*)&cb[(row0a + r + 8) * PA + 2 * c] = make_float2(C0[2], C0[3]);
                *(float2*)&cb[(row0b + r) * PA + 2 * c]     = make_float2(C1[0], C1[1]);
                *(float2*)&cb[(row0b + r + 8) * PA + 2 * c] = make_float2(C1[2], C1[3]);
            }
        }
        PBAR();

        // ---- stage 2: attention (CUDA cores), 2 batch items/warp ----
        {
            const int h = lane >> 3, qt = lane & 7, ho = h * 8;
            #pragma unroll 1
            for (int p = 0; p < 2; p++) {
                const int rb = m * 32 + (nh * 2 + p) * 8;
                const float4 qa = *(float4*)&sQ[(rb + qt) * PA + ho];
                const float4 qb = *(float4*)&sQ[(rb + qt) * PA + ho + 4];
                float e[8], mx = -1e30f;
                #pragma unroll
                for (int kt = 0; kt < 8; kt++) {
                    const float4 ka = *(const float4*)&sK[(rb + kt) * PA + ho];
                    const float4 kb = *(const float4*)&sK[(rb + kt) * PA + ho + 4];
                    float acc = qa.x * ka.x;
                    acc = fmaf(qa.y, ka.y, acc); acc = fmaf(qa.z, ka.z, acc);
                    acc = fmaf(qa.w, ka.w, acc); acc = fmaf(qb.x, kb.x, acc);
                    acc = fmaf(qb.y, kb.y, acc); acc = fmaf(qb.z, kb.z, acc);
                    acc = fmaf(qb.w, kb.w, acc);
                    e[kt] = (kt <= qt) ? acc : -1e30f;
                    mx = fmaxf(mx, e[kt]);
                }
                float sum = 0.f;
                #pragma unroll
                for (int kt = 0; kt < 8; kt++) { e[kt] = __expf(e[kt] - mx); sum += e[kt]; }
                const float inv = __fdividef(1.0f, sum);
                float4 oa = make_float4(0.f,0.f,0.f,0.f), ob = make_float4(0.f,0.f,0.f,0.f);
                #pragma unroll
                for (int kt = 0; kt < 8; kt++) {
                    const float w = e[kt] * inv;
                    const float4 va = *(const float4*)&sV[(rb + kt) * PA + ho];
                    const float4 vb = *(const float4*)&sV[(rb + kt) * PA + ho + 4];
                    oa.x = fmaf(w, va.x, oa.x); oa.y = fmaf(w, va.y, oa.y);
                    oa.z = fmaf(w, va.z, oa.z); oa.w = fmaf(w, va.w, oa.w);
                    ob.x = fmaf(w, vb.x, ob.x); ob.y = fmaf(w, vb.y, ob.y);
                    ob.z = fmaf(w, vb.z, ob.z); ob.w = fmaf(w, vb.w, ob.w);
                }
                __syncwarp();
                *(float4*)&sQ[(rb + qt) * PA + ho]     = oa;   // overlay q-slot
                *(float4*)&sQ[(rb + qt) * PA + ho + 4] = ob;
                __syncwarp();
            }
        }
        PBAR();

        // ---- stage 3: X1 = attn @ Wp + X -> sX ----
        {
            uint32_t A0[4][4], A1[4][4];
            #pragma unroll
            for (int ks = 0; ks < 4; ks++) {
                LOAD_A(A0[ks], sQ, PA, row0a, ks * 8);
                LOAD_A(A1[ks], sQ, PA, row0b, ks * 8);
            }
            #pragma unroll
            for (int j = 0; j < 2; j++) {
                const int n0 = nh * 16 + j * 8;
                uint32_t B[4][2];
                #pragma unroll
                for (int ks = 0; ks < 4; ks++) LOAD_BF(B[ks], sWp, (nh * 2 + j) * 4 + ks);
                float C0[4] = {0.f,0.f,0.f,0.f}, C1[4] = {0.f,0.f,0.f,0.f};
                #pragma unroll
                for (int ks = 0; ks < 4; ks++) { mma8(C0, A0[ks], B[ks]); mma8(C1, A1[ks], B[ks]); }
                float2* p00 = (float2*)&sX[(row0a + r) * PA + n0 + 2 * c];
                float2* p01 = (float2*)&sX[(row0a + r + 8) * PA + n0 + 2 * c];
                float2* p10 = (float2*)&sX[(row0b + r) * PA + n0 + 2 * c];
                float2* p11 = (float2*)&sX[(row0b + r + 8) * PA + n0 + 2 * c];
                float2 v;
                v = *p00; *p00 = make_float2(C0[0] + v.x, C0[1] + v.y);
                v = *p01; *p01 = make_float2(C0[2] + v.x, C0[3] + v.y);
                v = *p10; *p10 = make_float2(C1[0] + v.x, C1[1] + v.y);
                v = *p11; *p11 = make_float2(C1[2] + v.x, C1[3] + v.y);
            }
        }
        PBAR();

        // ---- stage 4: H = relu(X1 @ W1), kept in registers (f-half per nh) ----
        uint32_t H0[8][4], H1[8][4];
        {
            uint32_t A0[4][4], A1[4][4];
            #pragma unroll
            for (int ks = 0; ks < 4; ks++) {
                LOAD_A(A0[ks], sX, PA, row0a, ks * 8);
                LOAD_A(A1[ks], sX, PA, row0b, ks * 8);
            }
            #pragma unroll
            for (int j = 0; j < 8; j++) {
                uint32_t B[4][2];
                #pragma unroll
                for (int ks = 0; ks < 4; ks++) LOAD_BF(B[ks], sW1, (nh * 8 + j) * 4 + ks);
                float C0[4] = {0.f,0.f,0.f,0.f}, C1[4] = {0.f,0.f,0.f,0.f};
                #pragma unroll
                for (int ks = 0; ks < 4; ks++) { mma8(C0, A0[ks], B[ks]); mma8(C1, A1[ks], B[ks]); }
                #pragma unroll
                for (int i = 0; i < 4; i++) {
                    H0[j][i] = tf32u(fmaxf(C0[i], 0.f));
                    H1[j][i] = tf32u(fmaxf(C1[i], 0.f));
                }
            }
        }

        // ---- stage 5: FF2 partials, nf-outer (8 live accumulators) ----
        {
            float* const sPo = (nh == 0) ? sP0 : sP1;
            #pragma unroll
            for (int nf = 0; nf < 4; nf++) {
                float Ca[4] = {0.f,0.f,0.f,0.f}, Cb[4] = {0.f,0.f,0.f,0.f};
                #pragma unroll
                for (int j = 0; j < 8; j++) {
                    const uint32_t A0[4] = {H0[j][0], H0[j][2], H0[j][1], H0[j][3]};
                    const uint32_t A1[4] = {H1[j][0], H1[j][2], H1[j][1], H1[j][3]};
                    uint32_t B[2];
                    LOAD_BF(B, sW2, nf * 16 + nh * 8 + j);
                    mma8(Ca, A0, B);
                    mma8(Cb, A1, B);
                }
                *(float2*)&sPo[(row0a + r) * PA + nf * 8 + 2 * c]     = make_float2(Ca[0], Ca[1]);
                *(float2*)&sPo[(row0a + r + 8) * PA + nf * 8 + 2 * c] = make_float2(Ca[2], Ca[3]);
                *(float2*)&sPo[(row0b + r) * PA + nf * 8 + 2 * c]     = make_float2(Cb[0], Cb[1]);
                *(float2*)&sPo[(row0b + r + 8) * PA + nf * 8 + 2 * c] = make_float2(Cb[2], Cb[3]);
            }
        }
        PBAR();

        // ---- stage 6: out = X1 + P0 + P1 -> global (pair's 32 rows) ----
        #pragma unroll
        for (int i = 0; i < 4; i++) {
            const float4 a = *(float4*)&sX[prow * PA + psh + i * 4];
            const float4 b = *(float4*)&sP0[prow * PA + psh + i * 4];
            const float4 d = *(float4*)&sP1[prow * PA + psh + i * 4];
            *(float4*)(og + prow * 32 + psh + i * 4) =
                make_float4(a.x + b.x + d.x, a.y + b.y + d.y,
                            a.z + b.z + d.z, a.w + b.w + d.w);
        }
        PBAR();   // pair done reading sX/sP before next tile's stage 0 write
    }
}

extern "C" void kernel_launch(void* const* d_in, const int* in_sizes, int n_in,
                              void* d_out, int out_size) {
    const float* X  = (const float*)d_in[0];
    const float* Wa = (const float*)d_in[1];
    const float* Wp = (const float*)d_in[2];
    const float* W1 = (const float*)d_in[3];
    const float* W2 = (const float*)d_in[4];
    float* Out = (float*)d_out;

    cudaFuncSetAttribute(tblock_mma,
                         cudaFuncAttributeMaxDynamicSharedMemorySize, SMEM_BYTES);
    tblock_mma<<<NUM_CTAS, THREADS, SMEM_BYTES>>>(X, Wa, Wp, W1, W2, Out);
}

// round 10
// speedup vs baseline: 4.4363x; 1.3277x over previous
#include <cuda_runtime.h>
#include <cuda_fp16.h>
#include <cstdint>

// Fused transformer block via mma.sync fp16 (m16n8k16, fp32 accumulate).
// 2M rows x 32, 256-row tiles, 512 threads (16 warps), persistent grid 148.
// Per-pair named barriers; fragment-major fp16 weights (one LDS.64 per B frag,
// covering k=16); activations carried fp16 for MMA, fp32 for residuals.

#define THREADS 512
#define NUM_CTAS 148
#define NUM_TILES 8192

// u32 offsets in dynamic smem
#define OFF_WQKV 0          // 24 frags x 64
#define OFF_WP   1536       // 8 x 64
#define OFF_W1   2048       // 32 x 64
#define OFF_W2   4096       // 32 x 64
#define OFF_X    6144       // fp32 256 x 36
#define OFF_XH   15360      // fp16 256 x 20 (X then X1)
#define OFF_KH   20480      // fp16 256 x 20
#define OFF_QH   25600      // fp16 256 x 20 (Q then attn-out)
#define OFF_VH   30720      // fp16 256 x 20
#define OFF_P0   35840      // fp32 256 x 36
#define OFF_P1   45056      // fp32 256 x 36
#define SMEM_U32 54272
#define SMEM_BYTES (SMEM_U32 * 4)

#define PH 20
#define PA 36

__device__ __forceinline__ uint32_t pkh(float lo, float hi) {
    uint32_t r;
    asm("cvt.rn.f16x2.f32 %0, %1, %2;" : "=r"(r) : "f"(hi), "f"(lo));
    return r;
}
__device__ __forceinline__ float2 uph(uint32_t u) {
    __half2 h = *reinterpret_cast<__half2*>(&u);
    return __half22float2(h);
}
__device__ __forceinline__ void mma16(float c[4], const uint32_t a[4], const uint32_t b[2]) {
    asm volatile(
        "mma.sync.aligned.m16n8k16.row.col.f32.f16.f16.f32 "
        "{%0,%1,%2,%3},{%4,%5,%6,%7},{%8,%9},{%0,%1,%2,%3};"
        : "+f"(c[0]), "+f"(c[1]), "+f"(c[2]), "+f"(c[3])
        : "r"(a[0]), "r"(a[1]), "r"(a[2]), "r"(a[3]), "r"(b[0]), "r"(b[1]));
}

// pair barrier: warps {m, m+8} (64 threads), named barrier id m+1
#define PBAR() asm volatile("bar.sync %0, 64;" :: "r"(m + 1) : "memory")

// A fragment (16 rows x k16) from packed fp16 buffer (pitch PH u32), kp0 = k0/2
#define LOAD_AH(A, buf, row0, kp0) do {                                        \
    (A)[0] = (buf)[((row0) + r) * PH + (kp0) + c];                             \
    (A)[1] = (buf)[((row0) + r + 8) * PH + (kp0) + c];                         \
    (A)[2] = (buf)[((row0) + r) * PH + (kp0) + 4 + c];                         \
    (A)[3] = (buf)[((row0) + r + 8) * PH + (kp0) + 4 + c];                     \
} while (0)

// B fragment from fragment-major buffer: one LDS.64, conflict-free.
#define LOAD_BF(B, buf, fi) do {                                               \
    const uint2 v_ = *(const uint2*)&(buf)[((fi) << 6) + (lane << 1)];         \
    (B)[0] = v_.x; (B)[1] = v_.y;                                              \
} while (0)

__device__ __forceinline__ float wa_val(const float* __restrict__ Wa,
                                        int k, int n, float scale) {
    int g = n >> 5, hh = (n & 31) >> 3, d = n & 7;
    float v = Wa[hh * 768 + k * 24 + g * 8 + d];
    return (g == 1) ? v * scale : v;
}

__global__ void __launch_bounds__(THREADS, 1)
tblock_mma(const float* __restrict__ X, const float* __restrict__ Wa,
           const float* __restrict__ Wp, const float* __restrict__ W1,
           const float* __restrict__ W2, float* __restrict__ Out)
{
    extern __shared__ uint32_t smu[];
    uint32_t* const sWQ = smu + OFF_WQKV;
    uint32_t* const sWP = smu + OFF_WP;
    uint32_t* const sW1 = smu + OFF_W1;
    uint32_t* const sW2 = smu + OFF_W2;
    float*    const sX  = (float*)(smu + OFF_X);
    uint32_t* const sXH = smu + OFF_XH;
    uint32_t* const sKH = smu + OFF_KH;
    uint32_t* const sQH = smu + OFF_QH;
    uint32_t* const sVH = smu + OFF_VH;
    float*    const sP0 = (float*)(smu + OFF_P0);
    float*    const sP1 = (float*)(smu + OFF_P1);

    const int tid  = threadIdx.x;
    const int warp = tid >> 5;
    const int lane = tid & 31;
    const int r = lane >> 2;
    const int c = lane & 3;
    const float scale = 0.17677669529663687f;   // 32^{-1/2}, folded into Wq

    // -------- pack weights fragment-major, fp16 --------
    // frag f=(nb,t): lane (r,c): b0 = {W[k0+2c][n], W[k0+2c+1][n]}, b1 = +8
    for (int idx = tid; idx < 768; idx += THREADS) {       // Wqkv: 12 nb x 2 t
        int f = idx >> 5, l = idx & 31;
        int nb = f >> 1, t = f & 1;
        int rr = l >> 2, cl = l & 3;
        int n = nb * 8 + rr, k0 = t * 16;
        sWQ[f * 64 + l * 2 + 0] = pkh(wa_val(Wa, k0 + 2 * cl,     n, scale),
                                      wa_val(Wa, k0 + 2 * cl + 1, n, scale));
        sWQ[f * 64 + l * 2 + 1] = pkh(wa_val(Wa, k0 + 2 * cl + 8, n, scale),
                                      wa_val(Wa, k0 + 2 * cl + 9, n, scale));
    }
    for (int idx = tid; idx < 256; idx += THREADS) {       // Wp: 4 nb x 2 t
        int f = idx >> 5, l = idx & 31;
        int nb = f >> 1, t = f & 1;
        int rr = l >> 2, cl = l & 3;
        int n = nb * 8 + rr, k0 = t * 16;
        sWP[f * 64 + l * 2 + 0] = pkh(Wp[(k0 + 2 * cl) * 32 + n], Wp[(k0 + 2 * cl + 1) * 32 + n]);
        sWP[f * 64 + l * 2 + 1] = pkh(Wp[(k0 + 2 * cl + 8) * 32 + n], Wp[(k0 + 2 * cl + 9) * 32 + n]);
    }
    for (int idx = tid; idx < 1024; idx += THREADS) {      // W1: 16 nb x 2 t
        int f = idx >> 5, l = idx & 31;
        int nb = f >> 1, t = f & 1;
        int rr = l >> 2, cl = l & 3;
        int n = nb * 8 + rr, k0 = t * 16;
        sW1[f * 64 + l * 2 + 0] = pkh(W1[(k0 + 2 * cl) * 128 + n], W1[(k0 + 2 * cl + 1) * 128 + n]);
        sW1[f * 64 + l * 2 + 1] = pkh(W1[(k0 + 2 * cl + 8) * 128 + n], W1[(k0 + 2 * cl + 9) * 128 + n]);
    }
    for (int idx = tid; idx < 1024; idx += THREADS) {      // W2: 4 nb x 8 ks
        int f = idx >> 5, l = idx & 31;
        int nb = f >> 3, ks = f & 7;
        int rr = l >> 2, cl = l & 3;
        int n = nb * 8 + rr, k0 = ks * 16;
        sW2[f * 64 + l * 2 + 0] = pkh(W2[(k0 + 2 * cl) * 32 + n], W2[(k0 + 2 * cl + 1) * 32 + n]);
        sW2[f * 64 + l * 2 + 1] = pkh(W2[(k0 + 2 * cl + 8) * 32 + n], W2[(k0 + 2 * cl + 9) * 32 + n]);
    }
    __syncthreads();

    const int m  = warp & 7;            // 8 M-blocks of 32 rows (pair index)
    const int nh = warp >> 3;           // 2 N-halves within the pair
    const int row0a = m * 32;
    const int row0b = m * 32 + 16;
    const int prow = m * 32 + nh * 16 + (lane >> 1);
    const int psh  = (lane & 1) * 16;

    for (int tile = blockIdx.x; tile < NUM_TILES; tile += NUM_CTAS) {
        const float* xg = X + (long long)tile * 8192;
        float* og = Out + (long long)tile * 8192;

        // ---- stage 0: load pair's 32 rows -> sX (fp32) + sXH (fp16) ----
        {
            float4 xv[4];
            #pragma unroll
            for (int i = 0; i < 4; i++)
                xv[i] = *(const float4*)(xg + prow * 32 + psh + i * 4);
            #pragma unroll
            for (int i = 0; i < 4; i++)
                *(float4*)&sX[prow * PA + psh + i * 4] = xv[i];
            uint32_t hx[8];
            #pragma unroll
            for (int i = 0; i < 4; i++) {
                hx[2 * i]     = pkh(xv[i].x, xv[i].y);
                hx[2 * i + 1] = pkh(xv[i].z, xv[i].w);
            }
            *(uint4*)&sXH[prow * PH + (psh >> 1)]     = make_uint4(hx[0], hx[1], hx[2], hx[3]);
            *(uint4*)&sXH[prow * PH + (psh >> 1) + 4] = make_uint4(hx[4], hx[5], hx[6], hx[7]);
            const long long ntile = (long long)tile + NUM_CTAS;
            if (ntile < NUM_TILES && (lane & 1) == 0) {
                const float* np = X + ntile * 8192 + prow * 32;
                asm volatile("prefetch.global.L2 [%0];" :: "l"(np));
            }
        }
        PBAR();

        // ---- stage 1: QKV = X @ Wqkv -> sKH/sQH/sVH (fp16) ----
        {
            uint32_t A0[2][4], A1[2][4];
            LOAD_AH(A0[0], sXH, row0a, 0); LOAD_AH(A0[1], sXH, row0a, 8);
            LOAD_AH(A1[0], sXH, row0b, 0); LOAD_AH(A1[1], sXH, row0b, 8);
            #pragma unroll
            for (int j = 0; j < 6; j++) {
                const int n0 = nh * 48 + j * 8;
                const int fb = (nh * 6 + j) * 2;
                uint32_t B0[2], B1[2];
                LOAD_BF(B0, sWQ, fb); LOAD_BF(B1, sWQ, fb + 1);
                float C0[4] = {0.f,0.f,0.f,0.f}, C1[4] = {0.f,0.f,0.f,0.f};
                mma16(C0, A0[0], B0); mma16(C0, A0[1], B1);
                mma16(C1, A1[0], B0); mma16(C1, A1[1], B1);
                uint32_t* cb; int np;
                if (n0 < 32)      { cb = sKH; np = n0 >> 1; }
                else if (n0 < 64) { cb = sQH; np = (n0 - 32) >> 1; }
                else              { cb = sVH; np = (n0 - 64) >> 1; }
                cb[(row0a + r) * PH + np + c]     = pkh(C0[0], C0[1]);
                cb[(row0a + r + 8) * PH + np + c] = pkh(C0[2], C0[3]);
                cb[(row0b + r) * PH + np + c]     = pkh(C1[0], C1[1]);
                cb[(row0b + r + 8) * PH + np + c] = pkh(C1[2], C1[3]);
            }
        }
        PBAR();

        // ---- stage 2: attention (CUDA cores, fp32 math on fp16 data) ----
        {
            const int h = lane >> 3, qt = lane & 7;
            #pragma unroll 1
            for (int p = 0; p < 2; p++) {
                const int rb = m * 32 + (nh * 2 + p) * 8;
                const uint4 qu = *(const uint4*)&sQH[(rb + qt) * PH + 4 * h];
                const float2 q0 = uph(qu.x), q1 = uph(qu.y),
                             q2 = uph(qu.z), q3 = uph(qu.w);
                float e[8], mx = -1e30f;
                #pragma unroll
                for (int kt = 0; kt < 8; kt++) {
                    const uint4 ku = *(const uint4*)&sKH[(rb + kt) * PH + 4 * h];
                    const float2 k0 = uph(ku.x), k1 = uph(ku.y),
                                 k2 = uph(ku.z), k3 = uph(ku.w);
                    float acc = q0.x * k0.x;
                    acc = fmaf(q0.y, k0.y, acc);
                    acc = fmaf(q1.x, k1.x, acc); acc = fmaf(q1.y, k1.y, acc);
                    acc = fmaf(q2.x, k2.x, acc); acc = fmaf(q2.y, k2.y, acc);
                    acc = fmaf(q3.x, k3.x, acc); acc = fmaf(q3.y, k3.y, acc);
                    e[kt] = (kt <= qt) ? acc : -1e30f;
                    mx = fmaxf(mx, e[kt]);
                }
                float sum = 0.f;
                #pragma unroll
                for (int kt = 0; kt < 8; kt++) { e[kt] = __expf(e[kt] - mx); sum += e[kt]; }
                const float inv = __fdividef(1.0f, sum);
                float2 o[4];
                #pragma unroll
                for (int i = 0; i < 4; i++) o[i] = make_float2(0.f, 0.f);
                #pragma unroll
                for (int kt = 0; kt < 8; kt++) {
                    const float w = e[kt] * inv;
                    const uint4 vu = *(const uint4*)&sVH[(rb + kt) * PH + 4 * h];
                    const float2 v0 = uph(vu.x), v1 = uph(vu.y),
                                 v2 = uph(vu.z), v3 = uph(vu.w);
                    o[0].x = fmaf(w, v0.x, o[0].x); o[0].y = fmaf(w, v0.y, o[0].y);
                    o[1].x = fmaf(w, v1.x, o[1].x); o[1].y = fmaf(w, v1.y, o[1].y);
                    o[2].x = fmaf(w, v2.x, o[2].x); o[2].y = fmaf(w, v2.y, o[2].y);
                    o[3].x = fmaf(w, v3.x, o[3].x); o[3].y = fmaf(w, v3.y, o[3].y);
                }
                __syncwarp();
                *(uint4*)&sQH[(rb + qt) * PH + 4 * h] =
                    make_uint4(pkh(o[0].x, o[0].y), pkh(o[1].x, o[1].y),
                               pkh(o[2].x, o[2].y), pkh(o[3].x, o[3].y));
                __syncwarp();
            }
        }
        PBAR();

        // ---- stage 3: X1 = attn @ Wp + X -> sX (fp32) + sXH (fp16) ----
        {
            uint32_t A0[2][4], A1[2][4];
            LOAD_AH(A0[0], sQH, row0a, 0); LOAD_AH(A0[1], sQH, row0a, 8);
            LOAD_AH(A1[0], sQH, row0b, 0); LOAD_AH(A1[1], sQH, row0b, 8);
            #pragma unroll
            for (int j = 0; j < 2; j++) {
                const int n0 = nh * 16 + j * 8;
                const int fb = (nh * 2 + j) * 2;
                uint32_t B0[2], B1[2];
                LOAD_BF(B0, sWP, fb); LOAD_BF(B1, sWP, fb + 1);
                float C0[4] = {0.f,0.f,0.f,0.f}, C1[4] = {0.f,0.f,0.f,0.f};
                mma16(C0, A0[0], B0); mma16(C0, A0[1], B1);
                mma16(C1, A1[0], B0); mma16(C1, A1[1], B1);
                float2* p00 = (float2*)&sX[(row0a + r) * PA + n0 + 2 * c];
                float2* p01 = (float2*)&sX[(row0a + r + 8) * PA + n0 + 2 * c];
                float2* p10 = (float2*)&sX[(row0b + r) * PA + n0 + 2 * c];
                float2* p11 = (float2*)&sX[(row0b + r + 8) * PA + n0 + 2 * c];
                float2 v; float s0, s1;
                v = *p00; s0 = C0[0] + v.x; s1 = C0[1] + v.y; *p00 = make_float2(s0, s1);
                sXH[(row0a + r) * PH + (n0 >> 1) + c] = pkh(s0, s1);
                v = *p01; s0 = C0[2] + v.x; s1 = C0[3] + v.y; *p01 = make_float2(s0, s1);
                sXH[(row0a + r + 8) * PH + (n0 >> 1) + c] = pkh(s0, s1);
                v = *p10; s0 = C1[0] + v.x; s1 = C1[1] + v.y; *p10 = make_float2(s0, s1);
                sXH[(row0b + r) * PH + (n0 >> 1) + c] = pkh(s0, s1);
                v = *p11; s0 = C1[2] + v.x; s1 = C1[3] + v.y; *p11 = make_float2(s0, s1);
                sXH[(row0b + r + 8) * PH + (n0 >> 1) + c] = pkh(s0, s1);
            }
        }
        PBAR();

        // ---- stage 4: H = relu(X1 @ W1), kept in fp16x2 registers ----
        uint32_t H0a[8], H0b[8], H1a[8], H1b[8];
        {
            uint32_t A0[2][4], A1[2][4];
            LOAD_AH(A0[0], sXH, row0a, 0); LOAD_AH(A0[1], sXH, row0a, 8);
            LOAD_AH(A1[0], sXH, row0b, 0); LOAD_AH(A1[1], sXH, row0b, 8);
            #pragma unroll
            for (int j = 0; j < 8; j++) {
                const int fb = (nh * 8 + j) * 2;
                uint32_t B0[2], B1[2];
                LOAD_BF(B0, sW1, fb); LOAD_BF(B1, sW1, fb + 1);
                float C0[4] = {0.f,0.f,0.f,0.f}, C1[4] = {0.f,0.f,0.f,0.f};
                mma16(C0, A0[0], B0); mma16(C0, A0[1], B1);
                mma16(C1, A1[0], B0); mma16(C1, A1[1], B1);
                H0a[j] = pkh(fmaxf(C0[0], 0.f), fmaxf(C0[1], 0.f));
                H0b[j] = pkh(fmaxf(C0[2], 0.f), fmaxf(C0[3], 0.f));
                H1a[j] = pkh(fmaxf(C1[0], 0.f), fmaxf(C1[1], 0.f));
                H1b[j] = pkh(fmaxf(C1[2], 0.f), fmaxf(C1[3], 0.f));
            }
        }

        // ---- stage 5: FF2 partials; H C-frags feed A-slots natively ----
        {
            float* const sPo = (nh == 0) ? sP0 : sP1;
            #pragma unroll
            for (int nf = 0; nf < 4; nf++) {
                float Ca[4] = {0.f,0.f,0.f,0.f}, Cb[4] = {0.f,0.f,0.f,0.f};
                #pragma unroll
                for (int t = 0; t < 4; t++) {
                    const uint32_t A0[4] = {H0a[2*t], H0b[2*t], H0a[2*t+1], H0b[2*t+1]};
                    const uint32_t A1[4] = {H1a[2*t], H1b[2*t], H1a[2*t+1], H1b[2*t+1]};
                    uint32_t B[2];
                    LOAD_BF(B, sW2, nf * 8 + nh * 4 + t);
                    mma16(Ca, A0, B); mma16(Cb, A1, B);
                }
                *(float2*)&sPo[(row0a + r) * PA + nf * 8 + 2 * c]     = make_float2(Ca[0], Ca[1]);
                *(float2*)&sPo[(row0a + r + 8) * PA + nf * 8 + 2 * c] = make_float2(Ca[2], Ca[3]);
                *(float2*)&sPo[(row0b + r) * PA + nf * 8 + 2 * c]     = make_float2(Cb[0], Cb[1]);
                *(float2*)&sPo[(row0b + r + 8) * PA + nf * 8 + 2 * c] = make_float2(Cb[2], Cb[3]);
            }
        }
        PBAR();

        // ---- stage 6: out = X1 + P0 + P1 -> global (pair's 32 rows) ----
        #pragma unroll
        for (int i = 0; i < 4; i++) {
            const float4 a = *(float4*)&sX[prow * PA + psh + i * 4];
            const float4 b = *(float4*)&sP0[prow * PA + psh + i * 4];
            const float4 d = *(float4*)&sP1[prow * PA + psh + i * 4];
            *(float4*)(og + prow * 32 + psh + i * 4) =
                make_float4(a.x + b.x + d.x, a.y + b.y + d.y,
                            a.z + b.z + d.z, a.w + b.w + d.w);
        }
        PBAR();   // pair done reading sX/sP before next tile's stage 0 write
    }
}

extern "C" void kernel_launch(void* const* d_in, const int* in_sizes, int n_in,
                              void* d_out, int out_size) {
    const float* X  = (const float*)d_in[0];
    const float* Wa = (const float*)d_in[1];
    const float* Wp = (const float*)d_in[2];
    const float* W1 = (const float*)d_in[3];
    const float* W2 = (const float*)d_in[4];
    float* Out = (float*)d_out;

    cudaFuncSetAttribute(tblock_mma,
                         cudaFuncAttributeMaxDynamicSharedMemorySize, SMEM_BYTES);
    tblock_mma<<<NUM_CTAS, THREADS, SMEM_BYTES>>>(X, Wa, Wp, W1, W2, Out);
}

// round 11
// speedup vs baseline: 4.5815x; 1.0327x over previous
#include <cuda_runtime.h>
#include <cuda_fp16.h>
#include <cstdint>

// Fused transformer block via mma.sync fp16 (m16n8k16, fp32 accumulate).
// 2M rows x 32, 256-row tiles, 512 threads (16 warps), persistent grid 148.
// Per-pair named barriers; fragment-major fp16 weights; attention in
// half2-native HFMA2 (softmax fp32), output stored frag-ready (no cvts).

#define THREADS 512
#define NUM_CTAS 148
#define NUM_TILES 8192

// u32 offsets in dynamic smem
#define OFF_WQKV 0          // 24 frags x 64
#define OFF_WP   1536       // 8 x 64
#define OFF_W1   2048       // 32 x 64
#define OFF_W2   4096       // 32 x 64
#define OFF_X    6144       // fp32 256 x 36
#define OFF_XH   15360      // fp16 256 x 20 (X then X1)
#define OFF_KH   20480      // fp16 256 x 20
#define OFF_QH   25600      // fp16 256 x 20 (Q then attn-out)
#define OFF_VH   30720      // fp16 256 x 20
#define OFF_P0   35840      // fp32 256 x 36
#define OFF_P1   45056      // fp32 256 x 36
#define SMEM_U32 54272
#define SMEM_BYTES (SMEM_U32 * 4)

#define PH 20
#define PA 36

__device__ __forceinline__ uint32_t pkh(float lo, float hi) {
    uint32_t r;
    asm("cvt.rn.f16x2.f32 %0, %1, %2;" : "=r"(r) : "f"(hi), "f"(lo));
    return r;
}
__device__ __forceinline__ __half2 u2h(uint32_t u) {
    return *reinterpret_cast<__half2*>(&u);
}
__device__ __forceinline__ uint32_t h2u(__half2 h) {
    return *reinterpret_cast<uint32_t*>(&h);
}
__device__ __forceinline__ void mma16(float c[4], const uint32_t a[4], const uint32_t b[2]) {
    asm volatile(
        "mma.sync.aligned.m16n8k16.row.col.f32.f16.f16.f32 "
        "{%0,%1,%2,%3},{%4,%5,%6,%7},{%8,%9},{%0,%1,%2,%3};"
        : "+f"(c[0]), "+f"(c[1]), "+f"(c[2]), "+f"(c[3])
        : "r"(a[0]), "r"(a[1]), "r"(a[2]), "r"(a[3]), "r"(b[0]), "r"(b[1]));
}

// pair barrier: warps {m, m+8} (64 threads), named barrier id m+1
#define PBAR() asm volatile("bar.sync %0, 64;" :: "r"(m + 1) : "memory")

// A fragment (16 rows x k16) from packed fp16 buffer (pitch PH u32), kp0 = k0/2
#define LOAD_AH(A, buf, row0, kp0) do {                                        \
    (A)[0] = (buf)[((row0) + r) * PH + (kp0) + c];                             \
    (A)[1] = (buf)[((row0) + r + 8) * PH + (kp0) + c];                         \
    (A)[2] = (buf)[((row0) + r) * PH + (kp0) + 4 + c];                         \
    (A)[3] = (buf)[((row0) + r + 8) * PH + (kp0) + 4 + c];                     \
} while (0)

// B fragment from fragment-major buffer: one LDS.64, conflict-free.
#define LOAD_BF(B, buf, fi) do {                                               \
    const uint2 v_ = *(const uint2*)&(buf)[((fi) << 6) + (lane << 1)];         \
    (B)[0] = v_.x; (B)[1] = v_.y;                                              \
} while (0)

__device__ __forceinline__ float wa_val(const float* __restrict__ Wa,
                                        int k, int n, float scale) {
    int g = n >> 5, hh = (n & 31) >> 3, d = n & 7;
    float v = Wa[hh * 768 + k * 24 + g * 8 + d];
    return (g == 1) ? v * scale : v;
}

__global__ void __launch_bounds__(THREADS, 1)
tblock_mma(const float* __restrict__ X, const float* __restrict__ Wa,
           const float* __restrict__ Wp, const float* __restrict__ W1,
           const float* __restrict__ W2, float* __restrict__ Out)
{
    extern __shared__ uint32_t smu[];
    uint32_t* const sWQ = smu + OFF_WQKV;
    uint32_t* const sWP = smu + OFF_WP;
    uint32_t* const sW1 = smu + OFF_W1;
    uint32_t* const sW2 = smu + OFF_W2;
    float*    const sX  = (float*)(smu + OFF_X);
    uint32_t* const sXH = smu + OFF_XH;
    uint32_t* const sKH = smu + OFF_KH;
    uint32_t* const sQH = smu + OFF_QH;
    uint32_t* const sVH = smu + OFF_VH;
    float*    const sP0 = (float*)(smu + OFF_P0);
    float*    const sP1 = (float*)(smu + OFF_P1);

    const int tid  = threadIdx.x;
    const int warp = tid >> 5;
    const int lane = tid & 31;
    const int r = lane >> 2;
    const int c = lane & 3;
    const float scale = 0.17677669529663687f;   // 32^{-1/2}, folded into Wq

    // -------- pack weights fragment-major, fp16 --------
    for (int idx = tid; idx < 768; idx += THREADS) {       // Wqkv: 12 nb x 2 t
        int f = idx >> 5, l = idx & 31;
        int nb = f >> 1, t = f & 1;
        int rr = l >> 2, cl = l & 3;
        int n = nb * 8 + rr, k0 = t * 16;
        sWQ[f * 64 + l * 2 + 0] = pkh(wa_val(Wa, k0 + 2 * cl,     n, scale),
                                      wa_val(Wa, k0 + 2 * cl + 1, n, scale));
        sWQ[f * 64 + l * 2 + 1] = pkh(wa_val(Wa, k0 + 2 * cl + 8, n, scale),
                                      wa_val(Wa, k0 + 2 * cl + 9, n, scale));
    }
    for (int idx = tid; idx < 256; idx += THREADS) {       // Wp: 4 nb x 2 t
        int f = idx >> 5, l = idx & 31;
        int nb = f >> 1, t = f & 1;
        int rr = l >> 2, cl = l & 3;
        int n = nb * 8 + rr, k0 = t * 16;
        sWP[f * 64 + l * 2 + 0] = pkh(Wp[(k0 + 2 * cl) * 32 + n], Wp[(k0 + 2 * cl + 1) * 32 + n]);
        sWP[f * 64 + l * 2 + 1] = pkh(Wp[(k0 + 2 * cl + 8) * 32 + n], Wp[(k0 + 2 * cl + 9) * 32 + n]);
    }
    for (int idx = tid; idx < 1024; idx += THREADS) {      // W1: 16 nb x 2 t
        int f = idx >> 5, l = idx & 31;
        int nb = f >> 1, t = f & 1;
        int rr = l >> 2, cl = l & 3;
        int n = nb * 8 + rr, k0 = t * 16;
        sW1[f * 64 + l * 2 + 0] = pkh(W1[(k0 + 2 * cl) * 128 + n], W1[(k0 + 2 * cl + 1) * 128 + n]);
        sW1[f * 64 + l * 2 + 1] = pkh(W1[(k0 + 2 * cl + 8) * 128 + n], W1[(k0 + 2 * cl + 9) * 128 + n]);
    }
    for (int idx = tid; idx < 1024; idx += THREADS) {      // W2: 4 nb x 8 ks
        int f = idx >> 5, l = idx & 31;
        int nb = f >> 3, ks = f & 7;
        int rr = l >> 2, cl = l & 3;
        int n = nb * 8 + rr, k0 = ks * 16;
        sW2[f * 64 + l * 2 + 0] = pkh(W2[(k0 + 2 * cl) * 32 + n], W2[(k0 + 2 * cl + 1) * 32 + n]);
        sW2[f * 64 + l * 2 + 1] = pkh(W2[(k0 + 2 * cl + 8) * 32 + n], W2[(k0 + 2 * cl + 9) * 32 + n]);
    }
    __syncthreads();

    const int m  = warp & 7;            // 8 M-blocks of 32 rows (pair index)
    const int nh = warp >> 3;           // 2 N-halves within the pair
    const int row0a = m * 32;
    const int row0b = m * 32 + 16;
    const int prow = m * 32 + nh * 16 + (lane >> 1);
    const int psh  = (lane & 1) * 16;

    for (int tile = blockIdx.x; tile < NUM_TILES; tile += NUM_CTAS) {
        const float* xg = X + (long long)tile * 8192;
        float* og = Out + (long long)tile * 8192;

        // ---- stage 0: load pair's 32 rows -> sX (fp32) + sXH (fp16) ----
        {
            float4 xv[4];
            #pragma unroll
            for (int i = 0; i < 4; i++)
                xv[i] = *(const float4*)(xg + prow * 32 + psh + i * 4);
            #pragma unroll
            for (int i = 0; i < 4; i++)
                *(float4*)&sX[prow * PA + psh + i * 4] = xv[i];
            uint32_t hx[8];
            #pragma unroll
            for (int i = 0; i < 4; i++) {
                hx[2 * i]     = pkh(xv[i].x, xv[i].y);
                hx[2 * i + 1] = pkh(xv[i].z, xv[i].w);
            }
            *(uint4*)&sXH[prow * PH + (psh >> 1)]     = make_uint4(hx[0], hx[1], hx[2], hx[3]);
            *(uint4*)&sXH[prow * PH + (psh >> 1) + 4] = make_uint4(hx[4], hx[5], hx[6], hx[7]);
            const long long ntile = (long long)tile + NUM_CTAS;
            if (ntile < NUM_TILES && (lane & 1) == 0) {
                const float* np = X + ntile * 8192 + prow * 32;
                asm volatile("prefetch.global.L2 [%0];" :: "l"(np));
            }
        }
        PBAR();

        // ---- stage 1: QKV = X @ Wqkv -> sKH/sQH/sVH (fp16) ----
        {
            uint32_t A0[2][4], A1[2][4];
            LOAD_AH(A0[0], sXH, row0a, 0); LOAD_AH(A0[1], sXH, row0a, 8);
            LOAD_AH(A1[0], sXH, row0b, 0); LOAD_AH(A1[1], sXH, row0b, 8);
            #pragma unroll
            for (int j = 0; j < 6; j++) {
                const int n0 = nh * 48 + j * 8;
                const int fb = (nh * 6 + j) * 2;
                uint32_t B0[2], B1[2];
                LOAD_BF(B0, sWQ, fb); LOAD_BF(B1, sWQ, fb + 1);
                float C0[4] = {0.f,0.f,0.f,0.f}, C1[4] = {0.f,0.f,0.f,0.f};
                mma16(C0, A0[0], B0); mma16(C0, A0[1], B1);
                mma16(C1, A1[0], B0); mma16(C1, A1[1], B1);
                uint32_t* cb; int np;
                if (n0 < 32)      { cb = sKH; np = n0 >> 1; }
                else if (n0 < 64) { cb = sQH; np = (n0 - 32) >> 1; }
                else              { cb = sVH; np = (n0 - 64) >> 1; }
                cb[(row0a + r) * PH + np + c]     = pkh(C0[0], C0[1]);
                cb[(row0a + r + 8) * PH + np + c] = pkh(C0[2], C0[3]);
                cb[(row0b + r) * PH + np + c]     = pkh(C1[0], C1[1]);
                cb[(row0b + r + 8) * PH + np + c] = pkh(C1[2], C1[3]);
            }
        }
        PBAR();

        // ---- stage 2: attention, half2-native (softmax fp32) ----
        {
            const int h = lane >> 3, qt = lane & 7;
            #pragma unroll 1
            for (int p = 0; p < 2; p++) {
                const int rb = m * 32 + (nh * 2 + p) * 8;
                const uint4 qu = *(const uint4*)&sQH[(rb + qt) * PH + 4 * h];
                const __half2 q0 = u2h(qu.x), q1 = u2h(qu.y),
                              q2 = u2h(qu.z), q3 = u2h(qu.w);
                float e[8], mx = -1e30f;
                #pragma unroll
                for (int kt = 0; kt < 8; kt++) {
                    const uint4 ku = *(const uint4*)&sKH[(rb + kt) * PH + 4 * h];
                    __half2 acc = __hmul2(q0, u2h(ku.x));
                    acc = __hfma2(q1, u2h(ku.y), acc);
                    acc = __hfma2(q2, u2h(ku.z), acc);
                    acc = __hfma2(q3, u2h(ku.w), acc);
                    const float s = __low2float(acc) + __high2float(acc);
                    e[kt] = (kt <= qt) ? s : -1e30f;
                    mx = fmaxf(mx, e[kt]);
                }
                float sum = 0.f;
                #pragma unroll
                for (int kt = 0; kt < 8; kt++) { e[kt] = __expf(e[kt] - mx); sum += e[kt]; }
                const float inv = __fdividef(1.0f, sum);
                __half2 o0 = __float2half2_rn(0.f), o1 = o0, o2 = o0, o3 = o0;
                #pragma unroll
                for (int kt = 0; kt < 8; kt++) {
                    const __half2 wh = __float2half2_rn(e[kt] * inv);
                    const uint4 vu = *(const uint4*)&sVH[(rb + kt) * PH + 4 * h];
                    o0 = __hfma2(wh, u2h(vu.x), o0);
                    o1 = __hfma2(wh, u2h(vu.y), o1);
                    o2 = __hfma2(wh, u2h(vu.z), o2);
                    o3 = __hfma2(wh, u2h(vu.w), o3);
                }
                __syncwarp();
                *(uint4*)&sQH[(rb + qt) * PH + 4 * h] =
                    make_uint4(h2u(o0), h2u(o1), h2u(o2), h2u(o3));
                __syncwarp();
            }
        }
        PBAR();

        // ---- stage 3: X1 = attn @ Wp + X -> sX (fp32) + sXH (fp16) ----
        {
            uint32_t A0[2][4], A1[2][4];
            LOAD_AH(A0[0], sQH, row0a, 0); LOAD_AH(A0[1], sQH, row0a, 8);
            LOAD_AH(A1[0], sQH, row0b, 0); LOAD_AH(A1[1], sQH, row0b, 8);
            #pragma unroll
            for (int j = 0; j < 2; j++) {
                const int n0 = nh * 16 + j * 8;
                const int fb = (nh * 2 + j) * 2;
                uint32_t B0[2], B1[2];
                LOAD_BF(B0, sWP, fb); LOAD_BF(B1, sWP, fb + 1);
                float C0[4] = {0.f,0.f,0.f,0.f}, C1[4] = {0.f,0.f,0.f,0.f};
                mma16(C0, A0[0], B0); mma16(C0, A0[1], B1);
                mma16(C1, A1[0], B0); mma16(C1, A1[1], B1);
                float2* p00 = (float2*)&sX[(row0a + r) * PA + n0 + 2 * c];
                float2* p01 = (float2*)&sX[(row0a + r + 8) * PA + n0 + 2 * c];
                float2* p10 = (float2*)&sX[(row0b + r) * PA + n0 + 2 * c];
                float2* p11 = (float2*)&sX[(row0b + r + 8) * PA + n0 + 2 * c];
                float2 v; float s0, s1;
                v = *p00; s0 = C0[0] + v.x; s1 = C0[1] + v.y; *p00 = make_float2(s0, s1);
                sXH[(row0a + r) * PH + (n0 >> 1) + c] = pkh(s0, s1);
                v = *p01; s0 = C0[2] + v.x; s1 = C0[3] + v.y; *p01 = make_float2(s0, s1);
                sXH[(row0a + r + 8) * PH + (n0 >> 1) + c] = pkh(s0, s1);
                v = *p10; s0 = C1[0] + v.x; s1 = C1[1] + v.y; *p10 = make_float2(s0, s1);
                sXH[(row0b + r) * PH + (n0 >> 1) + c] = pkh(s0, s1);
                v = *p11; s0 = C1[2] + v.x; s1 = C1[3] + v.y; *p11 = make_float2(s0, s1);
                sXH[(row0b + r + 8) * PH + (n0 >> 1) + c] = pkh(s0, s1);
            }
        }
        PBAR();

        // ---- stage 4: H = relu(X1 @ W1), kept in fp16x2 registers ----
        uint32_t H0a[8], H0b[8], H1a[8], H1b[8];
        {
            uint32_t A0[2][4], A1[2][4];
            LOAD_AH(A0[0], sXH, row0a, 0); LOAD_AH(A0[1], sXH, row0a, 8);
            LOAD_AH(A1[0], sXH, row0b, 0); LOAD_AH(A1[1], sXH, row0b, 8);
            #pragma unroll
            for (int j = 0; j < 8; j++) {
                const int fb = (nh * 8 + j) * 2;
                uint32_t B0[2], B1[2];
                LOAD_BF(B0, sW1, fb); LOAD_BF(B1, sW1, fb + 1);
                float C0[4] = {0.f,0.f,0.f,0.f}, C1[4] = {0.f,0.f,0.f,0.f};
                mma16(C0, A0[0], B0); mma16(C0, A0[1], B1);
                mma16(C1, A1[0], B0); mma16(C1, A1[1], B1);
                H0a[j] = pkh(fmaxf(C0[0], 0.f), fmaxf(C0[1], 0.f));
                H0b[j] = pkh(fmaxf(C0[2], 0.f), fmaxf(C0[3], 0.f));
                H1a[j] = pkh(fmaxf(C1[0], 0.f), fmaxf(C1[1], 0.f));
                H1b[j] = pkh(fmaxf(C1[2], 0.f), fmaxf(C1[3], 0.f));
            }
        }

        // ---- stage 5: FF2 partials; H C-frags feed A-slots natively ----
        {
            float* const sPo = (nh == 0) ? sP0 : sP1;
            #pragma unroll
            for (int nf = 0; nf < 4; nf++) {
                float Ca[4] = {0.f,0.f,0.f,0.f}, Cb[4] = {0.f,0.f,0.f,0.f};
                #pragma unroll
                for (int t = 0; t < 4; t++) {
                    const uint32_t A0[4] = {H0a[2*t], H0b[2*t], H0a[2*t+1], H0b[2*t+1]};
                    const uint32_t A1[4] = {H1a[2*t], H1b[2*t], H1a[2*t+1], H1b[2*t+1]};
                    uint32_t B[2];
                    LOAD_BF(B, sW2, nf * 8 + nh * 4 + t);
                    mma16(Ca, A0, B); mma16(Cb, A1, B);
                }
                *(float2*)&sPo[(row0a + r) * PA + nf * 8 + 2 * c]     = make_float2(Ca[0], Ca[1]);
                *(float2*)&sPo[(row0a + r + 8) * PA + nf * 8 + 2 * c] = make_float2(Ca[2], Ca[3]);
                *(float2*)&sPo[(row0b + r) * PA + nf * 8 + 2 * c]     = make_float2(Cb[0], Cb[1]);
                *(float2*)&sPo[(row0b + r + 8) * PA + nf * 8 + 2 * c] = make_float2(Cb[2], Cb[3]);
            }
        }
        PBAR();

        // ---- stage 6: out = X1 + P0 + P1 -> global (pair's 32 rows) ----
        #pragma unroll
        for (int i = 0; i < 4; i++) {
            const float4 a = *(float4*)&sX[prow * PA + psh + i * 4];
            const float4 b = *(float4*)&sP0[prow * PA + psh + i * 4];
            const float4 d = *(float4*)&sP1[prow * PA + psh + i * 4];
            *(float4*)(og + prow * 32 + psh + i * 4) =
                make_float4(a.x + b.x + d.x, a.y + b.y + d.y,
                            a.z + b.z + d.z, a.w + b.w + d.w);
        }
        PBAR();   // pair done reading sX/sP before next tile's stage 0 write
    }
}

extern "C" void kernel_launch(void* const* d_in, const int* in_sizes, int n_in,
                              void* d_out, int out_size) {
    const float* X  = (const float*)d_in[0];
    const float* Wa = (const float*)d_in[1];
    const float* Wp = (const float*)d_in[2];
    const float* W1 = (const float*)d_in[3];
    const float* W2 = (const float*)d_in[4];
    float* Out = (float*)d_out;

    cudaFuncSetAttribute(tblock_mma,
                         cudaFuncAttributeMaxDynamicSharedMemorySize, SMEM_BYTES);
    tblock_mma<<<NUM_CTAS, THREADS, SMEM_BYTES>>>(X, Wa, Wp, W1, W2, Out);
}

// round 12
// speedup vs baseline: 4.8110x; 1.0501x over previous
#include <cuda_runtime.h>
#include <cuda_fp16.h>
#include <cstdint>

// Fused transformer block via mma.sync fp16 (m16n8k16, fp32 accumulate).
// 2M rows x 32, 256-row tiles, 512 threads (16 warps), persistent grid 148.
// Per-pair named barriers; fragment-major fp16 weights; HFMA2 attention;
// FF2 partials stored fp16 overlaid on dead KH/QH buffers (smem 145KB ->
// 83KB L1D carveout); 6 barriers/tile.

#define THREADS 512
#define NUM_CTAS 148
#define NUM_TILES 8192

// u32 offsets in dynamic smem
#define OFF_WQKV 0          // 24 frags x 64
#define OFF_WP   1536       // 8 x 64
#define OFF_W1   2048       // 32 x 64
#define OFF_W2   4096       // 32 x 64
#define OFF_X    6144       // fp32 256 x 36
#define OFF_XH   15360      // fp16 256 x 20 (X then X1)
#define OFF_KH   20480      // fp16 256 x 20 (reused: FF2 partial 0, fp16)
#define OFF_QH   25600      // fp16 256 x 20 (attn out; reused: FF2 partial 1)
#define OFF_VH   30720      // fp16 256 x 20
#define SMEM_U32 35840
#define SMEM_BYTES (SMEM_U32 * 4)

#define PH 20
#define PA 36

__device__ __forceinline__ uint32_t pkh(float lo, float hi) {
    uint32_t r;
    asm("cvt.rn.f16x2.f32 %0, %1, %2;" : "=r"(r) : "f"(hi), "f"(lo));
    return r;
}
__device__ __forceinline__ __half2 u2h(uint32_t u) {
    return *reinterpret_cast<__half2*>(&u);
}
__device__ __forceinline__ uint32_t h2u(__half2 h) {
    return *reinterpret_cast<uint32_t*>(&h);
}
__device__ __forceinline__ void mma16(float c[4], const uint32_t a[4], const uint32_t b[2]) {
    asm volatile(
        "mma.sync.aligned.m16n8k16.row.col.f32.f16.f16.f32 "
        "{%0,%1,%2,%3},{%4,%5,%6,%7},{%8,%9},{%0,%1,%2,%3};"
        : "+f"(c[0]), "+f"(c[1]), "+f"(c[2]), "+f"(c[3])
        : "r"(a[0]), "r"(a[1]), "r"(a[2]), "r"(a[3]), "r"(b[0]), "r"(b[1]));
}

// pair barrier: warps {m, m+8} (64 threads), named barrier id m+1
#define PBAR() asm volatile("bar.sync %0, 64;" :: "r"(m + 1) : "memory")

// A fragment (16 rows x k16) from packed fp16 buffer (pitch PH u32), kp0 = k0/2
#define LOAD_AH(A, buf, row0, kp0) do {                                        \
    (A)[0] = (buf)[((row0) + r) * PH + (kp0) + c];                             \
    (A)[1] = (buf)[((row0) + r + 8) * PH + (kp0) + c];                         \
    (A)[2] = (buf)[((row0) + r) * PH + (kp0) + 4 + c];                         \
    (A)[3] = (buf)[((row0) + r + 8) * PH + (kp0) + 4 + c];                     \
} while (0)

// B fragment from fragment-major buffer: one LDS.64, conflict-free.
#define LOAD_BF(B, buf, fi) do {                                               \
    const uint2 v_ = *(const uint2*)&(buf)[((fi) << 6) + (lane << 1)];         \
    (B)[0] = v_.x; (B)[1] = v_.y;                                              \
} while (0)

__device__ __forceinline__ float wa_val(const float* __restrict__ Wa,
                                        int k, int n, float scale) {
    int g = n >> 5, hh = (n & 31) >> 3, d = n & 7;
    float v = Wa[hh * 768 + k * 24 + g * 8 + d];
    return (g == 1) ? v * scale : v;
}

__global__ void __launch_bounds__(THREADS, 1)
tblock_mma(const float* __restrict__ X, const float* __restrict__ Wa,
           const float* __restrict__ Wp, const float* __restrict__ W1,
           const float* __restrict__ W2, float* __restrict__ Out)
{
    extern __shared__ uint32_t smu[];
    uint32_t* const sWQ = smu + OFF_WQKV;
    uint32_t* const sWP = smu + OFF_WP;
    uint32_t* const sW1 = smu + OFF_W1;
    uint32_t* const sW2 = smu + OFF_W2;
    float*    const sX  = (float*)(smu + OFF_X);
    uint32_t* const sXH = smu + OFF_XH;
    uint32_t* const sKH = smu + OFF_KH;
    uint32_t* const sQH = smu + OFF_QH;
    uint32_t* const sVH = smu + OFF_VH;

    const int tid  = threadIdx.x;
    const int warp = tid >> 5;
    const int lane = tid & 31;
    const int r = lane >> 2;
    const int c = lane & 3;
    const float scale = 0.17677669529663687f;   // 32^{-1/2}, folded into Wq

    // -------- pack weights fragment-major, fp16 --------
    for (int idx = tid; idx < 768; idx += THREADS) {       // Wqkv: 12 nb x 2 t
        int f = idx >> 5, l = idx & 31;
        int nb = f >> 1, t = f & 1;
        int rr = l >> 2, cl = l & 3;
        int n = nb * 8 + rr, k0 = t * 16;
        sWQ[f * 64 + l * 2 + 0] = pkh(wa_val(Wa, k0 + 2 * cl,     n, scale),
                                      wa_val(Wa, k0 + 2 * cl + 1, n, scale));
        sWQ[f * 64 + l * 2 + 1] = pkh(wa_val(Wa, k0 + 2 * cl + 8, n, scale),
                                      wa_val(Wa, k0 + 2 * cl + 9, n, scale));
    }
    for (int idx = tid; idx < 256; idx += THREADS) {       // Wp: 4 nb x 2 t
        int f = idx >> 5, l = idx & 31;
        int nb = f >> 1, t = f & 1;
        int rr = l >> 2, cl = l & 3;
        int n = nb * 8 + rr, k0 = t * 16;
        sWP[f * 64 + l * 2 + 0] = pkh(Wp[(k0 + 2 * cl) * 32 + n], Wp[(k0 + 2 * cl + 1) * 32 + n]);
        sWP[f * 64 + l * 2 + 1] = pkh(Wp[(k0 + 2 * cl + 8) * 32 + n], Wp[(k0 + 2 * cl + 9) * 32 + n]);
    }
    for (int idx = tid; idx < 1024; idx += THREADS) {      // W1: 16 nb x 2 t
        int f = idx >> 5, l = idx & 31;
        int nb = f >> 1, t = f & 1;
        int rr = l >> 2, cl = l & 3;
        int n = nb * 8 + rr, k0 = t * 16;
        sW1[f * 64 + l * 2 + 0] = pkh(W1[(k0 + 2 * cl) * 128 + n], W1[(k0 + 2 * cl + 1) * 128 + n]);
        sW1[f * 64 + l * 2 + 1] = pkh(W1[(k0 + 2 * cl + 8) * 128 + n], W1[(k0 + 2 * cl + 9) * 128 + n]);
    }
    for (int idx = tid; idx < 1024; idx += THREADS) {      // W2: 4 nb x 8 ks
        int f = idx >> 5, l = idx & 31;
        int nb = f >> 3, ks = f & 7;
        int rr = l >> 2, cl = l & 3;
        int n = nb * 8 + rr, k0 = ks * 16;
        sW2[f * 64 + l * 2 + 0] = pkh(W2[(k0 + 2 * cl) * 32 + n], W2[(k0 + 2 * cl + 1) * 32 + n]);
        sW2[f * 64 + l * 2 + 1] = pkh(W2[(k0 + 2 * cl + 8) * 32 + n], W2[(k0 + 2 * cl + 9) * 32 + n]);
    }
    __syncthreads();

    const int m  = warp & 7;            // 8 M-blocks of 32 rows (pair index)
    const int nh = warp >> 3;           // 2 N-halves within the pair
    const int row0a = m * 32;
    const int row0b = m * 32 + 16;
    const int prow = m * 32 + nh * 16 + (lane >> 1);
    const int psh  = (lane & 1) * 16;

    for (int tile = blockIdx.x; tile < NUM_TILES; tile += NUM_CTAS) {
        const float* xg = X + (long long)tile * 8192;
        float* og = Out + (long long)tile * 8192;

        // ---- stage 0: load pair's 32 rows -> sX (fp32) + sXH (fp16) ----
        {
            float4 xv[4];
            #pragma unroll
            for (int i = 0; i < 4; i++)
                xv[i] = *(const float4*)(xg + prow * 32 + psh + i * 4);
            #pragma unroll
            for (int i = 0; i < 4; i++)
                *(float4*)&sX[prow * PA + psh + i * 4] = xv[i];
            uint32_t hx[8];
            #pragma unroll
            for (int i = 0; i < 4; i++) {
                hx[2 * i]     = pkh(xv[i].x, xv[i].y);
                hx[2 * i + 1] = pkh(xv[i].z, xv[i].w);
            }
            *(uint4*)&sXH[prow * PH + (psh >> 1)]     = make_uint4(hx[0], hx[1], hx[2], hx[3]);
            *(uint4*)&sXH[prow * PH + (psh >> 1) + 4] = make_uint4(hx[4], hx[5], hx[6], hx[7]);
            const long long ntile = (long long)tile + NUM_CTAS;
            if (ntile < NUM_TILES && (lane & 1) == 0) {
                const float* np = X + ntile * 8192 + prow * 32;
                asm volatile("prefetch.global.L2 [%0];" :: "l"(np));
            }
        }
        PBAR();

        // ---- stage 1: QKV = X @ Wqkv -> sKH/sQH/sVH (fp16) ----
        {
            uint32_t A0[2][4], A1[2][4];
            LOAD_AH(A0[0], sXH, row0a, 0); LOAD_AH(A0[1], sXH, row0a, 8);
            LOAD_AH(A1[0], sXH, row0b, 0); LOAD_AH(A1[1], sXH, row0b, 8);
            #pragma unroll
            for (int j = 0; j < 6; j++) {
                const int n0 = nh * 48 + j * 8;
                const int fb = (nh * 6 + j) * 2;
                uint32_t B0[2], B1[2];
                LOAD_BF(B0, sWQ, fb); LOAD_BF(B1, sWQ, fb + 1);
                float C0[4] = {0.f,0.f,0.f,0.f}, C1[4] = {0.f,0.f,0.f,0.f};
                mma16(C0, A0[0], B0); mma16(C0, A0[1], B1);
                mma16(C1, A1[0], B0); mma16(C1, A1[1], B1);
                uint32_t* cb; int np;
                if (n0 < 32)      { cb = sKH; np = n0 >> 1; }
                else if (n0 < 64) { cb = sQH; np = (n0 - 32) >> 1; }
                else              { cb = sVH; np = (n0 - 64) >> 1; }
                cb[(row0a + r) * PH + np + c]     = pkh(C0[0], C0[1]);
                cb[(row0a + r + 8) * PH + np + c] = pkh(C0[2], C0[3]);
                cb[(row0b + r) * PH + np + c]     = pkh(C1[0], C1[1]);
                cb[(row0b + r + 8) * PH + np + c] = pkh(C1[2], C1[3]);
            }
        }
        PBAR();

        // ---- stage 2: attention, half2-native (softmax fp32) ----
        {
            const int h = lane >> 3, qt = lane & 7;
            #pragma unroll 1
            for (int p = 0; p < 2; p++) {
                const int rb = m * 32 + (nh * 2 + p) * 8;
                const uint4 qu = *(const uint4*)&sQH[(rb + qt) * PH + 4 * h];
                const __half2 q0 = u2h(qu.x), q1 = u2h(qu.y),
                              q2 = u2h(qu.z), q3 = u2h(qu.w);
                float e[8], mx = -1e30f;
                #pragma unroll
                for (int kt = 0; kt < 8; kt++) {
                    const uint4 ku = *(const uint4*)&sKH[(rb + kt) * PH + 4 * h];
                    __half2 acc = __hmul2(q0, u2h(ku.x));
                    acc = __hfma2(q1, u2h(ku.y), acc);
                    acc = __hfma2(q2, u2h(ku.z), acc);
                    acc = __hfma2(q3, u2h(ku.w), acc);
                    const float s = __low2float(acc) + __high2float(acc);
                    e[kt] = (kt <= qt) ? s : -1e30f;
                    mx = fmaxf(mx, e[kt]);
                }
                float sum = 0.f;
                #pragma unroll
                for (int kt = 0; kt < 8; kt++) { e[kt] = __expf(e[kt] - mx); sum += e[kt]; }
                const float inv = __fdividef(1.0f, sum);
                __half2 o0 = __float2half2_rn(0.f), o1 = o0, o2 = o0, o3 = o0;
                #pragma unroll
                for (int kt = 0; kt < 8; kt++) {
                    const __half2 wh = __float2half2_rn(e[kt] * inv);
                    const uint4 vu = *(const uint4*)&sVH[(rb + kt) * PH + 4 * h];
                    o0 = __hfma2(wh, u2h(vu.x), o0);
                    o1 = __hfma2(wh, u2h(vu.y), o1);
                    o2 = __hfma2(wh, u2h(vu.z), o2);
                    o3 = __hfma2(wh, u2h(vu.w), o3);
                }
                __syncwarp();
                *(uint4*)&sQH[(rb + qt) * PH + 4 * h] =
                    make_uint4(h2u(o0), h2u(o1), h2u(o2), h2u(o3));
                __syncwarp();
            }
        }
        PBAR();

        // ---- stage 3: X1 = attn @ Wp + X -> sX (fp32) + sXH (fp16) ----
        {
            uint32_t A0[2][4], A1[2][4];
            LOAD_AH(A0[0], sQH, row0a, 0); LOAD_AH(A0[1], sQH, row0a, 8);
            LOAD_AH(A1[0], sQH, row0b, 0); LOAD_AH(A1[1], sQH, row0b, 8);
            #pragma unroll
            for (int j = 0; j < 2; j++) {
                const int n0 = nh * 16 + j * 8;
                const int fb = (nh * 2 + j) * 2;
                uint32_t B0[2], B1[2];
                LOAD_BF(B0, sWP, fb); LOAD_BF(B1, sWP, fb + 1);
                float C0[4] = {0.f,0.f,0.f,0.f}, C1[4] = {0.f,0.f,0.f,0.f};
                mma16(C0, A0[0], B0); mma16(C0, A0[1], B1);
                mma16(C1, A1[0], B0); mma16(C1, A1[1], B1);
                float2* p00 = (float2*)&sX[(row0a + r) * PA + n0 + 2 * c];
                float2* p01 = (float2*)&sX[(row0a + r + 8) * PA + n0 + 2 * c];
                float2* p10 = (float2*)&sX[(row0b + r) * PA + n0 + 2 * c];
                float2* p11 = (float2*)&sX[(row0b + r + 8) * PA + n0 + 2 * c];
                float2 v; float s0, s1;
                v = *p00; s0 = C0[0] + v.x; s1 = C0[1] + v.y; *p00 = make_float2(s0, s1);
                sXH[(row0a + r) * PH + (n0 >> 1) + c] = pkh(s0, s1);
                v = *p01; s0 = C0[2] + v.x; s1 = C0[3] + v.y; *p01 = make_float2(s0, s1);
                sXH[(row0a + r + 8) * PH + (n0 >> 1) + c] = pkh(s0, s1);
                v = *p10; s0 = C1[0] + v.x; s1 = C1[1] + v.y; *p10 = make_float2(s0, s1);
                sXH[(row0b + r) * PH + (n0 >> 1) + c] = pkh(s0, s1);
                v = *p11; s0 = C1[2] + v.x; s1 = C1[3] + v.y; *p11 = make_float2(s0, s1);
                sXH[(row0b + r + 8) * PH + (n0 >> 1) + c] = pkh(s0, s1);
            }
        }
        PBAR();

        // ---- stage 4: H = relu(X1 @ W1), kept in fp16x2 registers ----
        uint32_t H0a[8], H0b[8], H1a[8], H1b[8];
        {
            uint32_t A0[2][4], A1[2][4];
            LOAD_AH(A0[0], sXH, row0a, 0); LOAD_AH(A0[1], sXH, row0a, 8);
            LOAD_AH(A1[0], sXH, row0b, 0); LOAD_AH(A1[1], sXH, row0b, 8);
            #pragma unroll
            for (int j = 0; j < 8; j++) {
                const int fb = (nh * 8 + j) * 2;
                uint32_t B0[2], B1[2];
                LOAD_BF(B0, sW1, fb); LOAD_BF(B1, sW1, fb + 1);
                float C0[4] = {0.f,0.f,0.f,0.f}, C1[4] = {0.f,0.f,0.f,0.f};
                mma16(C0, A0[0], B0); mma16(C0, A0[1], B1);
                mma16(C1, A1[0], B0); mma16(C1, A1[1], B1);
                H0a[j] = pkh(fmaxf(C0[0], 0.f), fmaxf(C0[1], 0.f));
                H0b[j] = pkh(fmaxf(C0[2], 0.f), fmaxf(C0[3], 0.f));
                H1a[j] = pkh(fmaxf(C1[0], 0.f), fmaxf(C1[1], 0.f));
                H1b[j] = pkh(fmaxf(C1[2], 0.f), fmaxf(C1[3], 0.f));
            }
        }

        // ---- stage 5: FF2 partials -> fp16, overlaid on KH (nh=0) / QH (nh=1) ----
        {
            uint32_t* const sPo = (nh == 0) ? sKH : sQH;
            #pragma unroll
            for (int nf = 0; nf < 4; nf++) {
                float Ca[4] = {0.f,0.f,0.f,0.f}, Cb[4] = {0.f,0.f,0.f,0.f};
                #pragma unroll
                for (int t = 0; t < 4; t++) {
                    const uint32_t A0[4] = {H0a[2*t], H0b[2*t], H0a[2*t+1], H0b[2*t+1]};
                    const uint32_t A1[4] = {H1a[2*t], H1b[2*t], H1a[2*t+1], H1b[2*t+1]};
                    uint32_t B[2];
                    LOAD_BF(B, sW2, nf * 8 + nh * 4 + t);
                    mma16(Ca, A0, B); mma16(Cb, A1, B);
                }
                sPo[(row0a + r) * PH + nf * 4 + c]     = pkh(Ca[0], Ca[1]);
                sPo[(row0a + r + 8) * PH + nf * 4 + c] = pkh(Ca[2], Ca[3]);
                sPo[(row0b + r) * PH + nf * 4 + c]     = pkh(Cb[0], Cb[1]);
                sPo[(row0b + r + 8) * PH + nf * 4 + c] = pkh(Cb[2], Cb[3]);
            }
        }
        PBAR();

        // ---- stage 6: out = X1 + P0 + P1 -> global (pair's 32 rows) ----
        #pragma unroll
        for (int i = 0; i < 2; i++) {
            const uint4 u0 = *(const uint4*)&sKH[prow * PH + (psh >> 1) + i * 4];
            const uint4 u1 = *(const uint4*)&sQH[prow * PH + (psh >> 1) + i * 4];
            const __half2 s0 = __hadd2(u2h(u0.x), u2h(u1.x));
            const __half2 s1 = __hadd2(u2h(u0.y), u2h(u1.y));
            const __half2 s2 = __hadd2(u2h(u0.z), u2h(u1.z));
            const __half2 s3 = __hadd2(u2h(u0.w), u2h(u1.w));
            const float2 f0 = __half22float2(s0), f1 = __half22float2(s1);
            const float2 f2 = __half22float2(s2), f3 = __half22float2(s3);
            const float4 a0 = *(float4*)&sX[prow * PA + psh + i * 8];
            const float4 a1 = *(float4*)&sX[prow * PA + psh + i * 8 + 4];
            *(float4*)(og + prow * 32 + psh + i * 8) =
                make_float4(a0.x + f0.x, a0.y + f0.y, a0.z + f1.x, a0.w + f1.y);
            *(float4*)(og + prow * 32 + psh + i * 8 + 4) =
                make_float4(a1.x + f2.x, a1.y + f2.y, a1.z + f3.x, a1.w + f3.y);
        }
        // no trailing PBAR: next tile's stage-0 writes touch only thread-owned
        // rows of sX/sXH, and the stage-0-end PBAR orders partner's stage-6
        // partial reads against stage-1's KH/QH overwrites.
    }
}

extern "C" void kernel_launch(void* const* d_in, const int* in_sizes, int n_in,
                              void* d_out, int out_size) {
    const float* X  = (const float*)d_in[0];
    const float* Wa = (const float*)d_in[1];
    const float* Wp = (const float*)d_in[2];
    const float* W1 = (const float*)d_in[3];
    const float* W2 = (const float*)d_in[4];
    float* Out = (float*)d_out;

    cudaFuncSetAttribute(tblock_mma,
                         cudaFuncAttributeMaxDynamicSharedMemorySize, SMEM_BYTES);
    tblock_mma<<<NUM_CTAS, THREADS, SMEM_BYTES>>>(X, Wa, Wp, W1, W2, Out);
}

// round 13
// speedup vs baseline: 5.1743x; 1.0755x over previous
#include <cuda_runtime.h>
#include <cuda_fp16.h>
#include <cstdint>

// Fused transformer block via mma.sync fp16 (m16n8k16, fp32 accumulate).
// 2M rows x 32, 256-row tiles, 512 threads (16 warps), persistent grid 148.
// proj->FF1->FF2 fully register-chained via C->A fragment identity; residual
// carried in fragments (no fp32 buffer); 5 pair barriers/tile; smem 104KB.

#define THREADS 512
#define NUM_CTAS 148
#define NUM_TILES 8192

// u32 offsets in dynamic smem
#define OFF_WQKV 0          // 24 frags x 64
#define OFF_WP   1536       // 8 x 64
#define OFF_W1   2048       // 32 x 64
#define OFF_W2   4096       // 32 x 64
#define OFF_XH   6144       // fp16 256 x 20
#define OFF_KH   11264      // fp16 256 x 20 (reused: FF2 partial 0)
#define OFF_QH   16384      // fp16 256 x 20 (attn out; reused: FF2 partial 1)
#define OFF_VH   21504      // fp16 256 x 20
#define SMEM_U32 26624
#define SMEM_BYTES (SMEM_U32 * 4)

#define PH 20

__device__ __forceinline__ uint32_t pkh(float lo, float hi) {
    uint32_t r;
    asm("cvt.rn.f16x2.f32 %0, %1, %2;" : "=r"(r) : "f"(hi), "f"(lo));
    return r;
}
__device__ __forceinline__ __half2 u2h(uint32_t u) {
    return *reinterpret_cast<__half2*>(&u);
}
__device__ __forceinline__ uint32_t h2u(__half2 h) {
    return *reinterpret_cast<uint32_t*>(&h);
}
__device__ __forceinline__ void mma16(float c[4], const uint32_t a[4], const uint32_t b[2]) {
    asm volatile(
        "mma.sync.aligned.m16n8k16.row.col.f32.f16.f16.f32 "
        "{%0,%1,%2,%3},{%4,%5,%6,%7},{%8,%9},{%0,%1,%2,%3};"
        : "+f"(c[0]), "+f"(c[1]), "+f"(c[2]), "+f"(c[3])
        : "r"(a[0]), "r"(a[1]), "r"(a[2]), "r"(a[3]), "r"(b[0]), "r"(b[1]));
}

// pair barrier: warps {m, m+8} (64 threads), named barrier id m+1
#define PBAR() asm volatile("bar.sync %0, 64;" :: "r"(m + 1) : "memory")

// A fragment (16 rows x k16) from packed fp16 buffer (pitch PH u32), kp0 = k0/2
#define LOAD_AH(A, buf, row0, kp0) do {                                        \
    (A)[0] = (buf)[((row0) + r) * PH + (kp0) + c];                             \
    (A)[1] = (buf)[((row0) + r + 8) * PH + (kp0) + c];                         \
    (A)[2] = (buf)[((row0) + r) * PH + (kp0) + 4 + c];                         \
    (A)[3] = (buf)[((row0) + r + 8) * PH + (kp0) + 4 + c];                     \
} while (0)

// B fragment from fragment-major buffer: one LDS.64, conflict-free.
#define LOAD_BF(B, buf, fi) do {                                               \
    const uint2 v_ = *(const uint2*)&(buf)[((fi) << 6) + (lane << 1)];         \
    (B)[0] = v_.x; (B)[1] = v_.y;                                              \
} while (0)

__device__ __forceinline__ float wa_val(const float* __restrict__ Wa,
                                        int k, int n, float scale) {
    int g = n >> 5, hh = (n & 31) >> 3, d = n & 7;
    float v = Wa[hh * 768 + k * 24 + g * 8 + d];
    return (g == 1) ? v * scale : v;
}

__global__ void __launch_bounds__(THREADS, 1)
tblock_mma(const float* __restrict__ X, const float* __restrict__ Wa,
           const float* __restrict__ Wp, const float* __restrict__ W1,
           const float* __restrict__ W2, float* __restrict__ Out)
{
    extern __shared__ uint32_t smu[];
    uint32_t* const sWQ = smu + OFF_WQKV;
    uint32_t* const sWP = smu + OFF_WP;
    uint32_t* const sW1 = smu + OFF_W1;
    uint32_t* const sW2 = smu + OFF_W2;
    uint32_t* const sXH = smu + OFF_XH;
    uint32_t* const sKH = smu + OFF_KH;
    uint32_t* const sQH = smu + OFF_QH;
    uint32_t* const sVH = smu + OFF_VH;

    const int tid  = threadIdx.x;
    const int warp = tid >> 5;
    const int lane = tid & 31;
    const int r = lane >> 2;
    const int c = lane & 3;
    const float scale = 0.17677669529663687f;   // 32^{-1/2}, folded into Wq

    // -------- pack weights fragment-major, fp16 --------
    for (int idx = tid; idx < 768; idx += THREADS) {       // Wqkv: 12 nb x 2 t
        int f = idx >> 5, l = idx & 31;
        int nb = f >> 1, t = f & 1;
        int rr = l >> 2, cl = l & 3;
        int n = nb * 8 + rr, k0 = t * 16;
        sWQ[f * 64 + l * 2 + 0] = pkh(wa_val(Wa, k0 + 2 * cl,     n, scale),
                                      wa_val(Wa, k0 + 2 * cl + 1, n, scale));
        sWQ[f * 64 + l * 2 + 1] = pkh(wa_val(Wa, k0 + 2 * cl + 8, n, scale),
                                      wa_val(Wa, k0 + 2 * cl + 9, n, scale));
    }
    for (int idx = tid; idx < 256; idx += THREADS) {       // Wp: 4 nb x 2 t
        int f = idx >> 5, l = idx & 31;
        int nb = f >> 1, t = f & 1;
        int rr = l >> 2, cl = l & 3;
        int n = nb * 8 + rr, k0 = t * 16;
        sWP[f * 64 + l * 2 + 0] = pkh(Wp[(k0 + 2 * cl) * 32 + n], Wp[(k0 + 2 * cl + 1) * 32 + n]);
        sWP[f * 64 + l * 2 + 1] = pkh(Wp[(k0 + 2 * cl + 8) * 32 + n], Wp[(k0 + 2 * cl + 9) * 32 + n]);
    }
    for (int idx = tid; idx < 1024; idx += THREADS) {      // W1: 16 nb x 2 t
        int f = idx >> 5, l = idx & 31;
        int nb = f >> 1, t = f & 1;
        int rr = l >> 2, cl = l & 3;
        int n = nb * 8 + rr, k0 = t * 16;
        sW1[f * 64 + l * 2 + 0] = pkh(W1[(k0 + 2 * cl) * 128 + n], W1[(k0 + 2 * cl + 1) * 128 + n]);
        sW1[f * 64 + l * 2 + 1] = pkh(W1[(k0 + 2 * cl + 8) * 128 + n], W1[(k0 + 2 * cl + 9) * 128 + n]);
    }
    for (int idx = tid; idx < 1024; idx += THREADS) {      // W2: 4 nb x 8 ks
        int f = idx >> 5, l = idx & 31;
        int nb = f >> 3, ks = f & 7;
        int rr = l >> 2, cl = l & 3;
        int n = nb * 8 + rr, k0 = ks * 16;
        sW2[f * 64 + l * 2 + 0] = pkh(W2[(k0 + 2 * cl) * 32 + n], W2[(k0 + 2 * cl + 1) * 32 + n]);
        sW2[f * 64 + l * 2 + 1] = pkh(W2[(k0 + 2 * cl + 8) * 32 + n], W2[(k0 + 2 * cl + 9) * 32 + n]);
    }
    __syncthreads();

    const int m  = warp & 7;            // 8 M-blocks of 32 rows (pair index)
    const int nh = warp >> 3;           // 2 N-halves within the pair
    const int row0a = m * 32;
    const int row0b = m * 32 + 16;
    const int prow = m * 32 + nh * 16 + (lane >> 1);
    const int psh  = (lane & 1) * 16;

    for (int tile = blockIdx.x; tile < NUM_TILES; tile += NUM_CTAS) {
        const float* xg = X + (long long)tile * 8192;
        float* og = Out + (long long)tile * 8192;

        // ---- stage 0: load pair's 32 rows -> sXH (fp16 only) ----
        {
            float4 xv[4];
            #pragma unroll
            for (int i = 0; i < 4; i++)
                xv[i] = *(const float4*)(xg + prow * 32 + psh + i * 4);
            uint32_t hx[8];
            #pragma unroll
            for (int i = 0; i < 4; i++) {
                hx[2 * i]     = pkh(xv[i].x, xv[i].y);
                hx[2 * i + 1] = pkh(xv[i].z, xv[i].w);
            }
            *(uint4*)&sXH[prow * PH + (psh >> 1)]     = make_uint4(hx[0], hx[1], hx[2], hx[3]);
            *(uint4*)&sXH[prow * PH + (psh >> 1) + 4] = make_uint4(hx[4], hx[5], hx[6], hx[7]);
            const long long ntile = (long long)tile + NUM_CTAS;
            if (ntile < NUM_TILES && (lane & 1) == 0) {
                const float* np = X + ntile * 8192 + prow * 32;
                asm volatile("prefetch.global.L2 [%0];" :: "l"(np));
            }
        }
        PBAR();

        // ---- stage 1: QKV = X @ Wqkv -> sKH/sQH/sVH; X A-frags held in regs ----
        uint32_t XA0[2][4], XA1[2][4];
        LOAD_AH(XA0[0], sXH, row0a, 0); LOAD_AH(XA0[1], sXH, row0a, 8);
        LOAD_AH(XA1[0], sXH, row0b, 0); LOAD_AH(XA1[1], sXH, row0b, 8);
        {
            #pragma unroll
            for (int j = 0; j < 6; j++) {
                const int n0 = nh * 48 + j * 8;
                const int fb = (nh * 6 + j) * 2;
                uint32_t B0[2], B1[2];
                LOAD_BF(B0, sWQ, fb); LOAD_BF(B1, sWQ, fb + 1);
                float C0[4] = {0.f,0.f,0.f,0.f}, C1[4] = {0.f,0.f,0.f,0.f};
                mma16(C0, XA0[0], B0); mma16(C0, XA0[1], B1);
                mma16(C1, XA1[0], B0); mma16(C1, XA1[1], B1);
                uint32_t* cb; int np;
                if (n0 < 32)      { cb = sKH; np = n0 >> 1; }
                else if (n0 < 64) { cb = sQH; np = (n0 - 32) >> 1; }
                else              { cb = sVH; np = (n0 - 64) >> 1; }
                cb[(row0a + r) * PH + np + c]     = pkh(C0[0], C0[1]);
                cb[(row0a + r + 8) * PH + np + c] = pkh(C0[2], C0[3]);
                cb[(row0b + r) * PH + np + c]     = pkh(C1[0], C1[1]);
                cb[(row0b + r + 8) * PH + np + c] = pkh(C1[2], C1[3]);
            }
        }
        PBAR();

        // ---- stage 2: attention, half2-native (softmax fp32) ----
        {
            const int h = lane >> 3, qt = lane & 7;
            #pragma unroll 1
            for (int p = 0; p < 2; p++) {
                const int rb = m * 32 + (nh * 2 + p) * 8;
                const uint4 qu = *(const uint4*)&sQH[(rb + qt) * PH + 4 * h];
                const __half2 q0 = u2h(qu.x), q1 = u2h(qu.y),
                              q2 = u2h(qu.z), q3 = u2h(qu.w);
                float e[8], mx = -1e30f;
                #pragma unroll
                for (int kt = 0; kt < 8; kt++) {
                    const uint4 ku = *(const uint4*)&sKH[(rb + kt) * PH + 4 * h];
                    __half2 acc = __hmul2(q0, u2h(ku.x));
                    acc = __hfma2(q1, u2h(ku.y), acc);
                    acc = __hfma2(q2, u2h(ku.z), acc);
                    acc = __hfma2(q3, u2h(ku.w), acc);
                    const float s = __low2float(acc) + __high2float(acc);
                    e[kt] = (kt <= qt) ? s : -1e30f;
                    mx = fmaxf(mx, e[kt]);
                }
                float sum = 0.f;
                #pragma unroll
                for (int kt = 0; kt < 8; kt++) { e[kt] = __expf(e[kt] - mx); sum += e[kt]; }
                const float inv = __fdividef(1.0f, sum);
                __half2 o0 = __float2half2_rn(0.f), o1 = o0, o2 = o0, o3 = o0;
                #pragma unroll
                for (int kt = 0; kt < 8; kt++) {
                    const __half2 wh = __float2half2_rn(e[kt] * inv);
                    const uint4 vu = *(const uint4*)&sVH[(rb + kt) * PH + 4 * h];
                    o0 = __hfma2(wh, u2h(vu.x), o0);
                    o1 = __hfma2(wh, u2h(vu.y), o1);
                    o2 = __hfma2(wh, u2h(vu.z), o2);
                    o3 = __hfma2(wh, u2h(vu.w), o3);
                }
                __syncwarp();
                *(uint4*)&sQH[(rb + qt) * PH + 4 * h] =
                    make_uint4(h2u(o0), h2u(o1), h2u(o2), h2u(o3));
                __syncwarp();
            }
        }
        PBAR();

        // ---- stage 3: X1 = attn @ Wp + X, full N per warp, kept as A-frags ----
        uint32_t X1a[2][4], X1b[2][4];
        {
            uint32_t AA0[2][4], AA1[2][4];
            LOAD_AH(AA0[0], sQH, row0a, 0); LOAD_AH(AA0[1], sQH, row0a, 8);
            LOAD_AH(AA1[0], sQH, row0b, 0); LOAD_AH(AA1[1], sQH, row0b, 8);
            PBAR();   // after this, partner may overwrite sQH (stage 5 partials)
            #pragma unroll
            for (int j = 0; j < 4; j++) {
                uint32_t B0[2], B1[2];
                LOAD_BF(B0, sWP, j * 2); LOAD_BF(B1, sWP, j * 2 + 1);
                float C0[4] = {0.f,0.f,0.f,0.f}, C1[4] = {0.f,0.f,0.f,0.f};
                mma16(C0, AA0[0], B0); mma16(C0, AA0[1], B1);
                mma16(C1, AA1[0], B0); mma16(C1, AA1[1], B1);
                const int t = j >> 1, s = (j & 1) * 2;
                const float2 x0 = __half22float2(u2h(XA0[t][s]));
                const float2 x1 = __half22float2(u2h(XA0[t][s + 1]));
                const float2 x2 = __half22float2(u2h(XA1[t][s]));
                const float2 x3 = __half22float2(u2h(XA1[t][s + 1]));
                X1a[t][s]     = pkh(C0[0] + x0.x, C0[1] + x0.y);
                X1a[t][s + 1] = pkh(C0[2] + x1.x, C0[3] + x1.y);
                X1b[t][s]     = pkh(C1[0] + x2.x, C1[1] + x2.y);
                X1b[t][s + 1] = pkh(C1[2] + x3.x, C1[3] + x3.y);
            }
        }

        // ---- stage 4: H = relu(X1 @ W1), A straight from X1 regs ----
        uint32_t H0a[8], H0b[8], H1a[8], H1b[8];
        {
            #pragma unroll
            for (int j = 0; j < 8; j++) {
                const int fb = (nh * 8 + j) * 2;
                uint32_t B0[2], B1[2];
                LOAD_BF(B0, sW1, fb); LOAD_BF(B1, sW1, fb + 1);
                float C0[4] = {0.f,0.f,0.f,0.f}, C1[4] = {0.f,0.f,0.f,0.f};
                mma16(C0, X1a[0], B0); mma16(C0, X1a[1], B1);
                mma16(C1, X1b[0], B0); mma16(C1, X1b[1], B1);
                H0a[j] = pkh(fmaxf(C0[0], 0.f), fmaxf(C0[1], 0.f));
                H0b[j] = pkh(fmaxf(C0[2], 0.f), fmaxf(C0[3], 0.f));
                H1a[j] = pkh(fmaxf(C1[0], 0.f), fmaxf(C1[1], 0.f));
                H1b[j] = pkh(fmaxf(C1[2], 0.f), fmaxf(C1[3], 0.f));
            }
        }

        // ---- stage 5: FF2 partials (+X1 residual on nh=0) -> KH/QH fp16 ----
        {
            uint32_t* const sPo = (nh == 0) ? sKH : sQH;
            #pragma unroll
            for (int nf = 0; nf < 4; nf++) {
                float Ca[4] = {0.f,0.f,0.f,0.f}, Cb[4] = {0.f,0.f,0.f,0.f};
                #pragma unroll
                for (int t = 0; t < 4; t++) {
                    const uint32_t A0[4] = {H0a[2*t], H0b[2*t], H0a[2*t+1], H0b[2*t+1]};
                    const uint32_t A1[4] = {H1a[2*t], H1b[2*t], H1a[2*t+1], H1b[2*t+1]};
                    uint32_t B[2];
                    LOAD_BF(B, sW2, nf * 8 + nh * 4 + t);
                    mma16(Ca, A0, B); mma16(Cb, A1, B);
                }
                if (nh == 0) {
                    const int t = nf >> 1, s = (nf & 1) * 2;
                    const float2 x0 = __half22float2(u2h(X1a[t][s]));
                    const float2 x1 = __half22float2(u2h(X1a[t][s + 1]));
                    const float2 x2 = __half22float2(u2h(X1b[t][s]));
                    const float2 x3 = __half22float2(u2h(X1b[t][s + 1]));
                    Ca[0] += x0.x; Ca[1] += x0.y; Ca[2] += x1.x; Ca[3] += x1.y;
                    Cb[0] += x2.x; Cb[1] += x2.y; Cb[2] += x3.x; Cb[3] += x3.y;
                }
                sPo[(row0a + r) * PH + nf * 4 + c]     = pkh(Ca[0], Ca[1]);
                sPo[(row0a + r + 8) * PH + nf * 4 + c] = pkh(Ca[2], Ca[3]);
                sPo[(row0b + r) * PH + nf * 4 + c]     = pkh(Cb[0], Cb[1]);
                sPo[(row0b + r + 8) * PH + nf * 4 + c] = pkh(Cb[2], Cb[3]);
            }
        }
        PBAR();

        // ---- stage 6: out = P0 + P1 -> global (pair's 32 rows) ----
        #pragma unroll
        for (int i = 0; i < 2; i++) {
            const uint4 u0 = *(const uint4*)&sKH[prow * PH + (psh >> 1) + i * 4];
            const uint4 u1 = *(const uint4*)&sQH[prow * PH + (psh >> 1) + i * 4];
            const __half2 s0 = __hadd2(u2h(u0.x), u2h(u1.x));
            const __half2 s1 = __hadd2(u2h(u0.y), u2h(u1.y));
            const __half2 s2 = __hadd2(u2h(u0.z), u2h(u1.z));
            const __half2 s3 = __hadd2(u2h(u0.w), u2h(u1.w));
            const float2 f0 = __half22float2(s0), f1 = __half22float2(s1);
            const float2 f2 = __half22float2(s2), f3 = __half22float2(s3);
            *(float4*)(og + prow * 32 + psh + i * 8) =
                make_float4(f0.x, f0.y, f1.x, f1.y);
            *(float4*)(og + prow * 32 + psh + i * 8 + 4) =
                make_float4(f2.x, f2.y, f3.x, f3.y);
        }
        // next tile's stage-0 writes only thread-owned sXH rows; partner's
        // stage-6 partial reads are ordered by the stage-0-end PBAR before
        // stage-1 overwrites KH/QH.
    }
}

extern "C" void kernel_launch(void* const* d_in, const int* in_sizes, int n_in,
                              void* d_out, int out_size) {
    const float* X  = (const float*)d_in[0];
    const float* Wa = (const float*)d_in[1];
    const float* Wp = (const float*)d_in[2];
    const float* W1 = (const float*)d_in[3];
    const float* W2 = (const float*)d_in[4];
    float* Out = (float*)d_out;

    cudaFuncSetAttribute(tblock_mma,
                         cudaFuncAttributeMaxDynamicSharedMemorySize, SMEM_BYTES);
    tblock_mma<<<NUM_CTAS, THREADS, SMEM_BYTES>>>(X, Wa, Wp, W1, W2, Out);
}

// round 14
// speedup vs baseline: 5.7446x; 1.1102x over previous
#include <cuda_runtime.h>
#include <cuda_fp16.h>
#include <cstdint>

// Fused transformer block via mma.sync fp16 (m16n8k16, fp32 accumulate).
// 2M rows x 32, 256-row tiles, 512 threads (16 warps), persistent grid 148.
// Register-chained proj->FF1->FF2; X loads software-pipelined across tiles
// (LDG hidden behind QKV MMAs); attention p-loop unrolled, no syncwarps;
// 5 pair barriers/tile; smem 104KB.

#define THREADS 512
#define NUM_CTAS 148
#define NUM_TILES 8192

// u32 offsets in dynamic smem
#define OFF_WQKV 0          // 24 frags x 64
#define OFF_WP   1536       // 8 x 64
#define OFF_W1   2048       // 32 x 64
#define OFF_W2   4096       // 32 x 64
#define OFF_XH   6144       // fp16 256 x 20
#define OFF_KH   11264      // fp16 256 x 20 (reused: FF2 partial 0)
#define OFF_QH   16384      // fp16 256 x 20 (attn out; reused: FF2 partial 1)
#define OFF_VH   21504      // fp16 256 x 20
#define SMEM_U32 26624
#define SMEM_BYTES (SMEM_U32 * 4)

#define PH 20

__device__ __forceinline__ uint32_t pkh(float lo, float hi) {
    uint32_t r;
    asm("cvt.rn.f16x2.f32 %0, %1, %2;" : "=r"(r) : "f"(hi), "f"(lo));
    return r;
}
__device__ __forceinline__ __half2 u2h(uint32_t u) {
    return *reinterpret_cast<__half2*>(&u);
}
__device__ __forceinline__ uint32_t h2u(__half2 h) {
    return *reinterpret_cast<uint32_t*>(&h);
}
__device__ __forceinline__ void mma16(float c[4], const uint32_t a[4], const uint32_t b[2]) {
    asm volatile(
        "mma.sync.aligned.m16n8k16.row.col.f32.f16.f16.f32 "
        "{%0,%1,%2,%3},{%4,%5,%6,%7},{%8,%9},{%0,%1,%2,%3};"
        : "+f"(c[0]), "+f"(c[1]), "+f"(c[2]), "+f"(c[3])
        : "r"(a[0]), "r"(a[1]), "r"(a[2]), "r"(a[3]), "r"(b[0]), "r"(b[1]));
}

// pair barrier: warps {m, m+8} (64 threads), named barrier id m+1
#define PBAR() asm volatile("bar.sync %0, 64;" :: "r"(m + 1) : "memory")

// A fragment (16 rows x k16) from packed fp16 buffer (pitch PH u32), kp0 = k0/2
#define LOAD_AH(A, buf, row0, kp0) do {                                        \
    (A)[0] = (buf)[((row0) + r) * PH + (kp0) + c];                             \
    (A)[1] = (buf)[((row0) + r + 8) * PH + (kp0) + c];                         \
    (A)[2] = (buf)[((row0) + r) * PH + (kp0) + 4 + c];                         \
    (A)[3] = (buf)[((row0) + r + 8) * PH + (kp0) + 4 + c];                     \
} while (0)

// B fragment from fragment-major buffer: one LDS.64, conflict-free.
#define LOAD_BF(B, buf, fi) do {                                               \
    const uint2 v_ = *(const uint2*)&(buf)[((fi) << 6) + (lane << 1)];         \
    (B)[0] = v_.x; (B)[1] = v_.y;                                              \
} while (0)

__device__ __forceinline__ float wa_val(const float* __restrict__ Wa,
                                        int k, int n, float scale) {
    int g = n >> 5, hh = (n & 31) >> 3, d = n & 7;
    float v = Wa[hh * 768 + k * 24 + g * 8 + d];
    return (g == 1) ? v * scale : v;
}

__global__ void __launch_bounds__(THREADS, 1)
tblock_mma(const float* __restrict__ X, const float* __restrict__ Wa,
           const float* __restrict__ Wp, const float* __restrict__ W1,
           const float* __restrict__ W2, float* __restrict__ Out)
{
    extern __shared__ uint32_t smu[];
    uint32_t* const sWQ = smu + OFF_WQKV;
    uint32_t* const sWP = smu + OFF_WP;
    uint32_t* const sW1 = smu + OFF_W1;
    uint32_t* const sW2 = smu + OFF_W2;
    uint32_t* const sXH = smu + OFF_XH;
    uint32_t* const sKH = smu + OFF_KH;
    uint32_t* const sQH = smu + OFF_QH;
    uint32_t* const sVH = smu + OFF_VH;

    const int tid  = threadIdx.x;
    const int warp = tid >> 5;
    const int lane = tid & 31;
    const int r = lane >> 2;
    const int c = lane & 3;
    const float scale = 0.17677669529663687f;   // 32^{-1/2}, folded into Wq

    // -------- pack weights fragment-major, fp16 --------
    for (int idx = tid; idx < 768; idx += THREADS) {       // Wqkv: 12 nb x 2 t
        int f = idx >> 5, l = idx & 31;
        int nb = f >> 1, t = f & 1;
        int rr = l >> 2, cl = l & 3;
        int n = nb * 8 + rr, k0 = t * 16;
        sWQ[f * 64 + l * 2 + 0] = pkh(wa_val(Wa, k0 + 2 * cl,     n, scale),
                                      wa_val(Wa, k0 + 2 * cl + 1, n, scale));
        sWQ[f * 64 + l * 2 + 1] = pkh(wa_val(Wa, k0 + 2 * cl + 8, n, scale),
                                      wa_val(Wa, k0 + 2 * cl + 9, n, scale));
    }
    for (int idx = tid; idx < 256; idx += THREADS) {       // Wp: 4 nb x 2 t
        int f = idx >> 5, l = idx & 31;
        int nb = f >> 1, t = f & 1;
        int rr = l >> 2, cl = l & 3;
        int n = nb * 8 + rr, k0 = t * 16;
        sWP[f * 64 + l * 2 + 0] = pkh(Wp[(k0 + 2 * cl) * 32 + n], Wp[(k0 + 2 * cl + 1) * 32 + n]);
        sWP[f * 64 + l * 2 + 1] = pkh(Wp[(k0 + 2 * cl + 8) * 32 + n], Wp[(k0 + 2 * cl + 9) * 32 + n]);
    }
    for (int idx = tid; idx < 1024; idx += THREADS) {      // W1: 16 nb x 2 t
        int f = idx >> 5, l = idx & 31;
        int nb = f >> 1, t = f & 1;
        int rr = l >> 2, cl = l & 3;
        int n = nb * 8 + rr, k0 = t * 16;
        sW1[f * 64 + l * 2 + 0] = pkh(W1[(k0 + 2 * cl) * 128 + n], W1[(k0 + 2 * cl + 1) * 128 + n]);
        sW1[f * 64 + l * 2 + 1] = pkh(W1[(k0 + 2 * cl + 8) * 128 + n], W1[(k0 + 2 * cl + 9) * 128 + n]);
    }
    for (int idx = tid; idx < 1024; idx += THREADS) {      // W2: 4 nb x 8 ks
        int f = idx >> 5, l = idx & 31;
        int nb = f >> 3, ks = f & 7;
        int rr = l >> 2, cl = l & 3;
        int n = nb * 8 + rr, k0 = ks * 16;
        sW2[f * 64 + l * 2 + 0] = pkh(W2[(k0 + 2 * cl) * 32 + n], W2[(k0 + 2 * cl + 1) * 32 + n]);
        sW2[f * 64 + l * 2 + 1] = pkh(W2[(k0 + 2 * cl + 8) * 32 + n], W2[(k0 + 2 * cl + 9) * 32 + n]);
    }
    __syncthreads();

    const int m  = warp & 7;            // 8 M-blocks of 32 rows (pair index)
    const int nh = warp >> 3;           // 2 N-halves within the pair
    const int row0a = m * 32;
    const int row0b = m * 32 + 16;
    const int prow = m * 32 + nh * 16 + (lane >> 1);
    const int psh  = (lane & 1) * 16;

    // -------- prologue: load first tile's X -> sXH --------
    {
        const float* xg0 = X + (long long)blockIdx.x * 8192 + prow * 32 + psh;
        float4 xv[4];
        #pragma unroll
        for (int i = 0; i < 4; i++) xv[i] = *(const float4*)(xg0 + i * 4);
        uint32_t hx[8];
        #pragma unroll
        for (int i = 0; i < 4; i++) {
            hx[2 * i]     = pkh(xv[i].x, xv[i].y);
            hx[2 * i + 1] = pkh(xv[i].z, xv[i].w);
        }
        *(uint4*)&sXH[prow * PH + (psh >> 1)]     = make_uint4(hx[0], hx[1], hx[2], hx[3]);
        *(uint4*)&sXH[prow * PH + (psh >> 1) + 4] = make_uint4(hx[4], hx[5], hx[6], hx[7]);
    }
    PBAR();

    for (int tile = blockIdx.x; tile < NUM_TILES; tile += NUM_CTAS) {
        float* og = Out + (long long)tile * 8192;
        const long long ntile = (long long)tile + NUM_CTAS;
        const bool nv = ntile < NUM_TILES;

        // ---- stage 1: QKV = X @ Wqkv; pipeline next tile's X load ----
        uint32_t XA0[2][4], XA1[2][4];
        LOAD_AH(XA0[0], sXH, row0a, 0); LOAD_AH(XA0[1], sXH, row0a, 8);
        LOAD_AH(XA1[0], sXH, row0b, 0); LOAD_AH(XA1[1], sXH, row0b, 8);

        float4 nxv0, nxv1, nxv2, nxv3;
        if (nv) {
            const float* np = X + ntile * 8192 + prow * 32 + psh;
            nxv0 = *(const float4*)(np);
            nxv1 = *(const float4*)(np + 4);
            nxv2 = *(const float4*)(np + 8);
            nxv3 = *(const float4*)(np + 12);
            const long long ptile = ntile + NUM_CTAS;
            if (ptile < NUM_TILES && (lane & 1) == 0)
                asm volatile("prefetch.global.L2 [%0];"
                             :: "l"(X + ptile * 8192 + prow * 32));
        }

        {
            #pragma unroll
            for (int j = 0; j < 6; j++) {
                const int n0 = nh * 48 + j * 8;
                const int fb = (nh * 6 + j) * 2;
                uint32_t B0[2], B1[2];
                LOAD_BF(B0, sWQ, fb); LOAD_BF(B1, sWQ, fb + 1);
                float C0[4] = {0.f,0.f,0.f,0.f}, C1[4] = {0.f,0.f,0.f,0.f};
                mma16(C0, XA0[0], B0); mma16(C0, XA0[1], B1);
                mma16(C1, XA1[0], B0); mma16(C1, XA1[1], B1);
                uint32_t* cb; int np;
                if (n0 < 32)      { cb = sKH; np = n0 >> 1; }
                else if (n0 < 64) { cb = sQH; np = (n0 - 32) >> 1; }
                else              { cb = sVH; np = (n0 - 64) >> 1; }
                cb[(row0a + r) * PH + np + c]     = pkh(C0[0], C0[1]);
                cb[(row0a + r + 8) * PH + np + c] = pkh(C0[2], C0[3]);
                cb[(row0b + r) * PH + np + c]     = pkh(C1[0], C1[1]);
                cb[(row0b + r + 8) * PH + np + c] = pkh(C1[2], C1[3]);
            }
        }
        uint32_t nx[8];
        if (nv) {
            nx[0] = pkh(nxv0.x, nxv0.y); nx[1] = pkh(nxv0.z, nxv0.w);
            nx[2] = pkh(nxv1.x, nxv1.y); nx[3] = pkh(nxv1.z, nxv1.w);
            nx[4] = pkh(nxv2.x, nxv2.y); nx[5] = pkh(nxv2.z, nxv2.w);
            nx[6] = pkh(nxv3.x, nxv3.y); nx[7] = pkh(nxv3.z, nxv3.w);
        }
        PBAR();   // QKV ready; both pair warps done reading sXH

        // store next tile's X into sXH (own rows)
        if (nv) {
            *(uint4*)&sXH[prow * PH + (psh >> 1)]     = make_uint4(nx[0], nx[1], nx[2], nx[3]);
            *(uint4*)&sXH[prow * PH + (psh >> 1) + 4] = make_uint4(nx[4], nx[5], nx[6], nx[7]);
        }

        // ---- stage 2: attention, half2-native, both items interleaved ----
        {
            const int h = lane >> 3, qt = lane & 7;
            #pragma unroll
            for (int p = 0; p < 2; p++) {
                const int rb = m * 32 + (nh * 2 + p) * 8;
                const uint4 qu = *(const uint4*)&sQH[(rb + qt) * PH + 4 * h];
                const __half2 q0 = u2h(qu.x), q1 = u2h(qu.y),
                              q2 = u2h(qu.z), q3 = u2h(qu.w);
                float e[8], mx = -1e30f;
                #pragma unroll
                for (int kt = 0; kt < 8; kt++) {
                    const uint4 ku = *(const uint4*)&sKH[(rb + kt) * PH + 4 * h];
                    __half2 acc = __hmul2(q0, u2h(ku.x));
                    acc = __hfma2(q1, u2h(ku.y), acc);
                    acc = __hfma2(q2, u2h(ku.z), acc);
                    acc = __hfma2(q3, u2h(ku.w), acc);
                    const float s = __low2float(acc) + __high2float(acc);
                    e[kt] = (kt <= qt) ? s : -1e30f;
                    mx = fmaxf(mx, e[kt]);
                }
                float sum = 0.f;
                #pragma unroll
                for (int kt = 0; kt < 8; kt++) { e[kt] = __expf(e[kt] - mx); sum += e[kt]; }
                const float inv = __fdividef(1.0f, sum);
                __half2 o0 = __float2half2_rn(0.f), o1 = o0, o2 = o0, o3 = o0;
                #pragma unroll
                for (int kt = 0; kt < 8; kt++) {
                    const __half2 wh = __float2half2_rn(e[kt] * inv);
                    const uint4 vu = *(const uint4*)&sVH[(rb + kt) * PH + 4 * h];
                    o0 = __hfma2(wh, u2h(vu.x), o0);
                    o1 = __hfma2(wh, u2h(vu.y), o1);
                    o2 = __hfma2(wh, u2h(vu.z), o2);
                    o3 = __hfma2(wh, u2h(vu.w), o3);
                }
                // each lane writes only its own (row, col) slot: no syncwarp needed
                *(uint4*)&sQH[(rb + qt) * PH + 4 * h] =
                    make_uint4(h2u(o0), h2u(o1), h2u(o2), h2u(o3));
            }
        }
        PBAR();

        // ---- stage 3: X1 = attn @ Wp + X, full N per warp, kept as A-frags ----
        uint32_t X1a[2][4], X1b[2][4];
        {
            uint32_t AA0[2][4], AA1[2][4];
            LOAD_AH(AA0[0], sQH, row0a, 0); LOAD_AH(AA0[1], sQH, row0a, 8);
            LOAD_AH(AA1[0], sQH, row0b, 0); LOAD_AH(AA1[1], sQH, row0b, 8);
            PBAR();   // after this, partner may overwrite sQH (stage 5 partials)
            #pragma unroll
            for (int j = 0; j < 4; j++) {
                uint32_t B0[2], B1[2];
                LOAD_BF(B0, sWP, j * 2); LOAD_BF(B1, sWP, j * 2 + 1);
                float C0[4] = {0.f,0.f,0.f,0.f}, C1[4] = {0.f,0.f,0.f,0.f};
                mma16(C0, AA0[0], B0); mma16(C0, AA0[1], B1);
                mma16(C1, AA1[0], B0); mma16(C1, AA1[1], B1);
                const int t = j >> 1, s = (j & 1) * 2;
                const float2 x0 = __half22float2(u2h(XA0[t][s]));
                const float2 x1 = __half22float2(u2h(XA0[t][s + 1]));
                const float2 x2 = __half22float2(u2h(XA1[t][s]));
                const float2 x3 = __half22float2(u2h(XA1[t][s + 1]));
                X1a[t][s]     = pkh(C0[0] + x0.x, C0[1] + x0.y);
                X1a[t][s + 1] = pkh(C0[2] + x1.x, C0[3] + x1.y);
                X1b[t][s]     = pkh(C1[0] + x2.x, C1[1] + x2.y);
                X1b[t][s + 1] = pkh(C1[2] + x3.x, C1[3] + x3.y);
            }
        }

        // ---- stage 4: H = relu(X1 @ W1), A straight from X1 regs ----
        uint32_t H0a[8], H0b[8], H1a[8], H1b[8];
        {
            #pragma unroll
            for (int j = 0; j < 8; j++) {
                const int fb = (nh * 8 + j) * 2;
                uint32_t B0[2], B1[2];
                LOAD_BF(B0, sW1, fb); LOAD_BF(B1, sW1, fb + 1);
                float C0[4] = {0.f,0.f,0.f,0.f}, C1[4] = {0.f,0.f,0.f,0.f};
                mma16(C0, X1a[0], B0); mma16(C0, X1a[1], B1);
                mma16(C1, X1b[0], B0); mma16(C1, X1b[1], B1);
                H0a[j] = pkh(fmaxf(C0[0], 0.f), fmaxf(C0[1], 0.f));
                H0b[j] = pkh(fmaxf(C0[2], 0.f), fmaxf(C0[3], 0.f));
                H1a[j] = pkh(fmaxf(C1[0], 0.f), fmaxf(C1[1], 0.f));
                H1b[j] = pkh(fmaxf(C1[2], 0.f), fmaxf(C1[3], 0.f));
            }
        }

        // ---- stage 5: FF2 partials (+X1 residual on nh=0) -> KH/QH fp16 ----
        {
            uint32_t* const sPo = (nh == 0) ? sKH : sQH;
            #pragma unroll
            for (int nf = 0; nf < 4; nf++) {
                float Ca[4] = {0.f,0.f,0.f,0.f}, Cb[4] = {0.f,0.f,0.f,0.f};
                #pragma unroll
                for (int t = 0; t < 4; t++) {
                    const uint32_t A0[4] = {H0a[2*t], H0b[2*t], H0a[2*t+1], H0b[2*t+1]};
                    const uint32_t A1[4] = {H1a[2*t], H1b[2*t], H1a[2*t+1], H1b[2*t+1]};
                    uint32_t B[2];
                    LOAD_BF(B, sW2, nf * 8 + nh * 4 + t);
                    mma16(Ca, A0, B); mma16(Cb, A1, B);
                }
                if (nh == 0) {
                    const int t = nf >> 1, s = (nf & 1) * 2;
                    const float2 x0 = __half22float2(u2h(X1a[t][s]));
                    const float2 x1 = __half22float2(u2h(X1a[t][s + 1]));
                    const float2 x2 = __half22float2(u2h(X1b[t][s]));
                    const float2 x3 = __half22float2(u2h(X1b[t][s + 1]));
                    Ca[0] += x0.x; Ca[1] += x0.y; Ca[2] += x1.x; Ca[3] += x1.y;
                    Cb[0] += x2.x; Cb[1] += x2.y; Cb[2] += x3.x; Cb[3] += x3.y;
                }
                sPo[(row0a + r) * PH + nf * 4 + c]     = pkh(Ca[0], Ca[1]);
                sPo[(row0a + r + 8) * PH + nf * 4 + c] = pkh(Ca[2], Ca[3]);
                sPo[(row0b + r) * PH + nf * 4 + c]     = pkh(Cb[0], Cb[1]);
                sPo[(row0b + r + 8) * PH + nf * 4 + c] = pkh(Cb[2], Cb[3]);
            }
        }
        PBAR();

        // ---- stage 6: out = P0 + P1 -> global (pair's 32 rows) ----
        #pragma unroll
        for (int i = 0; i < 2; i++) {
            const uint4 u0 = *(const uint4*)&sKH[prow * PH + (psh >> 1) + i * 4];
            const uint4 u1 = *(const uint4*)&sQH[prow * PH + (psh >> 1) + i * 4];
            const __half2 s0 = __hadd2(u2h(u0.x), u2h(u1.x));
            const __half2 s1 = __hadd2(u2h(u0.y), u2h(u1.y));
            const __half2 s2 = __hadd2(u2h(u0.z), u2h(u1.z));
            const __half2 s3 = __hadd2(u2h(u0.w), u2h(u1.w));
            const float2 f0 = __half22float2(s0), f1 = __half22float2(s1);
            const float2 f2 = __half22float2(s2), f3 = __half22float2(s3);
            *(float4*)(og + prow * 32 + psh + i * 8) =
                make_float4(f0.x, f0.y, f1.x, f1.y);
            *(float4*)(og + prow * 32 + psh + i * 8 + 4) =
                make_float4(f2.x, f2.y, f3.x, f3.y);
        }
        PBAR();   // partner's stage-6 reads done before next stage-1 KH/QH writes
    }
}

extern "C" void kernel_launch(void* const* d_in, const int* in_sizes, int n_in,
                              void* d_out, int out_size) {
    const float* X  = (const float*)d_in[0];
    const float* Wa = (const float*)d_in[1];
    const float* Wp = (const float*)d_in[2];
    const float* W1 = (const float*)d_in[3];
    const float* W2 = (const float*)d_in[4];
    float* Out = (float*)d_out;

    cudaFuncSetAttribute(tblock_mma,
                         cudaFuncAttributeMaxDynamicSharedMemorySize, SMEM_BYTES);
    tblock_mma<<<NUM_CTAS, THREADS, SMEM_BYTES>>>(X, Wa, Wp, W1, W2, Out);
}

// round 15
// speedup vs baseline: 6.6346x; 1.1549x over previous
#include <cuda_runtime.h>
#include <cuda_fp16.h>
#include <cstdint>

// Fused transformer block via mma.sync fp16 (m16n8k16, fp32 accumulate).
// 2M rows x 32, 256-row tiles, 512 threads (16 warps), persistent grid 148.
// Row-ownership design: QKV cooperatively (n-split), then each warp owns its
// 16-row block through attention -> proj -> FF1 -> FF2 (full N, full k, no
// partial exchange, output direct from C-frags). 2 pair barriers per tile.

#define THREADS 512
#define NUM_CTAS 148
#define NUM_TILES 8192

// u32 offsets in dynamic smem
#define OFF_WQKV 0          // 24 frags x 64
#define OFF_WP   1536       // 8 x 64
#define OFF_W1   2048       // 32 x 64
#define OFF_W2   4096       // 32 x 64
#define OFF_XH   6144       // fp16 256 x 20
#define OFF_KH   11264      // fp16 256 x 20
#define OFF_QH   16384      // fp16 256 x 20 (then attn out, own rows)
#define OFF_VH   21504      // fp16 256 x 20
#define SMEM_U32 26624
#define SMEM_BYTES (SMEM_U32 * 4)

#define PH 20

__device__ __forceinline__ uint32_t pkh(float lo, float hi) {
    uint32_t r;
    asm("cvt.rn.f16x2.f32 %0, %1, %2;" : "=r"(r) : "f"(hi), "f"(lo));
    return r;
}
__device__ __forceinline__ __half2 u2h(uint32_t u) {
    return *reinterpret_cast<__half2*>(&u);
}
__device__ __forceinline__ uint32_t h2u(__half2 h) {
    return *reinterpret_cast<uint32_t*>(&h);
}
__device__ __forceinline__ void mma16(float c[4], const uint32_t a[4], const uint32_t b[2]) {
    asm volatile(
        "mma.sync.aligned.m16n8k16.row.col.f32.f16.f16.f32 "
        "{%0,%1,%2,%3},{%4,%5,%6,%7},{%8,%9},{%0,%1,%2,%3};"
        : "+f"(c[0]), "+f"(c[1]), "+f"(c[2]), "+f"(c[3])
        : "r"(a[0]), "r"(a[1]), "r"(a[2]), "r"(a[3]), "r"(b[0]), "r"(b[1]));
}

// pair barrier: warps {m, m+8} (64 threads), named barrier id m+1
#define PBAR() asm volatile("bar.sync %0, 64;" :: "r"(m + 1) : "memory")

// A fragment (16 rows x k16) from packed fp16 buffer (pitch PH u32), kp0 = k0/2
#define LOAD_AH(A, buf, row0, kp0) do {                                        \
    (A)[0] = (buf)[((row0) + r) * PH + (kp0) + c];                             \
    (A)[1] = (buf)[((row0) + r + 8) * PH + (kp0) + c];                         \
    (A)[2] = (buf)[((row0) + r) * PH + (kp0) + 4 + c];                         \
    (A)[3] = (buf)[((row0) + r + 8) * PH + (kp0) + 4 + c];                     \
} while (0)

// B fragment from fragment-major buffer: one LDS.64, conflict-free.
#define LOAD_BF(B, buf, fi) do {                                               \
    const uint2 v_ = *(const uint2*)&(buf)[((fi) << 6) + (lane << 1)];         \
    (B)[0] = v_.x; (B)[1] = v_.y;                                              \
} while (0)

__device__ __forceinline__ float wa_val(const float* __restrict__ Wa,
                                        int k, int n, float scale) {
    int g = n >> 5, hh = (n & 31) >> 3, d = n & 7;
    float v = Wa[hh * 768 + k * 24 + g * 8 + d];
    return (g == 1) ? v * scale : v;
}

__global__ void __launch_bounds__(THREADS, 1)
tblock_mma(const float* __restrict__ X, const float* __restrict__ Wa,
           const float* __restrict__ Wp, const float* __restrict__ W1,
           const float* __restrict__ W2, float* __restrict__ Out)
{
    extern __shared__ uint32_t smu[];
    uint32_t* const sWQ = smu + OFF_WQKV;
    uint32_t* const sWP = smu + OFF_WP;
    uint32_t* const sW1 = smu + OFF_W1;
    uint32_t* const sW2 = smu + OFF_W2;
    uint32_t* const sXH = smu + OFF_XH;
    uint32_t* const sKH = smu + OFF_KH;
    uint32_t* const sQH = smu + OFF_QH;
    uint32_t* const sVH = smu + OFF_VH;

    const int tid  = threadIdx.x;
    const int warp = tid >> 5;
    const int lane = tid & 31;
    const int r = lane >> 2;
    const int c = lane & 3;
    const float scale = 0.17677669529663687f;   // 32^{-1/2}, folded into Wq

    // -------- pack weights fragment-major, fp16 --------
    for (int idx = tid; idx < 768; idx += THREADS) {       // Wqkv: 12 nb x 2 t
        int f = idx >> 5, l = idx & 31;
        int nb = f >> 1, t = f & 1;
        int rr = l >> 2, cl = l & 3;
        int n = nb * 8 + rr, k0 = t * 16;
        sWQ[f * 64 + l * 2 + 0] = pkh(wa_val(Wa, k0 + 2 * cl,     n, scale),
                                      wa_val(Wa, k0 + 2 * cl + 1, n, scale));
        sWQ[f * 64 + l * 2 + 1] = pkh(wa_val(Wa, k0 + 2 * cl + 8, n, scale),
                                      wa_val(Wa, k0 + 2 * cl + 9, n, scale));
    }
    for (int idx = tid; idx < 256; idx += THREADS) {       // Wp: 4 nb x 2 t
        int f = idx >> 5, l = idx & 31;
        int nb = f >> 1, t = f & 1;
        int rr = l >> 2, cl = l & 3;
        int n = nb * 8 + rr, k0 = t * 16;
        sWP[f * 64 + l * 2 + 0] = pkh(Wp[(k0 + 2 * cl) * 32 + n], Wp[(k0 + 2 * cl + 1) * 32 + n]);
        sWP[f * 64 + l * 2 + 1] = pkh(Wp[(k0 + 2 * cl + 8) * 32 + n], Wp[(k0 + 2 * cl + 9) * 32 + n]);
    }
    for (int idx = tid; idx < 1024; idx += THREADS) {      // W1: 16 nb x 2 t
        int f = idx >> 5, l = idx & 31;
        int nb = f >> 1, t = f & 1;
        int rr = l >> 2, cl = l & 3;
        int n = nb * 8 + rr, k0 = t * 16;
        sW1[f * 64 + l * 2 + 0] = pkh(W1[(k0 + 2 * cl) * 128 + n], W1[(k0 + 2 * cl + 1) * 128 + n]);
        sW1[f * 64 + l * 2 + 1] = pkh(W1[(k0 + 2 * cl + 8) * 128 + n], W1[(k0 + 2 * cl + 9) * 128 + n]);
    }
    for (int idx = tid; idx < 1024; idx += THREADS) {      // W2: 4 nb x 8 ks
        int f = idx >> 5, l = idx & 31;
        int nb = f >> 3, ks = f & 7;
        int rr = l >> 2, cl = l & 3;
        int n = nb * 8 + rr, k0 = ks * 16;
        sW2[f * 64 + l * 2 + 0] = pkh(W2[(k0 + 2 * cl) * 32 + n], W2[(k0 + 2 * cl + 1) * 32 + n]);
        sW2[f * 64 + l * 2 + 1] = pkh(W2[(k0 + 2 * cl + 8) * 32 + n], W2[(k0 + 2 * cl + 9) * 32 + n]);
    }
    __syncthreads();

    const int m  = warp & 7;            // 8 M-blocks of 32 rows (pair index)
    const int nh = warp >> 3;           // which 16-row half this warp OWNS
    const int row0a = m * 32;
    const int row0b = m * 32 + 16;
    const int rown  = m * 32 + nh * 16; // own block base
    const int prow = rown + (lane >> 1);
    const int psh  = (lane & 1) * 16;

    // -------- prologue: load first tile's X -> sXH --------
    {
        const float* xg0 = X + (long long)blockIdx.x * 8192 + prow * 32 + psh;
        float4 xv[4];
        #pragma unroll
        for (int i = 0; i < 4; i++) xv[i] = *(const float4*)(xg0 + i * 4);
        uint32_t hx[8];
        #pragma unroll
        for (int i = 0; i < 4; i++) {
            hx[2 * i]     = pkh(xv[i].x, xv[i].y);
            hx[2 * i + 1] = pkh(xv[i].z, xv[i].w);
        }
        *(uint4*)&sXH[prow * PH + (psh >> 1)]     = make_uint4(hx[0], hx[1], hx[2], hx[3]);
        *(uint4*)&sXH[prow * PH + (psh >> 1) + 4] = make_uint4(hx[4], hx[5], hx[6], hx[7]);
    }
    PBAR();

    for (int tile = blockIdx.x; tile < NUM_TILES; tile += NUM_CTAS) {
        float* og = Out + (long long)tile * 8192;
        const long long ntile = (long long)tile + NUM_CTAS;
        const bool nv = ntile < NUM_TILES;

        // ---- stage 1: QKV = X @ Wqkv (n-split, M=32); pipeline next X load ----
        uint32_t XAo[2][4];   // own block's X A-frags (residual)
        {
            uint32_t XA0[2][4], XA1[2][4];
            LOAD_AH(XA0[0], sXH, row0a, 0); LOAD_AH(XA0[1], sXH, row0a, 8);
            LOAD_AH(XA1[0], sXH, row0b, 0); LOAD_AH(XA1[1], sXH, row0b, 8);

            float4 nxv0, nxv1, nxv2, nxv3;
            if (nv) {
                const float* np = X + ntile * 8192 + prow * 32 + psh;
                nxv0 = *(const float4*)(np);
                nxv1 = *(const float4*)(np + 4);
                nxv2 = *(const float4*)(np + 8);
                nxv3 = *(const float4*)(np + 12);
                const long long ptile = ntile + NUM_CTAS;
                if (ptile < NUM_TILES && (lane & 1) == 0)
                    asm volatile("prefetch.global.L2 [%0];"
                                 :: "l"(X + ptile * 8192 + prow * 32));
            }

            #pragma unroll
            for (int j = 0; j < 6; j++) {
                const int n0 = nh * 48 + j * 8;
                const int fb = (nh * 6 + j) * 2;
                uint32_t B0[2], B1[2];
                LOAD_BF(B0, sWQ, fb); LOAD_BF(B1, sWQ, fb + 1);
                float C0[4] = {0.f,0.f,0.f,0.f}, C1[4] = {0.f,0.f,0.f,0.f};
                mma16(C0, XA0[0], B0); mma16(C0, XA0[1], B1);
                mma16(C1, XA1[0], B0); mma16(C1, XA1[1], B1);
                uint32_t* cb; int np;
                if (n0 < 32)      { cb = sKH; np = n0 >> 1; }
                else if (n0 < 64) { cb = sQH; np = (n0 - 32) >> 1; }
                else              { cb = sVH; np = (n0 - 64) >> 1; }
                cb[(row0a + r) * PH + np + c]     = pkh(C0[0], C0[1]);
                cb[(row0a + r + 8) * PH + np + c] = pkh(C0[2], C0[3]);
                cb[(row0b + r) * PH + np + c]     = pkh(C1[0], C1[1]);
                cb[(row0b + r + 8) * PH + np + c] = pkh(C1[2], C1[3]);
            }
            #pragma unroll
            for (int t = 0; t < 2; t++)
                #pragma unroll
                for (int i = 0; i < 4; i++)
                    XAo[t][i] = nh ? XA1[t][i] : XA0[t][i];

            uint32_t nx[8];
            if (nv) {
                nx[0] = pkh(nxv0.x, nxv0.y); nx[1] = pkh(nxv0.z, nxv0.w);
                nx[2] = pkh(nxv1.x, nxv1.y); nx[3] = pkh(nxv1.z, nxv1.w);
                nx[4] = pkh(nxv2.x, nxv2.y); nx[5] = pkh(nxv2.z, nxv2.w);
                nx[6] = pkh(nxv3.x, nxv3.y); nx[7] = pkh(nxv3.z, nxv3.w);
            }
            PBAR();   // QKV visible; both pair warps done reading sXH

            if (nv) {
                *(uint4*)&sXH[prow * PH + (psh >> 1)]     = make_uint4(nx[0], nx[1], nx[2], nx[3]);
                *(uint4*)&sXH[prow * PH + (psh >> 1) + 4] = make_uint4(nx[4], nx[5], nx[6], nx[7]);
            }
        }

        // ---- stage 2: attention on OWN 16 rows (2 batch items) ----
        {
            const int h = lane >> 3, qt = lane & 7;
            #pragma unroll
            for (int p = 0; p < 2; p++) {
                const int rb = rown + p * 8;
                const uint4 qu = *(const uint4*)&sQH[(rb + qt) * PH + 4 * h];
                const __half2 q0 = u2h(qu.x), q1 = u2h(qu.y),
                              q2 = u2h(qu.z), q3 = u2h(qu.w);
                float e[8], mx = -1e30f;
                #pragma unroll
                for (int kt = 0; kt < 8; kt++) {
                    const uint4 ku = *(const uint4*)&sKH[(rb + kt) * PH + 4 * h];
                    __half2 acc = __hmul2(q0, u2h(ku.x));
                    acc = __hfma2(q1, u2h(ku.y), acc);
                    acc = __hfma2(q2, u2h(ku.z), acc);
                    acc = __hfma2(q3, u2h(ku.w), acc);
                    const float s = __low2float(acc) + __high2float(acc);
                    e[kt] = (kt <= qt) ? s : -1e30f;
                    mx = fmaxf(mx, e[kt]);
                }
                float sum = 0.f;
                #pragma unroll
                for (int kt = 0; kt < 8; kt++) { e[kt] = __expf(e[kt] - mx); sum += e[kt]; }
                const float inv = __fdividef(1.0f, sum);
                __half2 o0 = __float2half2_rn(0.f), o1 = o0, o2 = o0, o3 = o0;
                #pragma unroll
                for (int kt = 0; kt < 8; kt++) {
                    const __half2 wh = __float2half2_rn(e[kt] * inv);
                    const uint4 vu = *(const uint4*)&sVH[(rb + kt) * PH + 4 * h];
                    o0 = __hfma2(wh, u2h(vu.x), o0);
                    o1 = __hfma2(wh, u2h(vu.y), o1);
                    o2 = __hfma2(wh, u2h(vu.z), o2);
                    o3 = __hfma2(wh, u2h(vu.w), o3);
                }
                *(uint4*)&sQH[(rb + qt) * PH + 4 * h] =
                    make_uint4(h2u(o0), h2u(o1), h2u(o2), h2u(o3));
            }
        }
        __syncwarp();   // own rows only: warp-local ordering suffices

        // ---- stage 3: X1 = attn @ Wp + X (own 16 rows, full N) ----
        uint32_t X1[2][4];
        {
            uint32_t AA[2][4];
            LOAD_AH(AA[0], sQH, rown, 0); LOAD_AH(AA[1], sQH, rown, 8);
            PBAR();   // partner done with KH/QH/VH reads; next-tile writes safe
            #pragma unroll
            for (int j = 0; j < 4; j++) {
                uint32_t B0[2], B1[2];
                LOAD_BF(B0, sWP, j * 2); LOAD_BF(B1, sWP, j * 2 + 1);
                float C[4] = {0.f,0.f,0.f,0.f};
                mma16(C, AA[0], B0); mma16(C, AA[1], B1);
                const int t = j >> 1, s = (j & 1) * 2;
                const float2 x0 = __half22float2(u2h(XAo[t][s]));
                const float2 x1 = __half22float2(u2h(XAo[t][s + 1]));
                X1[t][s]     = pkh(C[0] + x0.x, C[1] + x0.y);
                X1[t][s + 1] = pkh(C[2] + x1.x, C[3] + x1.y);
            }
        }

        // ---- stage 4: H = relu(X1 @ W1), full N=128, M=16, in registers ----
        uint32_t Ha[16], Hb[16];
        {
            #pragma unroll
            for (int j = 0; j < 16; j++) {
                uint32_t B0[2], B1[2];
                LOAD_BF(B0, sW1, j * 2); LOAD_BF(B1, sW1, j * 2 + 1);
                float C[4] = {0.f,0.f,0.f,0.f};
                mma16(C, X1[0], B0); mma16(C, X1[1], B1);
                Ha[j] = pkh(fmaxf(C[0], 0.f), fmaxf(C[1], 0.f));
                Hb[j] = pkh(fmaxf(C[2], 0.f), fmaxf(C[3], 0.f));
            }
        }

        // ---- stage 5: FF2 (full k) + X1 residual -> global, direct ----
        {
            #pragma unroll
            for (int nf = 0; nf < 4; nf++) {
                float C[4] = {0.f,0.f,0.f,0.f};
                #pragma unroll
                for (int t = 0; t < 8; t++) {
                    const uint32_t A[4] = {Ha[2*t], Hb[2*t], Ha[2*t+1], Hb[2*t+1]};
                    uint32_t B[2];
                    LOAD_BF(B, sW2, nf * 8 + t);
                    mma16(C, A, B);
                }
                const int t = nf >> 1, s = (nf & 1) * 2;
                const float2 x0 = __half22float2(u2h(X1[t][s]));
                const float2 x1 = __half22float2(u2h(X1[t][s + 1]));
                *(float2*)(og + (rown + r) * 32 + nf * 8 + 2 * c) =
                    make_float2(C[0] + x0.x, C[1] + x0.y);
                *(float2*)(og + (rown + r + 8) * 32 + nf * 8 + 2 * c) =
                    make_float2(C[2] + x1.x, C[3] + x1.y);
            }
        }
        // no trailing barrier: the stage-3 mid-PBAR of the NEXT iteration's
        // partner ordering was shown to cover all cross-warp smem hazards.
    }
}

extern "C" void kernel_launch(void* const* d_in, const int* in_sizes, int n_in,
                              void* d_out, int out_size) {
    const float* X  = (const float*)d_in[0];
    const float* Wa = (const float*)d_in[1];
    const float* Wp = (const float*)d_in[2];
    const float* W1 = (const float*)d_in[3];
    const float* W2 = (const float*)d_in[4];
    float* Out = (float*)d_out;

    cudaFuncSetAttribute(tblock_mma,
                         cudaFuncAttributeMaxDynamicSharedMemorySize, SMEM_BYTES);
    tblock_mma<<<NUM_CTAS, THREADS, SMEM_BYTES>>>(X, Wa, Wp, W1, W2, Out);
}

// round 16
// speedup vs baseline: 7.3981x; 1.1151x over previous
#include <cuda_runtime.h>
#include <cuda_fp16.h>
#include <cstdint>

// Fused transformer block via mma.sync fp16 (m16n8k16, fp32 accumulate).
// 2M rows x 32, 512-row tiles, 512 threads (16 warps), persistent grid 148.
// FULLY warp-independent: each warp owns 32 rows end-to-end (QKV full-N,
// attention, proj, fused FF1->FF2). Zero barriers in the main loop; weight
// fragments amortized over 32 rows (43% fewer weight LDS than R15).

#define THREADS 512
#define NUM_CTAS 148
#define NUM_TILES 4096      // 512 rows per tile

// u32 offsets in dynamic smem
#define OFF_WQKV 0          // 24 frags x 64
#define OFF_WP   1536       // 8 x 64
#define OFF_W1   2048       // 32 x 64
#define OFF_W2   4096       // 32 x 64
#define OFF_XH   6144       // fp16 512 x 20
#define OFF_KH   16384      // fp16 512 x 20
#define OFF_QH   26624      // fp16 512 x 20 (then attn out)
#define OFF_VH   36864      // fp16 512 x 20
#define SMEM_U32 47104
#define SMEM_BYTES (SMEM_U32 * 4)

#define PH 20

__device__ __forceinline__ uint32_t pkh(float lo, float hi) {
    uint32_t r;
    asm("cvt.rn.f16x2.f32 %0, %1, %2;" : "=r"(r) : "f"(hi), "f"(lo));
    return r;
}
__device__ __forceinline__ __half2 u2h(uint32_t u) {
    return *reinterpret_cast<__half2*>(&u);
}
__device__ __forceinline__ uint32_t h2u(__half2 h) {
    return *reinterpret_cast<uint32_t*>(&h);
}
__device__ __forceinline__ void mma16(float c[4], const uint32_t a[4], const uint32_t b[2]) {
    asm volatile(
        "mma.sync.aligned.m16n8k16.row.col.f32.f16.f16.f32 "
        "{%0,%1,%2,%3},{%4,%5,%6,%7},{%8,%9},{%0,%1,%2,%3};"
        : "+f"(c[0]), "+f"(c[1]), "+f"(c[2]), "+f"(c[3])
        : "r"(a[0]), "r"(a[1]), "r"(a[2]), "r"(a[3]), "r"(b[0]), "r"(b[1]));
}

// A fragment (16 rows x k16) from packed fp16 buffer (pitch PH u32), kp0 = k0/2
#define LOAD_AH(A, buf, row0, kp0) do {                                        \
    (A)[0] = (buf)[((row0) + r) * PH + (kp0) + c];                             \
    (A)[1] = (buf)[((row0) + r + 8) * PH + (kp0) + c];                         \
    (A)[2] = (buf)[((row0) + r) * PH + (kp0) + 4 + c];                         \
    (A)[3] = (buf)[((row0) + r + 8) * PH + (kp0) + 4 + c];                     \
} while (0)

// B fragment from fragment-major buffer: one LDS.64, conflict-free.
#define LOAD_BF(B, buf, fi) do {                                               \
    const uint2 v_ = *(const uint2*)&(buf)[((fi) << 6) + (lane << 1)];         \
    (B)[0] = v_.x; (B)[1] = v_.y;                                              \
} while (0)

__device__ __forceinline__ float wa_val(const float* __restrict__ Wa,
                                        int k, int n, float scale) {
    int g = n >> 5, hh = (n & 31) >> 3, d = n & 7;
    float v = Wa[hh * 768 + k * 24 + g * 8 + d];
    return (g == 1) ? v * scale : v;
}

__global__ void __launch_bounds__(THREADS, 1)
tblock_mma(const float* __restrict__ X, const float* __restrict__ Wa,
           const float* __restrict__ Wp, const float* __restrict__ W1,
           const float* __restrict__ W2, float* __restrict__ Out)
{
    extern __shared__ uint32_t smu[];
    uint32_t* const sWQ = smu + OFF_WQKV;
    uint32_t* const sWP = smu + OFF_WP;
    uint32_t* const sW1 = smu + OFF_W1;
    uint32_t* const sW2 = smu + OFF_W2;
    uint32_t* const sXH = smu + OFF_XH;
    uint32_t* const sKH = smu + OFF_KH;
    uint32_t* const sQH = smu + OFF_QH;
    uint32_t* const sVH = smu + OFF_VH;

    const int tid  = threadIdx.x;
    const int warp = tid >> 5;
    const int lane = tid & 31;
    const int r = lane >> 2;
    const int c = lane & 3;
    const float scale = 0.17677669529663687f;   // 32^{-1/2}, folded into Wq

    // -------- pack weights fragment-major, fp16 --------
    for (int idx = tid; idx < 768; idx += THREADS) {       // Wqkv: 12 nb x 2 t
        int f = idx >> 5, l = idx & 31;
        int nb = f >> 1, t = f & 1;
        int rr = l >> 2, cl = l & 3;
        int n = nb * 8 + rr, k0 = t * 16;
        sWQ[f * 64 + l * 2 + 0] = pkh(wa_val(Wa, k0 + 2 * cl,     n, scale),
                                      wa_val(Wa, k0 + 2 * cl + 1, n, scale));
        sWQ[f * 64 + l * 2 + 1] = pkh(wa_val(Wa, k0 + 2 * cl + 8, n, scale),
                                      wa_val(Wa, k0 + 2 * cl + 9, n, scale));
    }
    for (int idx = tid; idx < 256; idx += THREADS) {       // Wp: 4 nb x 2 t
        int f = idx >> 5, l = idx & 31;
        int nb = f >> 1, t = f & 1;
        int rr = l >> 2, cl = l & 3;
        int n = nb * 8 + rr, k0 = t * 16;
        sWP[f * 64 + l * 2 + 0] = pkh(Wp[(k0 + 2 * cl) * 32 + n], Wp[(k0 + 2 * cl + 1) * 32 + n]);
        sWP[f * 64 + l * 2 + 1] = pkh(Wp[(k0 + 2 * cl + 8) * 32 + n], Wp[(k0 + 2 * cl + 9) * 32 + n]);
    }
    for (int idx = tid; idx < 1024; idx += THREADS) {      // W1: 16 nb x 2 t
        int f = idx >> 5, l = idx & 31;
        int nb = f >> 1, t = f & 1;
        int rr = l >> 2, cl = l & 3;
        int n = nb * 8 + rr, k0 = t * 16;
        sW1[f * 64 + l * 2 + 0] = pkh(W1[(k0 + 2 * cl) * 128 + n], W1[(k0 + 2 * cl + 1) * 128 + n]);
        sW1[f * 64 + l * 2 + 1] = pkh(W1[(k0 + 2 * cl + 8) * 128 + n], W1[(k0 + 2 * cl + 9) * 128 + n]);
    }
    for (int idx = tid; idx < 1024; idx += THREADS) {      // W2: 4 nb x 8 ks
        int f = idx >> 5, l = idx & 31;
        int nb = f >> 3, ks = f & 7;
        int rr = l >> 2, cl = l & 3;
        int n = nb * 8 + rr, k0 = ks * 16;
        sW2[f * 64 + l * 2 + 0] = pkh(W2[(k0 + 2 * cl) * 32 + n], W2[(k0 + 2 * cl + 1) * 32 + n]);
        sW2[f * 64 + l * 2 + 1] = pkh(W2[(k0 + 2 * cl + 8) * 32 + n], W2[(k0 + 2 * cl + 9) * 32 + n]);
    }
    __syncthreads();

    const int w32   = warp * 32;        // this warp's 32-row block
    const int row0a = w32;
    const int row0b = w32 + 16;
    const int prA = row0a + (lane >> 1);   // staging rows, half A
    const int prB = row0b + (lane >> 1);   // staging rows, half B
    const int psh = (lane & 1) * 16;

    // -------- prologue: load first tile's X (own 32 rows) -> sXH --------
    {
        const float* xg0 = X + (long long)blockIdx.x * 16384;
        #pragma unroll
        for (int h = 0; h < 2; h++) {
            const int pr = h ? prB : prA;
            const float* p = xg0 + pr * 32 + psh;
            float4 v0 = *(const float4*)(p);
            float4 v1 = *(const float4*)(p + 4);
            float4 v2 = *(const float4*)(p + 8);
            float4 v3 = *(const float4*)(p + 12);
            *(uint4*)&sXH[pr * PH + (psh >> 1)] = make_uint4(
                pkh(v0.x, v0.y), pkh(v0.z, v0.w), pkh(v1.x, v1.y), pkh(v1.z, v1.w));
            *(uint4*)&sXH[pr * PH + (psh >> 1) + 4] = make_uint4(
                pkh(v2.x, v2.y), pkh(v2.z, v2.w), pkh(v3.x, v3.y), pkh(v3.z, v3.w));
        }
    }
    __syncwarp();

    for (int tile = blockIdx.x; tile < NUM_TILES; tile += NUM_CTAS) {
        float* og = Out + (long long)tile * 16384;
        const long long ntile = (long long)tile + NUM_CTAS;
        const bool nv = ntile < NUM_TILES;

        // ---- stage 1: QKV = X @ Wqkv (full N=96, M=32); pipeline next X ----
        uint32_t XA0[2][4], XA1[2][4];
        LOAD_AH(XA0[0], sXH, row0a, 0); LOAD_AH(XA0[1], sXH, row0a, 8);
        LOAD_AH(XA1[0], sXH, row0b, 0); LOAD_AH(XA1[1], sXH, row0b, 8);

        uint32_t nx[16];
        if (nv) {
            const float* nb0 = X + ntile * 16384;
            #pragma unroll
            for (int h = 0; h < 2; h++) {
                const int pr = h ? prB : prA;
                const float* p = nb0 + pr * 32 + psh;
                float4 v0 = *(const float4*)(p);
                float4 v1 = *(const float4*)(p + 4);
                float4 v2 = *(const float4*)(p + 8);
                float4 v3 = *(const float4*)(p + 12);
                nx[8*h+0] = pkh(v0.x, v0.y); nx[8*h+1] = pkh(v0.z, v0.w);
                nx[8*h+2] = pkh(v1.x, v1.y); nx[8*h+3] = pkh(v1.z, v1.w);
                nx[8*h+4] = pkh(v2.x, v2.y); nx[8*h+5] = pkh(v2.z, v2.w);
                nx[8*h+6] = pkh(v3.x, v3.y); nx[8*h+7] = pkh(v3.z, v3.w);
            }
            const long long ptile = ntile + NUM_CTAS;
            if (ptile < NUM_TILES && (lane & 1) == 0) {
                asm volatile("prefetch.global.L2 [%0];"
                             :: "l"(X + ptile * 16384 + prA * 32));
                asm volatile("prefetch.global.L2 [%0];"
                             :: "l"(X + ptile * 16384 + prB * 32));
            }
        }

        #pragma unroll
        for (int j = 0; j < 12; j++) {
            const int n0 = j * 8;
            uint32_t B0[2], B1[2];
            LOAD_BF(B0, sWQ, j * 2); LOAD_BF(B1, sWQ, j * 2 + 1);
            float C0[4] = {0.f,0.f,0.f,0.f}, C1[4] = {0.f,0.f,0.f,0.f};
            mma16(C0, XA0[0], B0); mma16(C0, XA0[1], B1);
            mma16(C1, XA1[0], B0); mma16(C1, XA1[1], B1);
            uint32_t* cb; int np;
            if (n0 < 32)      { cb = sKH; np = n0 >> 1; }
            else if (n0 < 64) { cb = sQH; np = (n0 - 32) >> 1; }
            else              { cb = sVH; np = (n0 - 64) >> 1; }
            cb[(row0a + r) * PH + np + c]     = pkh(C0[0], C0[1]);
            cb[(row0a + r + 8) * PH + np + c] = pkh(C0[2], C0[3]);
            cb[(row0b + r) * PH + np + c]     = pkh(C1[0], C1[1]);
            cb[(row0b + r + 8) * PH + np + c] = pkh(C1[2], C1[3]);
        }
        __syncwarp();   // QKV visible warp-wide; XA reads of sXH complete

        if (nv) {       // store next tile's X (own rows; read next iteration)
            *(uint4*)&sXH[prA * PH + (psh >> 1)]     = make_uint4(nx[0], nx[1], nx[2], nx[3]);
            *(uint4*)&sXH[prA * PH + (psh >> 1) + 4] = make_uint4(nx[4], nx[5], nx[6], nx[7]);
            *(uint4*)&sXH[prB * PH + (psh >> 1)]     = make_uint4(nx[8], nx[9], nx[10], nx[11]);
            *(uint4*)&sXH[prB * PH + (psh >> 1) + 4] = make_uint4(nx[12], nx[13], nx[14], nx[15]);
        }

        // ---- stage 2: attention on own 32 rows (4 batch items) ----
        {
            const int h = lane >> 3, qt = lane & 7;
            #pragma unroll
            for (int p = 0; p < 4; p++) {
                const int rb = w32 + p * 8;
                const uint4 qu = *(const uint4*)&sQH[(rb + qt) * PH + 4 * h];
                const __half2 q0 = u2h(qu.x), q1 = u2h(qu.y),
                              q2 = u2h(qu.z), q3 = u2h(qu.w);
                float e[8], mx = -1e30f;
                #pragma unroll
                for (int kt = 0; kt < 8; kt++) {
                    const uint4 ku = *(const uint4*)&sKH[(rb + kt) * PH + 4 * h];
                    __half2 acc = __hmul2(q0, u2h(ku.x));
                    acc = __hfma2(q1, u2h(ku.y), acc);
                    acc = __hfma2(q2, u2h(ku.z), acc);
                    acc = __hfma2(q3, u2h(ku.w), acc);
                    const float s = __low2float(acc) + __high2float(acc);
                    e[kt] = (kt <= qt) ? s : -1e30f;
                    mx = fmaxf(mx, e[kt]);
                }
                float sum = 0.f;
                #pragma unroll
                for (int kt = 0; kt < 8; kt++) { e[kt] = __expf(e[kt] - mx); sum += e[kt]; }
                const float inv = __fdividef(1.0f, sum);
                __half2 o0 = __float2half2_rn(0.f), o1 = o0, o2 = o0, o3 = o0;
                #pragma unroll
                for (int kt = 0; kt < 8; kt++) {
                    const __half2 wh = __float2half2_rn(e[kt] * inv);
                    const uint4 vu = *(const uint4*)&sVH[(rb + kt) * PH + 4 * h];
                    o0 = __hfma2(wh, u2h(vu.x), o0);
                    o1 = __hfma2(wh, u2h(vu.y), o1);
                    o2 = __hfma2(wh, u2h(vu.z), o2);
                    o3 = __hfma2(wh, u2h(vu.w), o3);
                }
                *(uint4*)&sQH[(rb + qt) * PH + 4 * h] =
                    make_uint4(h2u(o0), h2u(o1), h2u(o2), h2u(o3));
            }
        }
        __syncwarp();

        // ---- stage 3: X1 = attn @ Wp + X (own 32 rows, full N) ----
        uint32_t X1a[2][4], X1b[2][4];
        {
            uint32_t AA0[2][4], AA1[2][4];
            LOAD_AH(AA0[0], sQH, row0a, 0); LOAD_AH(AA0[1], sQH, row0a, 8);
            LOAD_AH(AA1[0], sQH, row0b, 0); LOAD_AH(AA1[1], sQH, row0b, 8);
            #pragma unroll
            for (int j = 0; j < 4; j++) {
                uint32_t B0[2], B1[2];
                LOAD_BF(B0, sWP, j * 2); LOAD_BF(B1, sWP, j * 2 + 1);
                float C0[4] = {0.f,0.f,0.f,0.f}, C1[4] = {0.f,0.f,0.f,0.f};
                mma16(C0, AA0[0], B0); mma16(C0, AA0[1], B1);
                mma16(C1, AA1[0], B0); mma16(C1, AA1[1], B1);
                const int t = j >> 1, s = (j & 1) * 2;
                const float2 xa0 = __half22float2(u2h(XA0[t][s]));
                const float2 xa1 = __half22float2(u2h(XA0[t][s + 1]));
                const float2 xb0 = __half22float2(u2h(XA1[t][s]));
                const float2 xb1 = __half22float2(u2h(XA1[t][s + 1]));
                X1a[t][s]     = pkh(C0[0] + xa0.x, C0[1] + xa0.y);
                X1a[t][s + 1] = pkh(C0[2] + xa1.x, C0[3] + xa1.y);
                X1b[t][s]     = pkh(C1[0] + xb0.x, C1[1] + xb0.y);
                X1b[t][s + 1] = pkh(C1[2] + xb1.x, C1[3] + xb1.y);
            }
        }

        // ---- stage 4+5 fused: FF2(relu(X1 @ W1)) accumulated per k-chunk ----
        float F0[4][4], F1[4][4];
        #pragma unroll
        for (int nf = 0; nf < 4; nf++)
            #pragma unroll
            for (int i = 0; i < 4; i++) { F0[nf][i] = 0.f; F1[nf][i] = 0.f; }
        #pragma unroll
        for (int t = 0; t < 8; t++) {
            uint32_t A0[4], A1[4];
            #pragma unroll
            for (int jj = 0; jj < 2; jj++) {
                const int j = 2 * t + jj;
                uint32_t B0[2], B1[2];
                LOAD_BF(B0, sW1, j * 2); LOAD_BF(B1, sW1, j * 2 + 1);
                float C0[4] = {0.f,0.f,0.f,0.f}, C1[4] = {0.f,0.f,0.f,0.f};
                mma16(C0, X1a[0], B0); mma16(C0, X1a[1], B1);
                mma16(C1, X1b[0], B0); mma16(C1, X1b[1], B1);
                A0[jj]     = pkh(fmaxf(C0[0], 0.f), fmaxf(C0[1], 0.f));
                A0[jj + 2] = pkh(fmaxf(C0[2], 0.f), fmaxf(C0[3], 0.f));
                A1[jj]     = pkh(fmaxf(C1[0], 0.f), fmaxf(C1[1], 0.f));
                A1[jj + 2] = pkh(fmaxf(C1[2], 0.f), fmaxf(C1[3], 0.f));
            }
            // A-frag order {k-lo j0, rows+8 j0, k-lo j1, rows+8 j1} = {A0[0],A0[2],A0[1],A0[3]}
            const uint32_t AA0[4] = {A0[0], A0[2], A0[1], A0[3]};
            const uint32_t AA1[4] = {A1[0], A1[2], A1[1], A1[3]};
            #pragma unroll
            for (int nf = 0; nf < 4; nf++) {
                uint32_t B[2];
                LOAD_BF(B, sW2, nf * 8 + t);
                mma16(F0[nf], AA0, B);
                mma16(F1[nf], AA1, B);
            }
        }

        // ---- output: F + X1 residual -> global ----
        #pragma unroll
        for (int nf = 0; nf < 4; nf++) {
            const int t = nf >> 1, s = (nf & 1) * 2;
            const float2 xa0 = __half22float2(u2h(X1a[t][s]));
            const float2 xa1 = __half22float2(u2h(X1a[t][s + 1]));
            const float2 xb0 = __half22float2(u2h(X1b[t][s]));
            const float2 xb1 = __half22float2(u2h(X1b[t][s + 1]));
            *(float2*)(og + (row0a + r) * 32 + nf * 8 + 2 * c) =
                make_float2(F0[nf][0] + xa0.x, F0[nf][1] + xa0.y);
            *(float2*)(og + (row0a + r + 8) * 32 + nf * 8 + 2 * c) =
                make_float2(F0[nf][2] + xa1.x, F0[nf][3] + xa1.y);
            *(float2*)(og + (row0b + r) * 32 + nf * 8 + 2 * c) =
                make_float2(F1[nf][0] + xb0.x, F1[nf][1] + xb0.y);
            *(float2*)(og + (row0b + r + 8) * 32 + nf * 8 + 2 * c) =
                make_float2(F1[nf][2] + xb1.x, F1[nf][3] + xb1.y);
        }
        __syncwarp();   // all lanes done with this tile's K/Q/V before next QKV
    }
}

extern "C" void kernel_launch(void* const* d_in, const int* in_sizes, int n_in,
                              void* d_out, int out_size) {
    const float* X  = (const float*)d_in[0];
    const float* Wa = (const float*)d_in[1];
    const float* Wp = (const float*)d_in[2];
    const float* W1 = (const float*)d_in[3];
    const float* W2 = (const float*)d_in[4];
    float* Out = (float*)d_out;

    cudaFuncSetAttribute(tblock_mma,
                         cudaFuncAttributeMaxDynamicSharedMemorySize, SMEM_BYTES);
    tblock_mma<<<NUM_CTAS, THREADS, SMEM_BYTES>>>(X, Wa, Wp, W1, W2, Out);
}

// round 17
// speedup vs baseline: 7.8711x; 1.0639x over previous
#include <cuda_runtime.h>
#include <cuda_fp16.h>
#include <cstdint>

// Fused transformer block via mma.sync fp16 (m16n8k16, fp32 accumulate).
// 2M rows x 32, 512-row tiles, 512 threads (16 warps), persistent grid 148.
// Fully warp-independent (zero barriers). Weights packed pair-interleaved
// (one LDS.128 per 2 B-frags); X loaded straight from global as A-fragments
// (no smem staging), pipelined across tiles in registers.

#define THREADS 512
#define NUM_CTAS 148
#define NUM_TILES 4096      // 512 rows per tile

// u32 offsets in dynamic smem
#define OFF_WQKV 0          // 24 frags (12 pairs x 128)
#define OFF_WP   1536       // 8 frags (4 pairs)
#define OFF_W1   2048       // 32 frags (16 pairs)
#define OFF_W2   4096       // 32 frags (16 pairs, order f' = t*4+nf)
#define OFF_KH   6144       // fp16 512 x 20
#define OFF_QH   16384      // fp16 512 x 20 (then attn out)
#define OFF_VH   26624      // fp16 512 x 20
#define SMEM_U32 36864
#define SMEM_BYTES (SMEM_U32 * 4)

#define PH 20

__device__ __forceinline__ uint32_t pkh(float lo, float hi) {
    uint32_t r;
    asm("cvt.rn.f16x2.f32 %0, %1, %2;" : "=r"(r) : "f"(hi), "f"(lo));
    return r;
}
__device__ __forceinline__ __half2 u2h(uint32_t u) {
    return *reinterpret_cast<__half2*>(&u);
}
__device__ __forceinline__ uint32_t h2u(__half2 h) {
    return *reinterpret_cast<uint32_t*>(&h);
}
__device__ __forceinline__ void mma16(float c[4], const uint32_t a[4], const uint32_t b[2]) {
    asm volatile(
        "mma.sync.aligned.m16n8k16.row.col.f32.f16.f16.f32 "
        "{%0,%1,%2,%3},{%4,%5,%6,%7},{%8,%9},{%0,%1,%2,%3};"
        : "+f"(c[0]), "+f"(c[1]), "+f"(c[2]), "+f"(c[3])
        : "r"(a[0]), "r"(a[1]), "r"(a[2]), "r"(a[3]), "r"(b[0]), "r"(b[1]));
}

// A fragment (16 rows x k16) from packed fp16 buffer (pitch PH u32), kp0 = k0/2
#define LOAD_AH(A, buf, row0, kp0) do {                                        \
    (A)[0] = (buf)[((row0) + r) * PH + (kp0) + c];                             \
    (A)[1] = (buf)[((row0) + r + 8) * PH + (kp0) + c];                         \
    (A)[2] = (buf)[((row0) + r) * PH + (kp0) + 4 + c];                         \
    (A)[3] = (buf)[((row0) + r + 8) * PH + (kp0) + 4 + c];                     \
} while (0)

// B fragment PAIR from pair-interleaved buffer: one LDS.128, conflict-free.
#define LOAD_BF2(B0, B1, buf, a) do {                                          \
    const uint4 v_ = *(const uint4*)&(buf)[((a) << 7) + (lane << 2)];          \
    (B0)[0] = v_.x; (B0)[1] = v_.y; (B1)[0] = v_.z; (B1)[1] = v_.w;            \
} while (0)

// pair-interleaved pack offset for frag f, lane l
#define PACK_OFF(f, l) ((((f) >> 1) << 7) + ((l) << 2) + (((f) & 1) << 1))

__device__ __forceinline__ float wa_val(const float* __restrict__ Wa,
                                        int k, int n, float scale) {
    int g = n >> 5, hh = (n & 31) >> 3, d = n & 7;
    float v = Wa[hh * 768 + k * 24 + g * 8 + d];
    return (g == 1) ? v * scale : v;
}

__global__ void __launch_bounds__(THREADS, 1)
tblock_mma(const float* __restrict__ X, const float* __restrict__ Wa,
           const float* __restrict__ Wp, const float* __restrict__ W1,
           const float* __restrict__ W2, float* __restrict__ Out)
{
    extern __shared__ uint32_t smu[];
    uint32_t* const sWQ = smu + OFF_WQKV;
    uint32_t* const sWP = smu + OFF_WP;
    uint32_t* const sW1 = smu + OFF_W1;
    uint32_t* const sW2 = smu + OFF_W2;
    uint32_t* const sKH = smu + OFF_KH;
    uint32_t* const sQH = smu + OFF_QH;
    uint32_t* const sVH = smu + OFF_VH;

    const int tid  = threadIdx.x;
    const int warp = tid >> 5;
    const int lane = tid & 31;
    const int r = lane >> 2;
    const int c = lane & 3;
    const float scale = 0.17677669529663687f;   // 32^{-1/2}, folded into Wq

    // -------- pack weights fragment-major, fp16, pair-interleaved --------
    for (int idx = tid; idx < 768; idx += THREADS) {       // Wqkv: f = nb*2+t
        int f = idx >> 5, l = idx & 31;
        int nb = f >> 1, t = f & 1;
        int rr = l >> 2, cl = l & 3;
        int n = nb * 8 + rr, k0 = t * 16;
        int o = PACK_OFF(f, l);
        sWQ[o + 0] = pkh(wa_val(Wa, k0 + 2 * cl,     n, scale),
                         wa_val(Wa, k0 + 2 * cl + 1, n, scale));
        sWQ[o + 1] = pkh(wa_val(Wa, k0 + 2 * cl + 8, n, scale),
                         wa_val(Wa, k0 + 2 * cl + 9, n, scale));
    }
    for (int idx = tid; idx < 256; idx += THREADS) {       // Wp
        int f = idx >> 5, l = idx & 31;
        int nb = f >> 1, t = f & 1;
        int rr = l >> 2, cl = l & 3;
        int n = nb * 8 + rr, k0 = t * 16;
        int o = PACK_OFF(f, l);
        sWP[o + 0] = pkh(Wp[(k0 + 2 * cl) * 32 + n], Wp[(k0 + 2 * cl + 1) * 32 + n]);
        sWP[o + 1] = pkh(Wp[(k0 + 2 * cl + 8) * 32 + n], Wp[(k0 + 2 * cl + 9) * 32 + n]);
    }
    for (int idx = tid; idx < 1024; idx += THREADS) {      // W1
        int f = idx >> 5, l = idx & 31;
        int nb = f >> 1, t = f & 1;
        int rr = l >> 2, cl = l & 3;
        int n = nb * 8 + rr, k0 = t * 16;
        int o = PACK_OFF(f, l);
        sW1[o + 0] = pkh(W1[(k0 + 2 * cl) * 128 + n], W1[(k0 + 2 * cl + 1) * 128 + n]);
        sW1[o + 1] = pkh(W1[(k0 + 2 * cl + 8) * 128 + n], W1[(k0 + 2 * cl + 9) * 128 + n]);
    }
    for (int idx = tid; idx < 1024; idx += THREADS) {      // W2: f' = ks*4 + nb
        int f = idx >> 5, l = idx & 31;
        int ks = f >> 2, nb = f & 3;
        int rr = l >> 2, cl = l & 3;
        int n = nb * 8 + rr, k0 = ks * 16;
        int o = PACK_OFF(f, l);
        sW2[o + 0] = pkh(W2[(k0 + 2 * cl) * 32 + n], W2[(k0 + 2 * cl + 1) * 32 + n]);
        sW2[o + 1] = pkh(W2[(k0 + 2 * cl + 8) * 32 + n], W2[(k0 + 2 * cl + 9) * 32 + n]);
    }
    __syncthreads();

    const int w32   = warp * 32;        // this warp's 32-row block
    const int row0a = w32;
    const int row0b = w32 + 16;

    // direct-from-global A-fragment loader (fp32 -> fp16 pairs)
    #define LOAD_XA_G(A, p, row0) do {                                         \
        _Pragma("unroll")                                                      \
        for (int t_ = 0; t_ < 2; t_++) {                                       \
            const float2 v0 = *(const float2*)((p) + ((row0) + r) * 32 + 16 * t_ + 2 * c);      \
            const float2 v1 = *(const float2*)((p) + ((row0) + r + 8) * 32 + 16 * t_ + 2 * c);  \
            const float2 v2 = *(const float2*)((p) + ((row0) + r) * 32 + 16 * t_ + 8 + 2 * c);  \
            const float2 v3 = *(const float2*)((p) + ((row0) + r + 8) * 32 + 16 * t_ + 8 + 2 * c); \
            (A)[t_][0] = pkh(v0.x, v0.y);                                      \
            (A)[t_][1] = pkh(v1.x, v1.y);                                      \
            (A)[t_][2] = pkh(v2.x, v2.y);                                      \
            (A)[t_][3] = pkh(v3.x, v3.y);                                      \
        }                                                                      \
    } while (0)

    // -------- prologue: first tile's X A-fragments straight from global ----
    uint32_t XA0[2][4], XA1[2][4];
    {
        const float* p0 = X + (long long)blockIdx.x * 16384;
        LOAD_XA_G(XA0, p0, row0a);
        LOAD_XA_G(XA1, p0, row0b);
    }

    for (int tile = blockIdx.x; tile < NUM_TILES; tile += NUM_CTAS) {
        float* og = Out + (long long)tile * 16384;
        const long long ntile = (long long)tile + NUM_CTAS;
        const bool nv = ntile < NUM_TILES;

        // ---- stage 1: issue next tile's X loads, then QKV (full N=96) ----
        uint32_t XN0[2][4], XN1[2][4];
        if (nv) {
            const float* np = X + ntile * 16384;
            LOAD_XA_G(XN0, np, row0a);
            LOAD_XA_G(XN1, np, row0b);
            const long long ptile = ntile + NUM_CTAS;
            if (ptile < NUM_TILES)
                asm volatile("prefetch.global.L2 [%0];"
                             :: "l"(X + ptile * 16384 + (w32 + lane) * 32));
        }

        #pragma unroll
        for (int j = 0; j < 12; j++) {
            const int n0 = j * 8;
            uint32_t B0[2], B1[2];
            LOAD_BF2(B0, B1, sWQ, j);
            float C0[4] = {0.f,0.f,0.f,0.f}, C1[4] = {0.f,0.f,0.f,0.f};
            mma16(C0, XA0[0], B0); mma16(C0, XA0[1], B1);
            mma16(C1, XA1[0], B0); mma16(C1, XA1[1], B1);
            uint32_t* cb; int np;
            if (n0 < 32)      { cb = sKH; np = n0 >> 1; }
            else if (n0 < 64) { cb = sQH; np = (n0 - 32) >> 1; }
            else              { cb = sVH; np = (n0 - 64) >> 1; }
            cb[(row0a + r) * PH + np + c]     = pkh(C0[0], C0[1]);
            cb[(row0a + r + 8) * PH + np + c] = pkh(C0[2], C0[3]);
            cb[(row0b + r) * PH + np + c]     = pkh(C1[0], C1[1]);
            cb[(row0b + r + 8) * PH + np + c] = pkh(C1[2], C1[3]);
        }
        __syncwarp();   // QKV visible warp-wide

        // ---- stage 2: attention on own 32 rows (4 batch items) ----
        {
            const int h = lane >> 3, qt = lane & 7;
            #pragma unroll
            for (int p = 0; p < 4; p++) {
                const int rb = w32 + p * 8;
                const uint4 qu = *(const uint4*)&sQH[(rb + qt) * PH + 4 * h];
                const __half2 q0 = u2h(qu.x), q1 = u2h(qu.y),
                              q2 = u2h(qu.z), q3 = u2h(qu.w);
                float e[8], mx = -1e30f;
                #pragma unroll
                for (int kt = 0; kt < 8; kt++) {
                    const uint4 ku = *(const uint4*)&sKH[(rb + kt) * PH + 4 * h];
                    __half2 acc = __hmul2(q0, u2h(ku.x));
                    acc = __hfma2(q1, u2h(ku.y), acc);
                    acc = __hfma2(q2, u2h(ku.z), acc);
                    acc = __hfma2(q3, u2h(ku.w), acc);
                    const float s = __low2float(acc) + __high2float(acc);
                    e[kt] = (kt <= qt) ? s : -1e30f;
                    mx = fmaxf(mx, e[kt]);
                }
                float sum = 0.f;
                #pragma unroll
                for (int kt = 0; kt < 8; kt++) { e[kt] = __expf(e[kt] - mx); sum += e[kt]; }
                const float inv = __fdividef(1.0f, sum);
                __half2 o0 = __float2half2_rn(0.f), o1 = o0, o2 = o0, o3 = o0;
                #pragma unroll
                for (int kt = 0; kt < 8; kt++) {
                    const __half2 wh = __float2half2_rn(e[kt] * inv);
                    const uint4 vu = *(const uint4*)&sVH[(rb + kt) * PH + 4 * h];
                    o0 = __hfma2(wh, u2h(vu.x), o0);
                    o1 = __hfma2(wh, u2h(vu.y), o1);
                    o2 = __hfma2(wh, u2h(vu.z), o2);
                    o3 = __hfma2(wh, u2h(vu.w), o3);
                }
                *(uint4*)&sQH[(rb + qt) * PH + 4 * h] =
                    make_uint4(h2u(o0), h2u(o1), h2u(o2), h2u(o3));
            }
        }
        __syncwarp();

        // ---- stage 3: X1 = attn @ Wp + X (own 32 rows, full N) ----
        uint32_t X1a[2][4], X1b[2][4];
        {
            uint32_t AA0[2][4], AA1[2][4];
            LOAD_AH(AA0[0], sQH, row0a, 0); LOAD_AH(AA0[1], sQH, row0a, 8);
            LOAD_AH(AA1[0], sQH, row0b, 0); LOAD_AH(AA1[1], sQH, row0b, 8);
            #pragma unroll
            for (int j = 0; j < 4; j++) {
                uint32_t B0[2], B1[2];
                LOAD_BF2(B0, B1, sWP, j);
                float C0[4] = {0.f,0.f,0.f,0.f}, C1[4] = {0.f,0.f,0.f,0.f};
                mma16(C0, AA0[0], B0); mma16(C0, AA0[1], B1);
                mma16(C1, AA1[0], B0); mma16(C1, AA1[1], B1);
                const int t = j >> 1, s = (j & 1) * 2;
                const float2 xa0 = __half22float2(u2h(XA0[t][s]));
                const float2 xa1 = __half22float2(u2h(XA0[t][s + 1]));
                const float2 xb0 = __half22float2(u2h(XA1[t][s]));
                const float2 xb1 = __half22float2(u2h(XA1[t][s + 1]));
                X1a[t][s]     = pkh(C0[0] + xa0.x, C0[1] + xa0.y);
                X1a[t][s + 1] = pkh(C0[2] + xa1.x, C0[3] + xa1.y);
                X1b[t][s]     = pkh(C1[0] + xb0.x, C1[1] + xb0.y);
                X1b[t][s + 1] = pkh(C1[2] + xb1.x, C1[3] + xb1.y);
            }
        }

        // ---- stage 4+5 fused: FF2(relu(X1 @ W1)) accumulated per k-chunk ----
        float F0[4][4], F1[4][4];
        #pragma unroll
        for (int nf = 0; nf < 4; nf++)
            #pragma unroll
            for (int i = 0; i < 4; i++) { F0[nf][i] = 0.f; F1[nf][i] = 0.f; }
        #pragma unroll
        for (int t = 0; t < 8; t++) {
            uint32_t A0[4], A1[4];
            #pragma unroll
            for (int jj = 0; jj < 2; jj++) {
                const int j = 2 * t + jj;
                uint32_t B0[2], B1[2];
                LOAD_BF2(B0, B1, sW1, j);
                float C0[4] = {0.f,0.f,0.f,0.f}, C1[4] = {0.f,0.f,0.f,0.f};
                mma16(C0, X1a[0], B0); mma16(C0, X1a[1], B1);
                mma16(C1, X1b[0], B0); mma16(C1, X1b[1], B1);
                A0[jj]     = pkh(fmaxf(C0[0], 0.f), fmaxf(C0[1], 0.f));
                A0[jj + 2] = pkh(fmaxf(C0[2], 0.f), fmaxf(C0[3], 0.f));
                A1[jj]     = pkh(fmaxf(C1[0], 0.f), fmaxf(C1[1], 0.f));
                A1[jj + 2] = pkh(fmaxf(C1[2], 0.f), fmaxf(C1[3], 0.f));
            }
            const uint32_t AA0[4] = {A0[0], A0[2], A0[1], A0[3]};
            const uint32_t AA1[4] = {A1[0], A1[2], A1[1], A1[3]};
            uint32_t Bn0[2], Bn1[2], Bn2[2], Bn3[2];
            LOAD_BF2(Bn0, Bn1, sW2, t * 2);
            LOAD_BF2(Bn2, Bn3, sW2, t * 2 + 1);
            mma16(F0[0], AA0, Bn0); mma16(F1[0], AA1, Bn0);
            mma16(F0[1], AA0, Bn1); mma16(F1[1], AA1, Bn1);
            mma16(F0[2], AA0, Bn2); mma16(F1[2], AA1, Bn2);
            mma16(F0[3], AA0, Bn3); mma16(F1[3], AA1, Bn3);
        }

        // ---- output: F + X1 residual -> global ----
        #pragma unroll
        for (int nf = 0; nf < 4; nf++) {
            const int t = nf >> 1, s = (nf & 1) * 2;
            const float2 xa0 = __half22float2(u2h(X1a[t][s]));
            const float2 xa1 = __half22float2(u2h(X1a[t][s + 1]));
            const float2 xb0 = __half22float2(u2h(X1b[t][s]));
            const float2 xb1 = __half22float2(u2h(X1b[t][s + 1]));
            *(float2*)(og + (row0a + r) * 32 + nf * 8 + 2 * c) =
                make_float2(F0[nf][0] + xa0.x, F0[nf][1] + xa0.y);
            *(float2*)(og + (row0a + r + 8) * 32 + nf * 8 + 2 * c) =
                make_float2(F0[nf][2] + xa1.x, F0[nf][3] + xa1.y);
            *(float2*)(og + (row0b + r) * 32 + nf * 8 + 2 * c) =
                make_float2(F1[nf][0] + xb0.x, F1[nf][1] + xb0.y);
            *(float2*)(og + (row0b + r + 8) * 32 + nf * 8 + 2 * c) =
                make_float2(F1[nf][2] + xb1.x, F1[nf][3] + xb1.y);
        }

        // carry next tile's X fragments
        #pragma unroll
        for (int t = 0; t < 2; t++)
            #pragma unroll
            for (int i = 0; i < 4; i++) {
                XA0[t][i] = XN0[t][i];
                XA1[t][i] = XN1[t][i];
            }
        __syncwarp();   // all lanes done with this tile's K/Q/V before next QKV
    }
    #undef LOAD_XA_G
}

extern "C" void kernel_launch(void* const* d_in, const int* in_sizes, int n_in,
                              void* d_out, int out_size) {
    const float* X  = (const float*)d_in[0];
    const float* Wa = (const float*)d_in[1];
    const float* Wp = (const float*)d_in[2];
    const float* W1 = (const float*)d_in[3];
    const float* W2 = (const float*)d_in[4];
    float* Out = (float*)d_out;

    cudaFuncSetAttribute(tblock_mma,
                         cudaFuncAttributeMaxDynamicSharedMemorySize, SMEM_BYTES);
    tblock_mma<<<NUM_CTAS, THREADS, SMEM_BYTES>>>(X, Wa, Wp, W1, W2, Out);
}